// round 5
// baseline (speedup 1.0000x reference)
#include <cuda_runtime.h>
#include <math.h>

#define BT    16384
#define DOBS  512
#define DD    128
#define NS    16
#define HH    256
#define EPC   2      // entries per CTA in slot kernel

typedef unsigned long long u64;

__device__ __forceinline__ u64 fma2(u64 a, u64 b, u64 c) {
    u64 d;
    asm("fma.rn.f32x2 %0, %1, %2, %3;" : "=l"(d) : "l"(a), "l"(b), "l"(c));
    return d;
}
__device__ __forceinline__ float sum2(u64 a) {
    float2 f = *(float2*)&a;
    return f.x + f.y;
}
__device__ __forceinline__ u64 pack2(float lo, float hi) {
    u64 r;
    asm("mov.b64 %0, {%1, %2};" : "=l"(r) : "f"(lo), "f"(hi));
    return r;
}
__device__ __forceinline__ float tanha(float x) {
    float y;
    asm("tanh.approx.f32 %0, %1;" : "=f"(y) : "f"(x));
    return y;
}
__device__ __forceinline__ float sigm(float x) { return 0.5f * tanha(0.5f * x) + 0.5f; }

// ---------------- device scratch ----------------
__device__ float g_z[BT * DD];
__device__ float gA1p[DD];   // mW1^T @ lml_b + mb1
__device__ float gB1[DD];    // mW1^T @ lml_g

// pair-interleaved packed weights
__device__ ulonglong2 pW1[128 * 256];
__device__ ulonglong2 pW2[64 * 128];
__device__ ulonglong2 pSkip[128 * 128];
__device__ ulonglong2 pWk[32 * 128];
__device__ ulonglong2 pWv[32 * 128];
__device__ ulonglong2 pWqT[32 * 128];
__device__ ulonglong2 pWih[32 * 384];
__device__ ulonglong2 pWhh[32 * 384];
__device__ ulonglong2 pmW1g[32 * 128];  // lml_g-scaled mW1
__device__ ulonglong2 pmW2[32 * 128];
__device__ ulonglong2 pWt[32 * 128];

// ---------------- pack helpers ----------------
__device__ __forceinline__ void pack_elem(const float* __restrict__ src,
                                          ulonglong2* __restrict__ dst, int C, int idx)
{
    int c = idx % C, k4 = idx / C;
    const float* s = src + (4 * k4) * C + c;
    ulonglong2 v;
    v.x = pack2(s[0], s[C]);
    v.y = pack2(s[2 * C], s[3 * C]);
    dst[idx] = v;
}
__device__ __forceinline__ void pack_elem_scaled(const float* __restrict__ src,
                                                 const float* __restrict__ sc,
                                                 ulonglong2* __restrict__ dst, int C, int idx)
{
    int c = idx % C, k4 = idx / C;
    const float* s = src + (4 * k4) * C + c;
    const float* q = sc + 4 * k4;
    ulonglong2 v;
    v.x = pack2(s[0] * q[0], s[C] * q[1]);
    v.y = pack2(s[2 * C] * q[2], s[3 * C] * q[3]);
    dst[idx] = v;
}
__device__ __forceinline__ void packT_elem(const float* __restrict__ src,
                                           ulonglong2* __restrict__ dst, int K, int C4, int idx)
{
    int i = idx % K, j4 = idx / K;
    const float* s = src + i * (C4 * 4) + 4 * j4;
    ulonglong2 v;
    v.x = pack2(s[0], s[1]);
    v.y = pack2(s[2], s[3]);
    dst[idx] = v;
}

__global__ __launch_bounds__(256) void pack_all(
    const float* __restrict__ eW1, const float* __restrict__ eW2,
    const float* __restrict__ skipW,
    const float* __restrict__ Wk, const float* __restrict__ Wv,
    const float* __restrict__ Wq,
    const float* __restrict__ gWih, const float* __restrict__ gWhh,
    const float* __restrict__ mW1, const float* __restrict__ mW2,
    const float* __restrict__ Wt, const float* __restrict__ lml_g)
{
    int idx = blockIdx.x * 256 + threadIdx.x;
    if (idx < 32768) { pack_elem(eW1,  pW1,  256, idx); return; }  idx -= 32768;
    if (idx < 8192)  { pack_elem(eW2,  pW2,  128, idx); return; }  idx -= 8192;
    if (idx < 16384) { pack_elem(skipW,pSkip,128, idx); return; }  idx -= 16384;
    if (idx < 4096)  { pack_elem(Wk,   pWk,  128, idx); return; }  idx -= 4096;
    if (idx < 4096)  { pack_elem(Wv,   pWv,  128, idx); return; }  idx -= 4096;
    if (idx < 4096)  { packT_elem(Wq,  pWqT, 128, 32, idx); return; } idx -= 4096;
    if (idx < 12288) { pack_elem(gWih, pWih, 384, idx); return; }  idx -= 12288;
    if (idx < 12288) { pack_elem(gWhh, pWhh, 384, idx); return; }  idx -= 12288;
    if (idx < 4096)  { pack_elem_scaled(mW1, lml_g, pmW1g, 128, idx); return; }  idx -= 4096;
    if (idx < 4096)  { pack_elem(mW2,  pmW2, 128, idx); return; }  idx -= 4096;
    if (idx < 4096)  { pack_elem(Wt,   pWt,  128, idx); return; }
}

// A1p[j] = sum_d lml_b[d]*mW1[d][j] + mb1[j];  B1[j] = sum_d lml_g[d]*mW1[d][j]
__global__ __launch_bounds__(128) void prep_vec(
    const float* __restrict__ mW1, const float* __restrict__ mb1,
    const float* __restrict__ lml_g, const float* __restrict__ lml_b)
{
    const int j = threadIdx.x;
    float a = 0.f, b = 0.f;
    for (int d = 0; d < DD; d++) {
        const float w = mW1[d * DD + j];
        a += lml_b[d] * w;
        b += lml_g[d] * w;
    }
    gA1p[j] = a + mb1[j];
    gB1[j] = b;
}

// ---------------------------------------------------------------------------
// Kernel 1: encoder (unchanged)
// ---------------------------------------------------------------------------
__global__ __launch_bounds__(256) void enc_kernel(
    const float* __restrict__ obs,
    const float* __restrict__ b1, const float* __restrict__ b2)
{
    __shared__ __align__(16) float s_obs[8 * DOBS];
    __shared__ __align__(16) float s_h[8 * HH];
    __shared__ __align__(16) float s_p1[8 * DD];

    const int tid = threadIdx.x;
    const long e0 = (long)blockIdx.x * 8;
    const float* op = obs + e0 * DOBS;

    for (int i = tid; i < 8 * DOBS / 4; i += 256)
        ((float4*)s_obs)[i] = ((const float4*)op)[i];
    __syncthreads();

    {
        const int j = tid;
        u64 acc[8] = {0, 0, 0, 0, 0, 0, 0, 0};
        for (int d4 = 0; d4 < 128; d4++) {
            const ulonglong2 w = pW1[d4 * HH + j];
            #pragma unroll
            for (int r = 0; r < 8; r++) {
                const ulonglong2 s = *(const ulonglong2*)&s_obs[r * DOBS + 4 * d4];
                acc[r] = fma2(s.x, w.x, acc[r]);
                acc[r] = fma2(s.y, w.y, acc[r]);
            }
        }
        const float bj = b1[j];
        #pragma unroll
        for (int r = 0; r < 8; r++) {
            const float a = sum2(acc[r]) + bj;
            s_h[r * HH + j] = 0.5f * a * (1.f + erff(a * 0.70710678118654752f));
        }
    }
    __syncthreads();

    const int j = tid & 127;
    const int half = tid >> 7;
    u64 acc[8] = {0, 0, 0, 0, 0, 0, 0, 0};

    if (half == 0) {
        for (int d4 = 0; d4 < 64; d4++) {
            const ulonglong2 w = pW2[d4 * DD + j];
            #pragma unroll
            for (int r = 0; r < 8; r++) {
                const ulonglong2 s = *(const ulonglong2*)&s_h[r * HH + 4 * d4];
                acc[r] = fma2(s.x, w.x, acc[r]);
                acc[r] = fma2(s.y, w.y, acc[r]);
            }
        }
        for (int d4 = 0; d4 < 32; d4++) {
            const ulonglong2 w = pSkip[d4 * DD + j];
            #pragma unroll
            for (int r = 0; r < 8; r++) {
                const ulonglong2 s = *(const ulonglong2*)&s_obs[r * DOBS + 4 * d4];
                acc[r] = fma2(s.x, w.x, acc[r]);
                acc[r] = fma2(s.y, w.y, acc[r]);
            }
        }
    } else {
        for (int d4 = 32; d4 < 128; d4++) {
            const ulonglong2 w = pSkip[d4 * DD + j];
            #pragma unroll
            for (int r = 0; r < 8; r++) {
                const ulonglong2 s = *(const ulonglong2*)&s_obs[r * DOBS + 4 * d4];
                acc[r] = fma2(s.x, w.x, acc[r]);
                acc[r] = fma2(s.y, w.y, acc[r]);
            }
        }
        #pragma unroll
        for (int r = 0; r < 8; r++) s_p1[r * DD + j] = sum2(acc[r]);
    }
    __syncthreads();

    if (half == 0) {
        const float bj = b2[j];
        #pragma unroll
        for (int r = 0; r < 8; r++)
            g_z[(e0 + r) * DD + j] = tanha(sum2(acc[r]) + s_p1[r * DD + j] + bj);
    }
}

// ---------------------------------------------------------------------------
// Kernel 2: fused slot attention, EPC=2 entries per CTA, 512 threads, 2 CTAs/SM.
// LayerNorms folded into GEMMs; 6 barriers per iteration (3 per entry).
// ---------------------------------------------------------------------------
struct __align__(16) SlotSmem {
    float slots[EPC][NS * DD];   // 16 KB
    float h1[EPC][NS * DD];      // 16 KB
    float inp[EPC][DD];
    float k[EPC][DD];
    float v[EPC][DD];
    float wqk2[EPC][DD];         // lsl_g ∘ (Wq @ k)
    float vwih[EPC][384];
    float logits[EPC][NS];
    float attn[EPC][NS];
    float sp[EPC][NS][4][2];     // per-row stats partials (sum, sumsq)
    float scp[EPC][4][2];        // wqk scalar partials
    float sc[EPC][2];            // [sgw, cb]
    float red[EPC][12];
};

__global__ __launch_bounds__(512, 2) void slot_kernel(
    const float* __restrict__ slot_mu,
    const float* __restrict__ bih, const float* __restrict__ bhh,
    const float* __restrict__ mb2,
    const float* __restrict__ lin_g, const float* __restrict__ lin_b,
    const float* __restrict__ lsl_g, const float* __restrict__ lsl_b,
    float* __restrict__ out)
{
    __shared__ SlotSmem sm;

    const int tid = threadIdx.x, lane = tid & 31, warp = tid >> 5;
    const int j = tid & 127, g = tid >> 7;
    const long e0 = (long)blockIdx.x * EPC;

    // ---- prologue: z-LN stats (threads<256), slot init (threads>=256) ----
    float zv = 0.f;
    if (tid < 256) {
        const int e = tid >> 7;
        zv = g_z[(e0 + e) * DD + j];
        float s1 = zv, s2 = zv * zv;
        #pragma unroll
        for (int off = 16; off > 0; off >>= 1) {
            s1 += __shfl_down_sync(0xffffffffu, s1, off);
            s2 += __shfl_down_sync(0xffffffffu, s2, off);
        }
        if (lane == 0) { sm.red[e][warp & 3] = s1; sm.red[e][4 + (warp & 3)] = s2; }
    } else {
        const int idx = tid - 256;  // 0..255
        const float4* mu4 = (const float4*)slot_mu;
        #pragma unroll
        for (int e = 0; e < EPC; e++) {
            ((float4*)sm.slots[e])[idx]       = mu4[idx];
            ((float4*)sm.slots[e])[idx + 256] = mu4[idx + 256];
        }
    }
    __syncthreads();
    if (tid < EPC) {
        const int e = tid;
        float s = sm.red[e][0] + sm.red[e][1] + sm.red[e][2] + sm.red[e][3];
        float q = sm.red[e][4] + sm.red[e][5] + sm.red[e][6] + sm.red[e][7];
        const float mu = s * (1.f / 128.f);
        const float var = q * (1.f / 128.f) - mu * mu;
        sm.red[e][8] = mu;
        sm.red[e][9] = rsqrtf(var + 1e-5f);
    }
    __syncthreads();
    if (tid < 256) {
        const int e = tid >> 7;
        sm.inp[e][j] = (zv - sm.red[e][8]) * sm.red[e][9] * lin_g[j] + lin_b[j];
    }
    __syncthreads();

    // ---- k and v: 4 groups = (entry, k|v) ----
    {
        const int e = g >> 1, which = g & 1;
        const ulonglong2* W = which ? pWv : pWk;
        u64 acc = 0;
        for (int d4 = 0; d4 < 32; d4++) {
            const ulonglong2 s = *(const ulonglong2*)&sm.inp[e][4 * d4];
            const ulonglong2 w = W[d4 * DD + j];
            acc = fma2(s.x, w.x, acc);
            acc = fma2(s.y, w.y, acc);
        }
        if (which) sm.v[e][j] = sum2(acc); else sm.k[e][j] = sum2(acc);
    }
    __syncthreads();

    // ---- wqk2 + scalar partials (tid<128), vwih (tid>=128) — per entry ----
    #pragma unroll
    for (int e = 0; e < EPC; e++) {
        if (tid < DD) {
            u64 acc = 0;
            for (int j4 = 0; j4 < 32; j4++) {
                const ulonglong2 s = *(const ulonglong2*)&sm.k[e][4 * j4];
                const ulonglong2 w = pWqT[j4 * DD + tid];
                acc = fma2(s.x, w.x, acc);
                acc = fma2(s.y, w.y, acc);
            }
            const float wq = sum2(acc);
            const float w2 = lsl_g[tid] * wq;
            sm.wqk2[e][tid] = w2;
            float p1 = w2, p2 = lsl_b[tid] * wq;
            #pragma unroll
            for (int off = 16; off > 0; off >>= 1) {
                p1 += __shfl_down_sync(0xffffffffu, p1, off);
                p2 += __shfl_down_sync(0xffffffffu, p2, off);
            }
            if (lane == 0) { sm.scp[e][warp][0] = p1; sm.scp[e][warp][1] = p2; }
        } else {
            const int c = tid - DD;  // 0..383
            u64 acc = 0;
            for (int d4 = 0; d4 < 32; d4++) {
                const ulonglong2 s = *(const ulonglong2*)&sm.v[e][4 * d4];
                const ulonglong2 w = pWih[d4 * 384 + c];
                acc = fma2(s.x, w.x, acc);
                acc = fma2(s.y, w.y, acc);
            }
            sm.vwih[e][c] = sum2(acc);
        }
    }
    __syncthreads();
    if (tid < EPC) {
        sm.sc[tid][0] = sm.scp[tid][0][0] + sm.scp[tid][1][0] + sm.scp[tid][2][0] + sm.scp[tid][3][0];
        sm.sc[tid][1] = sm.scp[tid][0][1] + sm.scp[tid][1][1] + sm.scp[tid][2][1] + sm.scp[tid][3][1];
    }
    __syncthreads();

    const float invscale = 0.088388347648318447f;  // 1/sqrt(128)
    const float bi_r = bih[j], bi_z = bih[j + 128], bi_n = bih[j + 256];
    const float bh_r = bhh[j], bh_z = bhh[j + 128], bh_n = bhh[j + 256];
    const float A1p_j = gA1p[j], B1_j = gB1[j], mb2_j = mb2[j];

    for (int it = 0; it < 3; it++) {
        // (a) folded slot-LN + logits — warp w owns row w, per entry
        #pragma unroll
        for (int e = 0; e < EPC; e++) {
            const float* src = &sm.slots[e][warp * DD];
            float x0 = src[lane], x1 = src[lane + 32], x2 = src[lane + 64], x3 = src[lane + 96];
            float s = x0 + x1 + x2 + x3;
            float q = x0 * x0 + x1 * x1 + x2 * x2 + x3 * x3;
            float p = x0 * sm.wqk2[e][lane] + x1 * sm.wqk2[e][lane + 32]
                    + x2 * sm.wqk2[e][lane + 64] + x3 * sm.wqk2[e][lane + 96];
            #pragma unroll
            for (int off = 16; off > 0; off >>= 1) {
                s += __shfl_down_sync(0xffffffffu, s, off);
                q += __shfl_down_sync(0xffffffffu, q, off);
                p += __shfl_down_sync(0xffffffffu, p, off);
            }
            if (lane == 0) {
                const float mu = s * (1.f / 128.f);
                const float rstd = rsqrtf(q * (1.f / 128.f) - mu * mu + 1e-5f);
                sm.logits[e][warp] =
                    invscale * (rstd * (p - mu * sm.sc[e][0]) + sm.sc[e][1]);
            }
        }
        __syncthreads();
        // (b) softmax — warp e, lanes 0..15
        if (warp < EPC && lane < 16) {
            const float l = sm.logits[warp][lane];
            float m = l;
            #pragma unroll
            for (int off = 8; off > 0; off >>= 1)
                m = fmaxf(m, __shfl_xor_sync(0xffffu, m, off));
            const float ex = __expf(l - m);
            float ssum = ex;
            #pragma unroll
            for (int off = 8; off > 0; off >>= 1)
                ssum += __shfl_xor_sync(0xffffu, ssum, off);
            sm.attn[warp][lane] = ex / ssum;
        }
        __syncthreads();

        // (c) GRU + mlp-LN stats partials from registers
        float nv[EPC][4];
        #pragma unroll
        for (int e = 0; e < EPC; e++) {
            u64 ar[4] = {0, 0, 0, 0}, az[4] = {0, 0, 0, 0}, an[4] = {0, 0, 0, 0};
            for (int d4 = 0; d4 < 32; d4++) {
                const ulonglong2 wr = pWhh[d4 * 384 + j];
                const ulonglong2 wz = pWhh[d4 * 384 + j + 128];
                const ulonglong2 wn = pWhh[d4 * 384 + j + 256];
                #pragma unroll
                for (int r = 0; r < 4; r++) {
                    const ulonglong2 sv = *(const ulonglong2*)&sm.slots[e][(4 * g + r) * DD + 4 * d4];
                    ar[r] = fma2(sv.x, wr.x, ar[r]);
                    ar[r] = fma2(sv.y, wr.y, ar[r]);
                    az[r] = fma2(sv.x, wz.x, az[r]);
                    az[r] = fma2(sv.y, wz.y, az[r]);
                    an[r] = fma2(sv.x, wn.x, an[r]);
                    an[r] = fma2(sv.y, wn.y, an[r]);
                }
            }
            const float vwr = sm.vwih[e][j], vwz = sm.vwih[e][j + 128], vwn = sm.vwih[e][j + 256];
            #pragma unroll
            for (int r = 0; r < 4; r++) {
                const int n = 4 * g + r;
                const float a = sm.attn[e][n];
                const float hr = sum2(ar[r]) + bh_r;
                const float hz = sum2(az[r]) + bh_z;
                const float hn = sum2(an[r]) + bh_n;
                const float rr = sigm(a * vwr + bi_r + hr);
                const float zz = sigm(a * vwz + bi_z + hz);
                const float nn = tanha(a * vwn + bi_n + rr * hn);
                const float h = sm.slots[e][n * DD + j];
                nv[e][r] = (1.f - zz) * nn + zz * h;
            }
            // per-row stats partials over this warp's 32 columns
            #pragma unroll
            for (int r = 0; r < 4; r++) {
                float s1 = nv[e][r], s2 = s1 * s1;
                #pragma unroll
                for (int off = 16; off > 0; off >>= 1) {
                    s1 += __shfl_down_sync(0xffffffffu, s1, off);
                    s2 += __shfl_down_sync(0xffffffffu, s2, off);
                }
                if (lane == 0) {
                    sm.sp[e][4 * g + r][warp & 3][0] = s1;
                    sm.sp[e][4 * g + r][warp & 3][1] = s2;
                }
            }
        }
        __syncthreads();
        #pragma unroll
        for (int e = 0; e < EPC; e++)
            #pragma unroll
            for (int r = 0; r < 4; r++)
                sm.slots[e][(4 * g + r) * DD + j] = nv[e][r];
        __syncthreads();

        // (e) folded mlp-LN + W1 GEMM: h1 = relu(rstd*(S - mu*B1_j) + A1p_j)
        #pragma unroll
        for (int e = 0; e < EPC; e++) {
            float mu_[4], rs_[4];
            #pragma unroll
            for (int r = 0; r < 4; r++) {
                const int n = 4 * g + r;
                const float s = sm.sp[e][n][0][0] + sm.sp[e][n][1][0]
                              + sm.sp[e][n][2][0] + sm.sp[e][n][3][0];
                const float q = sm.sp[e][n][0][1] + sm.sp[e][n][1][1]
                              + sm.sp[e][n][2][1] + sm.sp[e][n][3][1];
                mu_[r] = s * (1.f / 128.f);
                rs_[r] = rsqrtf(q * (1.f / 128.f) - mu_[r] * mu_[r] + 1e-5f);
            }
            u64 acc[4] = {0, 0, 0, 0};
            for (int d4 = 0; d4 < 32; d4++) {
                const ulonglong2 w = pmW1g[d4 * DD + j];
                #pragma unroll
                for (int r = 0; r < 4; r++) {
                    const ulonglong2 sv = *(const ulonglong2*)&sm.slots[e][(4 * g + r) * DD + 4 * d4];
                    acc[r] = fma2(sv.x, w.x, acc[r]);
                    acc[r] = fma2(sv.y, w.y, acc[r]);
                }
            }
            #pragma unroll
            for (int r = 0; r < 4; r++) {
                const float S = sum2(acc[r]);
                sm.h1[e][(4 * g + r) * DD + j] =
                    fmaxf(rs_[r] * (S - mu_[r] * B1_j) + A1p_j, 0.f);
            }
        }
        __syncthreads();
        // (f) slots += h1@W2 + b2
        #pragma unroll
        for (int e = 0; e < EPC; e++) {
            u64 acc[4] = {0, 0, 0, 0};
            for (int d4 = 0; d4 < 32; d4++) {
                const ulonglong2 w = pmW2[d4 * DD + j];
                #pragma unroll
                for (int r = 0; r < 4; r++) {
                    const ulonglong2 sv = *(const ulonglong2*)&sm.h1[e][(4 * g + r) * DD + 4 * d4];
                    acc[r] = fma2(sv.x, w.x, acc[r]);
                    acc[r] = fma2(sv.y, w.y, acc[r]);
                }
            }
            #pragma unroll
            for (int r = 0; r < 4; r++)
                sm.slots[e][(4 * g + r) * DD + j] += sum2(acc[r]) + mb2_j;
        }
        __syncthreads();
    }

    // final F.normalize — warp w row w, per entry
    #pragma unroll
    for (int e = 0; e < EPC; e++) {
        const float* src = &sm.slots[e][warp * DD];
        float x0 = src[lane], x1 = src[lane + 32], x2 = src[lane + 64], x3 = src[lane + 96];
        float q = x0 * x0 + x1 * x1 + x2 * x2 + x3 * x3;
        #pragma unroll
        for (int off = 16; off > 0; off >>= 1) q += __shfl_down_sync(0xffffffffu, q, off);
        q = __shfl_sync(0xffffffffu, q, 0);
        const float inv = 1.f / fmaxf(sqrtf(q), 1e-8f);
        float* dst = out + (e0 + e) * (NS * DD) + warp * DD;
        dst[lane]      = x0 * inv;
        dst[lane + 32] = x1 * inv;
        dst[lane + 64] = x2 * inv;
        dst[lane + 96] = x3 * inv;
    }
}

// ---------------------------------------------------------------------------
// Kernel 3: temporal blend, one CTA per (b, n) row chain. 128 threads.
// out[b,t,n,:] = 0.7*out[b,t,n,:] + 0.3*tanh(out[b,t-1,n,:] @ Wt)
// ---------------------------------------------------------------------------
__global__ __launch_bounds__(128) void temporal_kernel(float* __restrict__ out)
{
    __shared__ __align__(16) float s_prev[DD];
    const int j = threadIdx.x;
    const int b = blockIdx.x >> 4;
    const int n = blockIdx.x & 15;
    float* base = out + ((long)b * 64) * (NS * DD) + n * DD;

    s_prev[j] = base[j];
    __syncthreads();

    for (int t = 1; t < 64; t++) {
        float* cur = base + t * (NS * DD);
        const float c = cur[j];
        u64 acc = 0;
        for (int d4 = 0; d4 < 32; d4++) {
            const ulonglong2 s = *(const ulonglong2*)&s_prev[4 * d4];
            const ulonglong2 w = pWt[d4 * DD + j];
            acc = fma2(s.x, w.x, acc);
            acc = fma2(s.y, w.y, acc);
        }
        const float v = 0.7f * c + 0.3f * tanha(sum2(acc));
        __syncthreads();
        s_prev[j] = v;
        cur[j] = v;
        __syncthreads();
    }
}

// ---------------------------------------------------------------------------
extern "C" void kernel_launch(void* const* d_in, const int* in_sizes, int n_in,
                              void* d_out, int out_size)
{
    const float* obs    = (const float*)d_in[0];
    const float* eW1    = (const float*)d_in[1];
    const float* eb1    = (const float*)d_in[2];
    const float* eW2    = (const float*)d_in[3];
    const float* eb2    = (const float*)d_in[4];
    const float* skipW  = (const float*)d_in[5];
    const float* smu    = (const float*)d_in[6];
    const float* Wk     = (const float*)d_in[7];
    const float* Wv     = (const float*)d_in[8];
    const float* Wq     = (const float*)d_in[9];
    const float* gWih   = (const float*)d_in[10];
    const float* gWhh   = (const float*)d_in[11];
    const float* gbih   = (const float*)d_in[12];
    const float* gbhh   = (const float*)d_in[13];
    const float* mW1    = (const float*)d_in[14];
    const float* mb1    = (const float*)d_in[15];
    const float* mW2    = (const float*)d_in[16];
    const float* mb2    = (const float*)d_in[17];
    const float* lin_g  = (const float*)d_in[18];
    const float* lin_b  = (const float*)d_in[19];
    const float* lsl_g  = (const float*)d_in[20];
    const float* lsl_b  = (const float*)d_in[21];
    const float* lml_g  = (const float*)d_in[22];
    const float* lml_b  = (const float*)d_in[23];
    const float* Wt     = (const float*)d_in[24];
    float* out = (float*)d_out;

    pack_all<<<(106496 + 255) / 256, 256>>>(eW1, eW2, skipW, Wk, Wv, Wq,
                                            gWih, gWhh, mW1, mW2, Wt, lml_g);
    prep_vec<<<1, 128>>>(mW1, mb1, lml_g, lml_b);

    enc_kernel<<<BT / 8, 256>>>(obs, eb1, eb2);

    slot_kernel<<<BT / EPC, 512>>>(smu, gbih, gbhh, mb2,
                                   lin_g, lin_b, lsl_g, lsl_b, out);

    temporal_kernel<<<256 * NS, 128>>>(out);
}

// round 6
// speedup vs baseline: 1.7478x; 1.7478x over previous
#include <cuda_runtime.h>
#include <math.h>

#define BT    16384
#define DOBS  512
#define DD    128
#define NS    16
#define HH    256

typedef unsigned long long u64;

__device__ __forceinline__ u64 fma2(u64 a, u64 b, u64 c) {
    u64 d;
    asm("fma.rn.f32x2 %0, %1, %2, %3;" : "=l"(d) : "l"(a), "l"(b), "l"(c));
    return d;
}
__device__ __forceinline__ float sum2(u64 a) {
    float2 f = *(float2*)&a;
    return f.x + f.y;
}
__device__ __forceinline__ u64 pack2(float lo, float hi) {
    u64 r;
    asm("mov.b64 %0, {%1, %2};" : "=l"(r) : "f"(lo), "f"(hi));
    return r;
}
__device__ __forceinline__ float tanha(float x) {
    float y;
    asm("tanh.approx.f32 %0, %1;" : "=f"(y) : "f"(x));
    return y;
}
__device__ __forceinline__ float sigm(float x) { return 0.5f * tanha(0.5f * x) + 0.5f; }

// ---------------- device scratch ----------------
__device__ float g_z[BT * DD];

// pair-interleaved packed weights
__device__ ulonglong2 pW1[128 * 256];
__device__ ulonglong2 pW2[64 * 128];
__device__ ulonglong2 pSkip[128 * 128];
__device__ ulonglong2 pWk[32 * 128];
__device__ ulonglong2 pWv[32 * 128];
__device__ ulonglong2 pWqT[32 * 128];
__device__ ulonglong2 pWih[32 * 384];
__device__ ulonglong2 pWhh[32 * 384];
__device__ ulonglong2 pmW1[32 * 128];
__device__ ulonglong2 pmW2[32 * 128];
__device__ ulonglong2 pWt[32 * 128];

// ---------------- fused pack kernel ----------------
__device__ __forceinline__ void pack_elem(const float* __restrict__ src,
                                          ulonglong2* __restrict__ dst, int C, int idx)
{
    int c = idx % C, k4 = idx / C;
    const float* s = src + (4 * k4) * C + c;
    ulonglong2 v;
    v.x = pack2(s[0], s[C]);
    v.y = pack2(s[2 * C], s[3 * C]);
    dst[idx] = v;
}
__device__ __forceinline__ void packT_elem(const float* __restrict__ src,
                                           ulonglong2* __restrict__ dst, int K, int C4, int idx)
{
    int i = idx % K, j4 = idx / K;
    const float* s = src + i * (C4 * 4) + 4 * j4;
    ulonglong2 v;
    v.x = pack2(s[0], s[1]);
    v.y = pack2(s[2], s[3]);
    dst[idx] = v;
}

__global__ __launch_bounds__(256) void pack_all(
    const float* __restrict__ eW1, const float* __restrict__ eW2,
    const float* __restrict__ skipW,
    const float* __restrict__ Wk, const float* __restrict__ Wv,
    const float* __restrict__ Wq,
    const float* __restrict__ gWih, const float* __restrict__ gWhh,
    const float* __restrict__ mW1, const float* __restrict__ mW2,
    const float* __restrict__ Wt)
{
    int idx = blockIdx.x * 256 + threadIdx.x;
    if (idx < 32768) { pack_elem(eW1,  pW1,  256, idx); return; }  idx -= 32768;
    if (idx < 8192)  { pack_elem(eW2,  pW2,  128, idx); return; }  idx -= 8192;
    if (idx < 16384) { pack_elem(skipW,pSkip,128, idx); return; }  idx -= 16384;
    if (idx < 4096)  { pack_elem(Wk,   pWk,  128, idx); return; }  idx -= 4096;
    if (idx < 4096)  { pack_elem(Wv,   pWv,  128, idx); return; }  idx -= 4096;
    if (idx < 4096)  { packT_elem(Wq,  pWqT, 128, 32, idx); return; } idx -= 4096;
    if (idx < 12288) { pack_elem(gWih, pWih, 384, idx); return; }  idx -= 12288;
    if (idx < 12288) { pack_elem(gWhh, pWhh, 384, idx); return; }  idx -= 12288;
    if (idx < 4096)  { pack_elem(mW1,  pmW1, 128, idx); return; }  idx -= 4096;
    if (idx < 4096)  { pack_elem(mW2,  pmW2, 128, idx); return; }  idx -= 4096;
    if (idx < 4096)  { pack_elem(Wt,   pWt,  128, idx); return; }
}

// ---------------------------------------------------------------------------
// Kernel 1: encoder (R3 version, verbatim)
// ---------------------------------------------------------------------------
__global__ __launch_bounds__(256) void enc_kernel(
    const float* __restrict__ obs,
    const float* __restrict__ b1, const float* __restrict__ b2)
{
    __shared__ __align__(16) float s_obs[8 * DOBS];
    __shared__ __align__(16) float s_h[8 * HH];
    __shared__ __align__(16) float s_p1[8 * DD];

    const int tid = threadIdx.x;
    const long e0 = (long)blockIdx.x * 8;
    const float* op = obs + e0 * DOBS;

    for (int i = tid; i < 8 * DOBS / 4; i += 256)
        ((float4*)s_obs)[i] = ((const float4*)op)[i];
    __syncthreads();

    {
        const int j = tid;
        u64 acc[8] = {0, 0, 0, 0, 0, 0, 0, 0};
        for (int d4 = 0; d4 < 128; d4++) {
            const ulonglong2 w = pW1[d4 * HH + j];
            #pragma unroll
            for (int r = 0; r < 8; r++) {
                const ulonglong2 s = *(const ulonglong2*)&s_obs[r * DOBS + 4 * d4];
                acc[r] = fma2(s.x, w.x, acc[r]);
                acc[r] = fma2(s.y, w.y, acc[r]);
            }
        }
        const float bj = b1[j];
        #pragma unroll
        for (int r = 0; r < 8; r++) {
            const float a = sum2(acc[r]) + bj;
            s_h[r * HH + j] = 0.5f * a * (1.f + erff(a * 0.70710678118654752f));
        }
    }
    __syncthreads();

    const int j = tid & 127;
    const int half = tid >> 7;
    u64 acc[8] = {0, 0, 0, 0, 0, 0, 0, 0};

    if (half == 0) {
        for (int d4 = 0; d4 < 64; d4++) {
            const ulonglong2 w = pW2[d4 * DD + j];
            #pragma unroll
            for (int r = 0; r < 8; r++) {
                const ulonglong2 s = *(const ulonglong2*)&s_h[r * HH + 4 * d4];
                acc[r] = fma2(s.x, w.x, acc[r]);
                acc[r] = fma2(s.y, w.y, acc[r]);
            }
        }
        for (int d4 = 0; d4 < 32; d4++) {
            const ulonglong2 w = pSkip[d4 * DD + j];
            #pragma unroll
            for (int r = 0; r < 8; r++) {
                const ulonglong2 s = *(const ulonglong2*)&s_obs[r * DOBS + 4 * d4];
                acc[r] = fma2(s.x, w.x, acc[r]);
                acc[r] = fma2(s.y, w.y, acc[r]);
            }
        }
    } else {
        for (int d4 = 32; d4 < 128; d4++) {
            const ulonglong2 w = pSkip[d4 * DD + j];
            #pragma unroll
            for (int r = 0; r < 8; r++) {
                const ulonglong2 s = *(const ulonglong2*)&s_obs[r * DOBS + 4 * d4];
                acc[r] = fma2(s.x, w.x, acc[r]);
                acc[r] = fma2(s.y, w.y, acc[r]);
            }
        }
        #pragma unroll
        for (int r = 0; r < 8; r++) s_p1[r * DD + j] = sum2(acc[r]);
    }
    __syncthreads();

    if (half == 0) {
        const float bj = b2[j];
        #pragma unroll
        for (int r = 0; r < 8; r++)
            g_z[(e0 + r) * DD + j] = tanha(sum2(acc[r]) + s_p1[r * DD + j] + bj);
    }
}

// ---------------------------------------------------------------------------
__device__ __forceinline__ void norm_store128(
    const float* __restrict__ src, float* __restrict__ dst, int lane)
{
    float x0 = src[lane], x1 = src[lane + 32], x2 = src[lane + 64], x3 = src[lane + 96];
    float q = x0 * x0 + x1 * x1 + x2 * x2 + x3 * x3;
    #pragma unroll
    for (int off = 16; off > 0; off >>= 1) q += __shfl_down_sync(0xffffffffu, q, off);
    q = __shfl_sync(0xffffffffu, q, 0);
    const float inv = 1.f / fmaxf(sqrtf(q), 1e-8f);
    dst[lane]      = x0 * inv;
    dst[lane + 32] = x1 * inv;
    dst[lane + 64] = x2 * inv;
    dst[lane + 96] = x3 * inv;
}

// ---------------------------------------------------------------------------
// Kernel 2: fused slot attention (R3 version, verbatim). One CTA per (b,t),
// 512 threads = 16 warps, 2 CTAs/SM.
// ---------------------------------------------------------------------------
__global__ __launch_bounds__(512, 2) void slot_kernel(
    const float* __restrict__ slot_mu,
    const float* __restrict__ bih, const float* __restrict__ bhh,
    const float* __restrict__ mb1, const float* __restrict__ mb2,
    const float* __restrict__ lin_g, const float* __restrict__ lin_b,
    const float* __restrict__ lsl_g, const float* __restrict__ lsl_b,
    const float* __restrict__ lml_g, const float* __restrict__ lml_b,
    float* __restrict__ out)
{
    __shared__ __align__(16) float s_inp[DD], s_k[DD], s_v[DD], s_wqk[DD];
    __shared__ __align__(16) float s_vwih[384];
    __shared__ __align__(16) float s_slots[NS * DD];
    __shared__ __align__(16) float s_ln[NS * DD];
    __shared__ __align__(16) float s_h1[NS * DD];
    __shared__ __align__(16) float s_lnp[512];
    __shared__ float s_attn[NS], s_logits[NS];
    __shared__ float s_red[20];

    const int tid = threadIdx.x, lane = tid & 31, warp = tid >> 5;
    const int j = tid & 127, g = tid >> 7;
    const long e = blockIdx.x;

    const float zv = (tid < DD) ? g_z[e * DD + tid] : 0.f;
    if (tid < DD) {
        float s1 = zv, s2 = zv * zv;
        #pragma unroll
        for (int off = 16; off > 0; off >>= 1) {
            s1 += __shfl_down_sync(0xffffffffu, s1, off);
            s2 += __shfl_down_sync(0xffffffffu, s2, off);
        }
        if (lane == 0) { s_red[warp] = s1; s_red[8 + warp] = s2; }
    }
    __syncthreads();
    if (tid == 0) {
        float s = s_red[0] + s_red[1] + s_red[2] + s_red[3];
        float q = s_red[8] + s_red[9] + s_red[10] + s_red[11];
        const float mu = s * (1.f / 128.f);
        const float var = q * (1.f / 128.f) - mu * mu;
        s_red[16] = mu;
        s_red[17] = rsqrtf(var + 1e-5f);
    }
    __syncthreads();
    if (tid < DD) s_inp[tid] = (zv - s_red[16]) * s_red[17] * lin_g[tid] + lin_b[tid];
    __syncthreads();

    if (g == 0 || g == 1) {
        const ulonglong2* W = (g == 0) ? pWk : pWv;
        u64 acc = 0;
        for (int d4 = 0; d4 < 32; d4++) {
            const ulonglong2 s = *(const ulonglong2*)&s_inp[4 * d4];
            const ulonglong2 w = W[d4 * DD + j];
            acc = fma2(s.x, w.x, acc);
            acc = fma2(s.y, w.y, acc);
        }
        if (g == 0) s_k[j] = sum2(acc); else s_v[j] = sum2(acc);
    } else if (g == 2) {
        const int t2 = tid - 256;
        ((float4*)s_slots)[t2]       = ((const float4*)slot_mu)[t2];
        ((float4*)s_slots)[t2 + 128] = ((const float4*)slot_mu)[t2 + 128];
        ((float4*)s_slots)[t2 + 256] = ((const float4*)slot_mu)[t2 + 256];
        ((float4*)s_slots)[t2 + 384] = ((const float4*)slot_mu)[t2 + 384];
    } else {
        const int t3 = tid - 384;
        if (t3 < 32)       ((float4*)s_lnp)[t3] = ((const float4*)lsl_g)[t3];
        else if (t3 < 64)  ((float4*)s_lnp)[t3] = ((const float4*)lsl_b)[t3 - 32];
        else if (t3 < 96)  ((float4*)s_lnp)[t3] = ((const float4*)lml_g)[t3 - 64];
        else               ((float4*)s_lnp)[t3] = ((const float4*)lml_b)[t3 - 96];
    }
    __syncthreads();

    if (tid < DD) {
        u64 acc = 0;
        for (int j4 = 0; j4 < 32; j4++) {
            const ulonglong2 s = *(const ulonglong2*)&s_k[4 * j4];
            const ulonglong2 w = pWqT[j4 * DD + tid];
            acc = fma2(s.x, w.x, acc);
            acc = fma2(s.y, w.y, acc);
        }
        s_wqk[tid] = sum2(acc);
    } else {
        const int c = tid - DD;
        u64 acc = 0;
        for (int d4 = 0; d4 < 32; d4++) {
            const ulonglong2 s = *(const ulonglong2*)&s_v[4 * d4];
            const ulonglong2 w = pWih[d4 * 384 + c];
            acc = fma2(s.x, w.x, acc);
            acc = fma2(s.y, w.y, acc);
        }
        s_vwih[c] = sum2(acc);
    }
    __syncthreads();

    const float invscale = 0.088388347648318447f;

    for (int it = 0; it < 3; it++) {
        {
            const float* src = &s_slots[warp * DD];
            float x0 = src[lane], x1 = src[lane + 32], x2 = src[lane + 64], x3 = src[lane + 96];
            float s = x0 + x1 + x2 + x3;
            float q = x0 * x0 + x1 * x1 + x2 * x2 + x3 * x3;
            #pragma unroll
            for (int off = 16; off > 0; off >>= 1) {
                s += __shfl_down_sync(0xffffffffu, s, off);
                q += __shfl_down_sync(0xffffffffu, q, off);
            }
            s = __shfl_sync(0xffffffffu, s, 0);
            q = __shfl_sync(0xffffffffu, q, 0);
            const float mu = s * (1.f / 128.f);
            const float rstd = rsqrtf(q * (1.f / 128.f) - mu * mu + 1e-5f);
            const float n0 = (x0 - mu) * rstd * s_lnp[lane]      + s_lnp[128 + lane];
            const float n1 = (x1 - mu) * rstd * s_lnp[lane + 32] + s_lnp[160 + lane];
            const float n2 = (x2 - mu) * rstd * s_lnp[lane + 64] + s_lnp[192 + lane];
            const float n3 = (x3 - mu) * rstd * s_lnp[lane + 96] + s_lnp[224 + lane];
            float p = n0 * s_wqk[lane] + n1 * s_wqk[lane + 32]
                    + n2 * s_wqk[lane + 64] + n3 * s_wqk[lane + 96];
            #pragma unroll
            for (int off = 16; off > 0; off >>= 1) p += __shfl_down_sync(0xffffffffu, p, off);
            if (lane == 0) s_logits[warp] = p * invscale;
        }
        __syncthreads();
        if (warp == 0 && lane < 16) {
            const float l = s_logits[lane];
            float m = l;
            #pragma unroll
            for (int off = 8; off > 0; off >>= 1)
                m = fmaxf(m, __shfl_xor_sync(0xffffu, m, off));
            const float ex = __expf(l - m);
            float ssum = ex;
            #pragma unroll
            for (int off = 8; off > 0; off >>= 1)
                ssum += __shfl_xor_sync(0xffffu, ssum, off);
            s_attn[lane] = ex / ssum;
        }
        __syncthreads();

        {
            u64 ar[4] = {0, 0, 0, 0}, az[4] = {0, 0, 0, 0}, an[4] = {0, 0, 0, 0};
            for (int d4 = 0; d4 < 32; d4++) {
                const ulonglong2 wr = pWhh[d4 * 384 + j];
                const ulonglong2 wz = pWhh[d4 * 384 + j + 128];
                const ulonglong2 wn = pWhh[d4 * 384 + j + 256];
                #pragma unroll
                for (int r = 0; r < 4; r++) {
                    const ulonglong2 sv = *(const ulonglong2*)&s_slots[(4 * g + r) * DD + 4 * d4];
                    ar[r] = fma2(sv.x, wr.x, ar[r]);
                    ar[r] = fma2(sv.y, wr.y, ar[r]);
                    az[r] = fma2(sv.x, wz.x, az[r]);
                    az[r] = fma2(sv.y, wz.y, az[r]);
                    an[r] = fma2(sv.x, wn.x, an[r]);
                    an[r] = fma2(sv.y, wn.y, an[r]);
                }
            }
            const float vw_r = s_vwih[j], vw_z = s_vwih[j + 128], vw_n = s_vwih[j + 256];
            const float bi_r = bih[j], bi_z = bih[j + 128], bi_n = bih[j + 256];
            const float bh_r = bhh[j], bh_z = bhh[j + 128], bh_n = bhh[j + 256];
            float nv[4];
            #pragma unroll
            for (int r = 0; r < 4; r++) {
                const int n = 4 * g + r;
                const float a = s_attn[n];
                const float hr = sum2(ar[r]) + bh_r;
                const float hz = sum2(az[r]) + bh_z;
                const float hn = sum2(an[r]) + bh_n;
                const float rr = sigm(a * vw_r + bi_r + hr);
                const float zz = sigm(a * vw_z + bi_z + hz);
                const float nn = tanha(a * vw_n + bi_n + rr * hn);
                const float h = s_slots[n * DD + j];
                nv[r] = (1.f - zz) * nn + zz * h;
            }
            __syncthreads();
            #pragma unroll
            for (int r = 0; r < 4; r++) s_slots[(4 * g + r) * DD + j] = nv[r];
        }
        __syncthreads();

        {
            const float* src = &s_slots[warp * DD];
            float x0 = src[lane], x1 = src[lane + 32], x2 = src[lane + 64], x3 = src[lane + 96];
            float s = x0 + x1 + x2 + x3;
            float q = x0 * x0 + x1 * x1 + x2 * x2 + x3 * x3;
            #pragma unroll
            for (int off = 16; off > 0; off >>= 1) {
                s += __shfl_down_sync(0xffffffffu, s, off);
                q += __shfl_down_sync(0xffffffffu, q, off);
            }
            s = __shfl_sync(0xffffffffu, s, 0);
            q = __shfl_sync(0xffffffffu, q, 0);
            const float mu = s * (1.f / 128.f);
            const float rstd = rsqrtf(q * (1.f / 128.f) - mu * mu + 1e-5f);
            float* dst = &s_ln[warp * DD];
            dst[lane]      = (x0 - mu) * rstd * s_lnp[256 + lane]      + s_lnp[384 + lane];
            dst[lane + 32] = (x1 - mu) * rstd * s_lnp[288 + lane]      + s_lnp[416 + lane];
            dst[lane + 64] = (x2 - mu) * rstd * s_lnp[320 + lane]      + s_lnp[448 + lane];
            dst[lane + 96] = (x3 - mu) * rstd * s_lnp[352 + lane]      + s_lnp[480 + lane];
        }
        __syncthreads();

        {
            u64 acc[4] = {0, 0, 0, 0};
            for (int d4 = 0; d4 < 32; d4++) {
                const ulonglong2 w = pmW1[d4 * DD + j];
                #pragma unroll
                for (int r = 0; r < 4; r++) {
                    const ulonglong2 sv = *(const ulonglong2*)&s_ln[(4 * g + r) * DD + 4 * d4];
                    acc[r] = fma2(sv.x, w.x, acc[r]);
                    acc[r] = fma2(sv.y, w.y, acc[r]);
                }
            }
            const float b = mb1[j];
            #pragma unroll
            for (int r = 0; r < 4; r++)
                s_h1[(4 * g + r) * DD + j] = fmaxf(sum2(acc[r]) + b, 0.f);
        }
        __syncthreads();
        {
            u64 acc[4] = {0, 0, 0, 0};
            for (int d4 = 0; d4 < 32; d4++) {
                const ulonglong2 w = pmW2[d4 * DD + j];
                #pragma unroll
                for (int r = 0; r < 4; r++) {
                    const ulonglong2 sv = *(const ulonglong2*)&s_h1[(4 * g + r) * DD + 4 * d4];
                    acc[r] = fma2(sv.x, w.x, acc[r]);
                    acc[r] = fma2(sv.y, w.y, acc[r]);
                }
            }
            const float b = mb2[j];
            #pragma unroll
            for (int r = 0; r < 4; r++)
                s_slots[(4 * g + r) * DD + j] += sum2(acc[r]) + b;
        }
        __syncthreads();
    }

    norm_store128(&s_slots[warp * DD], out + e * (NS * DD) + warp * DD, lane);
}

// ---------------------------------------------------------------------------
// Kernel 3: persistent temporal blend, split by row-halves.
// 512 CTAs = (batch b, row-half). 256 threads = 128 cols x 2 groups of 4 rows.
// Rows are independent chains: out[b,t,n,:] depends only on out[b,t-1,n,:].
// ---------------------------------------------------------------------------
__global__ __launch_bounds__(256) void temporal_kernel(float* __restrict__ out)
{
    __shared__ __align__(16) float s_prev[8 * DD];
    const int tid = threadIdx.x;
    const int j = tid & 127;
    const int gg = tid >> 7;               // 0..1 -> local rows gg*4..gg*4+3
    const int b = blockIdx.x >> 1;
    const int half = blockIdx.x & 1;       // rows half*8..half*8+7
    float* base = out + ((long)b * 64) * (NS * DD) + half * 8 * DD;

    for (int i = tid; i < 8 * DD; i += 256) s_prev[i] = base[i];
    __syncthreads();

    for (int t = 1; t < 64; t++) {
        float* cur = base + t * (NS * DD);
        float c[4];
        #pragma unroll
        for (int r = 0; r < 4; r++) c[r] = cur[(gg * 4 + r) * DD + j];

        u64 acc[4] = {0, 0, 0, 0};
        for (int d4 = 0; d4 < 32; d4++) {
            const ulonglong2 w = pWt[d4 * DD + j];
            #pragma unroll
            for (int r = 0; r < 4; r++) {
                const ulonglong2 s = *(const ulonglong2*)&s_prev[(gg * 4 + r) * DD + 4 * d4];
                acc[r] = fma2(s.x, w.x, acc[r]);
                acc[r] = fma2(s.y, w.y, acc[r]);
            }
        }
        __syncthreads();
        #pragma unroll
        for (int r = 0; r < 4; r++) {
            const float v = 0.7f * c[r] + 0.3f * tanha(sum2(acc[r]));
            cur[(gg * 4 + r) * DD + j] = v;
            s_prev[(gg * 4 + r) * DD + j] = v;
        }
        __syncthreads();
    }
}

// ---------------------------------------------------------------------------
extern "C" void kernel_launch(void* const* d_in, const int* in_sizes, int n_in,
                              void* d_out, int out_size)
{
    const float* obs    = (const float*)d_in[0];
    const float* eW1    = (const float*)d_in[1];
    const float* eb1    = (const float*)d_in[2];
    const float* eW2    = (const float*)d_in[3];
    const float* eb2    = (const float*)d_in[4];
    const float* skipW  = (const float*)d_in[5];
    const float* smu    = (const float*)d_in[6];
    const float* Wk     = (const float*)d_in[7];
    const float* Wv     = (const float*)d_in[8];
    const float* Wq     = (const float*)d_in[9];
    const float* gWih   = (const float*)d_in[10];
    const float* gWhh   = (const float*)d_in[11];
    const float* gbih   = (const float*)d_in[12];
    const float* gbhh   = (const float*)d_in[13];
    const float* mW1    = (const float*)d_in[14];
    const float* mb1    = (const float*)d_in[15];
    const float* mW2    = (const float*)d_in[16];
    const float* mb2    = (const float*)d_in[17];
    const float* lin_g  = (const float*)d_in[18];
    const float* lin_b  = (const float*)d_in[19];
    const float* lsl_g  = (const float*)d_in[20];
    const float* lsl_b  = (const float*)d_in[21];
    const float* lml_g  = (const float*)d_in[22];
    const float* lml_b  = (const float*)d_in[23];
    const float* Wt     = (const float*)d_in[24];
    float* out = (float*)d_out;

    pack_all<<<(106496 + 255) / 256, 256>>>(eW1, eW2, skipW, Wk, Wv, Wq,
                                            gWih, gWhh, mW1, mW2, Wt);

    enc_kernel<<<BT / 8, 256>>>(obs, eb1, eb2);

    slot_kernel<<<BT, 512>>>(smu, gbih, gbhh, mb1, mb2,
                             lin_g, lin_b, lsl_g, lsl_b, lml_g, lml_b, out);

    temporal_kernel<<<512, 256>>>(out);
}

// round 7
// speedup vs baseline: 1.7478x; 1.0000x over previous
#include <cuda_runtime.h>
#include <math.h>

#define BT    16384
#define DOBS  512
#define DD    128
#define NS    16
#define HH    256

typedef unsigned long long u64;

__device__ __forceinline__ u64 fma2(u64 a, u64 b, u64 c) {
    u64 d;
    asm("fma.rn.f32x2 %0, %1, %2, %3;" : "=l"(d) : "l"(a), "l"(b), "l"(c));
    return d;
}
__device__ __forceinline__ float sum2(u64 a) {
    float2 f = *(float2*)&a;
    return f.x + f.y;
}
__device__ __forceinline__ u64 pack2(float lo, float hi) {
    u64 r;
    asm("mov.b64 %0, {%1, %2};" : "=l"(r) : "f"(lo), "f"(hi));
    return r;
}
__device__ __forceinline__ float tanha(float x) {
    float y;
    asm("tanh.approx.f32 %0, %1;" : "=f"(y) : "f"(x));
    return y;
}
__device__ __forceinline__ float sigm(float x) { return 0.5f * tanha(0.5f * x) + 0.5f; }

// ---------------- device scratch ----------------
__device__ float g_z[BT * DD];

// pair-interleaved packed weights
__device__ ulonglong2 pW1[128 * 256];
__device__ ulonglong2 pW2[64 * 128];
__device__ ulonglong2 pSkip[128 * 128];
__device__ ulonglong2 pWk[32 * 128];
__device__ ulonglong2 pWv[32 * 128];
__device__ ulonglong2 pWqT[32 * 128];
__device__ ulonglong2 pWih[32 * 384];
__device__ ulonglong2 pWhh[32 * 384];
__device__ ulonglong2 pmW1[32 * 128];
__device__ ulonglong2 pmW2[32 * 128];
__device__ ulonglong2 pWt[32 * 128];

// ---------------- fused pack kernel ----------------
__device__ __forceinline__ void pack_elem(const float* __restrict__ src,
                                          ulonglong2* __restrict__ dst, int C, int idx)
{
    int c = idx % C, k4 = idx / C;
    const float* s = src + (4 * k4) * C + c;
    ulonglong2 v;
    v.x = pack2(s[0], s[C]);
    v.y = pack2(s[2 * C], s[3 * C]);
    dst[idx] = v;
}
__device__ __forceinline__ void packT_elem(const float* __restrict__ src,
                                           ulonglong2* __restrict__ dst, int K, int C4, int idx)
{
    int i = idx % K, j4 = idx / K;
    const float* s = src + i * (C4 * 4) + 4 * j4;
    ulonglong2 v;
    v.x = pack2(s[0], s[1]);
    v.y = pack2(s[2], s[3]);
    dst[idx] = v;
}

__global__ __launch_bounds__(256) void pack_all(
    const float* __restrict__ eW1, const float* __restrict__ eW2,
    const float* __restrict__ skipW,
    const float* __restrict__ Wk, const float* __restrict__ Wv,
    const float* __restrict__ Wq,
    const float* __restrict__ gWih, const float* __restrict__ gWhh,
    const float* __restrict__ mW1, const float* __restrict__ mW2,
    const float* __restrict__ Wt)
{
    int idx = blockIdx.x * 256 + threadIdx.x;
    if (idx < 32768) { pack_elem(eW1,  pW1,  256, idx); return; }  idx -= 32768;
    if (idx < 8192)  { pack_elem(eW2,  pW2,  128, idx); return; }  idx -= 8192;
    if (idx < 16384) { pack_elem(skipW,pSkip,128, idx); return; }  idx -= 16384;
    if (idx < 4096)  { pack_elem(Wk,   pWk,  128, idx); return; }  idx -= 4096;
    if (idx < 4096)  { pack_elem(Wv,   pWv,  128, idx); return; }  idx -= 4096;
    if (idx < 4096)  { packT_elem(Wq,  pWqT, 128, 32, idx); return; } idx -= 4096;
    if (idx < 12288) { pack_elem(gWih, pWih, 384, idx); return; }  idx -= 12288;
    if (idx < 12288) { pack_elem(gWhh, pWhh, 384, idx); return; }  idx -= 12288;
    if (idx < 4096)  { pack_elem(mW1,  pmW1, 128, idx); return; }  idx -= 4096;
    if (idx < 4096)  { pack_elem(mW2,  pmW2, 128, idx); return; }  idx -= 4096;
    if (idx < 4096)  { pack_elem(Wt,   pWt,  128, idx); return; }
}

// ---------------------------------------------------------------------------
// Kernel 1: encoder (R3 version, verbatim)
// ---------------------------------------------------------------------------
__global__ __launch_bounds__(256) void enc_kernel(
    const float* __restrict__ obs,
    const float* __restrict__ b1, const float* __restrict__ b2)
{
    __shared__ __align__(16) float s_obs[8 * DOBS];
    __shared__ __align__(16) float s_h[8 * HH];
    __shared__ __align__(16) float s_p1[8 * DD];

    const int tid = threadIdx.x;
    const long e0 = (long)blockIdx.x * 8;
    const float* op = obs + e0 * DOBS;

    for (int i = tid; i < 8 * DOBS / 4; i += 256)
        ((float4*)s_obs)[i] = ((const float4*)op)[i];
    __syncthreads();

    {
        const int j = tid;
        u64 acc[8] = {0, 0, 0, 0, 0, 0, 0, 0};
        for (int d4 = 0; d4 < 128; d4++) {
            const ulonglong2 w = pW1[d4 * HH + j];
            #pragma unroll
            for (int r = 0; r < 8; r++) {
                const ulonglong2 s = *(const ulonglong2*)&s_obs[r * DOBS + 4 * d4];
                acc[r] = fma2(s.x, w.x, acc[r]);
                acc[r] = fma2(s.y, w.y, acc[r]);
            }
        }
        const float bj = b1[j];
        #pragma unroll
        for (int r = 0; r < 8; r++) {
            const float a = sum2(acc[r]) + bj;
            s_h[r * HH + j] = 0.5f * a * (1.f + erff(a * 0.70710678118654752f));
        }
    }
    __syncthreads();

    const int j = tid & 127;
    const int half = tid >> 7;
    u64 acc[8] = {0, 0, 0, 0, 0, 0, 0, 0};

    if (half == 0) {
        for (int d4 = 0; d4 < 64; d4++) {
            const ulonglong2 w = pW2[d4 * DD + j];
            #pragma unroll
            for (int r = 0; r < 8; r++) {
                const ulonglong2 s = *(const ulonglong2*)&s_h[r * HH + 4 * d4];
                acc[r] = fma2(s.x, w.x, acc[r]);
                acc[r] = fma2(s.y, w.y, acc[r]);
            }
        }
        for (int d4 = 0; d4 < 32; d4++) {
            const ulonglong2 w = pSkip[d4 * DD + j];
            #pragma unroll
            for (int r = 0; r < 8; r++) {
                const ulonglong2 s = *(const ulonglong2*)&s_obs[r * DOBS + 4 * d4];
                acc[r] = fma2(s.x, w.x, acc[r]);
                acc[r] = fma2(s.y, w.y, acc[r]);
            }
        }
    } else {
        for (int d4 = 32; d4 < 128; d4++) {
            const ulonglong2 w = pSkip[d4 * DD + j];
            #pragma unroll
            for (int r = 0; r < 8; r++) {
                const ulonglong2 s = *(const ulonglong2*)&s_obs[r * DOBS + 4 * d4];
                acc[r] = fma2(s.x, w.x, acc[r]);
                acc[r] = fma2(s.y, w.y, acc[r]);
            }
        }
        #pragma unroll
        for (int r = 0; r < 8; r++) s_p1[r * DD + j] = sum2(acc[r]);
    }
    __syncthreads();

    if (half == 0) {
        const float bj = b2[j];
        #pragma unroll
        for (int r = 0; r < 8; r++)
            g_z[(e0 + r) * DD + j] = tanha(sum2(acc[r]) + s_p1[r * DD + j] + bj);
    }
}

// ---------------------------------------------------------------------------
__device__ __forceinline__ void norm_store128(
    const float* __restrict__ src, float* __restrict__ dst, int lane)
{
    float x0 = src[lane], x1 = src[lane + 32], x2 = src[lane + 64], x3 = src[lane + 96];
    float q = x0 * x0 + x1 * x1 + x2 * x2 + x3 * x3;
    #pragma unroll
    for (int off = 16; off > 0; off >>= 1) q += __shfl_down_sync(0xffffffffu, q, off);
    q = __shfl_sync(0xffffffffu, q, 0);
    const float inv = 1.f / fmaxf(sqrtf(q), 1e-8f);
    dst[lane]      = x0 * inv;
    dst[lane + 32] = x1 * inv;
    dst[lane + 64] = x2 * inv;
    dst[lane + 96] = x3 * inv;
}

// ---------------------------------------------------------------------------
// Kernel 2: fused slot attention (R3 version, verbatim). One CTA per (b,t),
// 512 threads = 16 warps, 2 CTAs/SM.
// ---------------------------------------------------------------------------
__global__ __launch_bounds__(512, 2) void slot_kernel(
    const float* __restrict__ slot_mu,
    const float* __restrict__ bih, const float* __restrict__ bhh,
    const float* __restrict__ mb1, const float* __restrict__ mb2,
    const float* __restrict__ lin_g, const float* __restrict__ lin_b,
    const float* __restrict__ lsl_g, const float* __restrict__ lsl_b,
    const float* __restrict__ lml_g, const float* __restrict__ lml_b,
    float* __restrict__ out)
{
    __shared__ __align__(16) float s_inp[DD], s_k[DD], s_v[DD], s_wqk[DD];
    __shared__ __align__(16) float s_vwih[384];
    __shared__ __align__(16) float s_slots[NS * DD];
    __shared__ __align__(16) float s_ln[NS * DD];
    __shared__ __align__(16) float s_h1[NS * DD];
    __shared__ __align__(16) float s_lnp[512];
    __shared__ float s_attn[NS], s_logits[NS];
    __shared__ float s_red[20];

    const int tid = threadIdx.x, lane = tid & 31, warp = tid >> 5;
    const int j = tid & 127, g = tid >> 7;
    const long e = blockIdx.x;

    const float zv = (tid < DD) ? g_z[e * DD + tid] : 0.f;
    if (tid < DD) {
        float s1 = zv, s2 = zv * zv;
        #pragma unroll
        for (int off = 16; off > 0; off >>= 1) {
            s1 += __shfl_down_sync(0xffffffffu, s1, off);
            s2 += __shfl_down_sync(0xffffffffu, s2, off);
        }
        if (lane == 0) { s_red[warp] = s1; s_red[8 + warp] = s2; }
    }
    __syncthreads();
    if (tid == 0) {
        float s = s_red[0] + s_red[1] + s_red[2] + s_red[3];
        float q = s_red[8] + s_red[9] + s_red[10] + s_red[11];
        const float mu = s * (1.f / 128.f);
        const float var = q * (1.f / 128.f) - mu * mu;
        s_red[16] = mu;
        s_red[17] = rsqrtf(var + 1e-5f);
    }
    __syncthreads();
    if (tid < DD) s_inp[tid] = (zv - s_red[16]) * s_red[17] * lin_g[tid] + lin_b[tid];
    __syncthreads();

    if (g == 0 || g == 1) {
        const ulonglong2* W = (g == 0) ? pWk : pWv;
        u64 acc = 0;
        for (int d4 = 0; d4 < 32; d4++) {
            const ulonglong2 s = *(const ulonglong2*)&s_inp[4 * d4];
            const ulonglong2 w = W[d4 * DD + j];
            acc = fma2(s.x, w.x, acc);
            acc = fma2(s.y, w.y, acc);
        }
        if (g == 0) s_k[j] = sum2(acc); else s_v[j] = sum2(acc);
    } else if (g == 2) {
        const int t2 = tid - 256;
        ((float4*)s_slots)[t2]       = ((const float4*)slot_mu)[t2];
        ((float4*)s_slots)[t2 + 128] = ((const float4*)slot_mu)[t2 + 128];
        ((float4*)s_slots)[t2 + 256] = ((const float4*)slot_mu)[t2 + 256];
        ((float4*)s_slots)[t2 + 384] = ((const float4*)slot_mu)[t2 + 384];
    } else {
        const int t3 = tid - 384;
        if (t3 < 32)       ((float4*)s_lnp)[t3] = ((const float4*)lsl_g)[t3];
        else if (t3 < 64)  ((float4*)s_lnp)[t3] = ((const float4*)lsl_b)[t3 - 32];
        else if (t3 < 96)  ((float4*)s_lnp)[t3] = ((const float4*)lml_g)[t3 - 64];
        else               ((float4*)s_lnp)[t3] = ((const float4*)lml_b)[t3 - 96];
    }
    __syncthreads();

    if (tid < DD) {
        u64 acc = 0;
        for (int j4 = 0; j4 < 32; j4++) {
            const ulonglong2 s = *(const ulonglong2*)&s_k[4 * j4];
            const ulonglong2 w = pWqT[j4 * DD + tid];
            acc = fma2(s.x, w.x, acc);
            acc = fma2(s.y, w.y, acc);
        }
        s_wqk[tid] = sum2(acc);
    } else {
        const int c = tid - DD;
        u64 acc = 0;
        for (int d4 = 0; d4 < 32; d4++) {
            const ulonglong2 s = *(const ulonglong2*)&s_v[4 * d4];
            const ulonglong2 w = pWih[d4 * 384 + c];
            acc = fma2(s.x, w.x, acc);
            acc = fma2(s.y, w.y, acc);
        }
        s_vwih[c] = sum2(acc);
    }
    __syncthreads();

    const float invscale = 0.088388347648318447f;

    for (int it = 0; it < 3; it++) {
        {
            const float* src = &s_slots[warp * DD];
            float x0 = src[lane], x1 = src[lane + 32], x2 = src[lane + 64], x3 = src[lane + 96];
            float s = x0 + x1 + x2 + x3;
            float q = x0 * x0 + x1 * x1 + x2 * x2 + x3 * x3;
            #pragma unroll
            for (int off = 16; off > 0; off >>= 1) {
                s += __shfl_down_sync(0xffffffffu, s, off);
                q += __shfl_down_sync(0xffffffffu, q, off);
            }
            s = __shfl_sync(0xffffffffu, s, 0);
            q = __shfl_sync(0xffffffffu, q, 0);
            const float mu = s * (1.f / 128.f);
            const float rstd = rsqrtf(q * (1.f / 128.f) - mu * mu + 1e-5f);
            const float n0 = (x0 - mu) * rstd * s_lnp[lane]      + s_lnp[128 + lane];
            const float n1 = (x1 - mu) * rstd * s_lnp[lane + 32] + s_lnp[160 + lane];
            const float n2 = (x2 - mu) * rstd * s_lnp[lane + 64] + s_lnp[192 + lane];
            const float n3 = (x3 - mu) * rstd * s_lnp[lane + 96] + s_lnp[224 + lane];
            float p = n0 * s_wqk[lane] + n1 * s_wqk[lane + 32]
                    + n2 * s_wqk[lane + 64] + n3 * s_wqk[lane + 96];
            #pragma unroll
            for (int off = 16; off > 0; off >>= 1) p += __shfl_down_sync(0xffffffffu, p, off);
            if (lane == 0) s_logits[warp] = p * invscale;
        }
        __syncthreads();
        if (warp == 0 && lane < 16) {
            const float l = s_logits[lane];
            float m = l;
            #pragma unroll
            for (int off = 8; off > 0; off >>= 1)
                m = fmaxf(m, __shfl_xor_sync(0xffffu, m, off));
            const float ex = __expf(l - m);
            float ssum = ex;
            #pragma unroll
            for (int off = 8; off > 0; off >>= 1)
                ssum += __shfl_xor_sync(0xffffu, ssum, off);
            s_attn[lane] = ex / ssum;
        }
        __syncthreads();

        {
            u64 ar[4] = {0, 0, 0, 0}, az[4] = {0, 0, 0, 0}, an[4] = {0, 0, 0, 0};
            for (int d4 = 0; d4 < 32; d4++) {
                const ulonglong2 wr = pWhh[d4 * 384 + j];
                const ulonglong2 wz = pWhh[d4 * 384 + j + 128];
                const ulonglong2 wn = pWhh[d4 * 384 + j + 256];
                #pragma unroll
                for (int r = 0; r < 4; r++) {
                    const ulonglong2 sv = *(const ulonglong2*)&s_slots[(4 * g + r) * DD + 4 * d4];
                    ar[r] = fma2(sv.x, wr.x, ar[r]);
                    ar[r] = fma2(sv.y, wr.y, ar[r]);
                    az[r] = fma2(sv.x, wz.x, az[r]);
                    az[r] = fma2(sv.y, wz.y, az[r]);
                    an[r] = fma2(sv.x, wn.x, an[r]);
                    an[r] = fma2(sv.y, wn.y, an[r]);
                }
            }
            const float vw_r = s_vwih[j], vw_z = s_vwih[j + 128], vw_n = s_vwih[j + 256];
            const float bi_r = bih[j], bi_z = bih[j + 128], bi_n = bih[j + 256];
            const float bh_r = bhh[j], bh_z = bhh[j + 128], bh_n = bhh[j + 256];
            float nv[4];
            #pragma unroll
            for (int r = 0; r < 4; r++) {
                const int n = 4 * g + r;
                const float a = s_attn[n];
                const float hr = sum2(ar[r]) + bh_r;
                const float hz = sum2(az[r]) + bh_z;
                const float hn = sum2(an[r]) + bh_n;
                const float rr = sigm(a * vw_r + bi_r + hr);
                const float zz = sigm(a * vw_z + bi_z + hz);
                const float nn = tanha(a * vw_n + bi_n + rr * hn);
                const float h = s_slots[n * DD + j];
                nv[r] = (1.f - zz) * nn + zz * h;
            }
            __syncthreads();
            #pragma unroll
            for (int r = 0; r < 4; r++) s_slots[(4 * g + r) * DD + j] = nv[r];
        }
        __syncthreads();

        {
            const float* src = &s_slots[warp * DD];
            float x0 = src[lane], x1 = src[lane + 32], x2 = src[lane + 64], x3 = src[lane + 96];
            float s = x0 + x1 + x2 + x3;
            float q = x0 * x0 + x1 * x1 + x2 * x2 + x3 * x3;
            #pragma unroll
            for (int off = 16; off > 0; off >>= 1) {
                s += __shfl_down_sync(0xffffffffu, s, off);
                q += __shfl_down_sync(0xffffffffu, q, off);
            }
            s = __shfl_sync(0xffffffffu, s, 0);
            q = __shfl_sync(0xffffffffu, q, 0);
            const float mu = s * (1.f / 128.f);
            const float rstd = rsqrtf(q * (1.f / 128.f) - mu * mu + 1e-5f);
            float* dst = &s_ln[warp * DD];
            dst[lane]      = (x0 - mu) * rstd * s_lnp[256 + lane]      + s_lnp[384 + lane];
            dst[lane + 32] = (x1 - mu) * rstd * s_lnp[288 + lane]      + s_lnp[416 + lane];
            dst[lane + 64] = (x2 - mu) * rstd * s_lnp[320 + lane]      + s_lnp[448 + lane];
            dst[lane + 96] = (x3 - mu) * rstd * s_lnp[352 + lane]      + s_lnp[480 + lane];
        }
        __syncthreads();

        {
            u64 acc[4] = {0, 0, 0, 0};
            for (int d4 = 0; d4 < 32; d4++) {
                const ulonglong2 w = pmW1[d4 * DD + j];
                #pragma unroll
                for (int r = 0; r < 4; r++) {
                    const ulonglong2 sv = *(const ulonglong2*)&s_ln[(4 * g + r) * DD + 4 * d4];
                    acc[r] = fma2(sv.x, w.x, acc[r]);
                    acc[r] = fma2(sv.y, w.y, acc[r]);
                }
            }
            const float b = mb1[j];
            #pragma unroll
            for (int r = 0; r < 4; r++)
                s_h1[(4 * g + r) * DD + j] = fmaxf(sum2(acc[r]) + b, 0.f);
        }
        __syncthreads();
        {
            u64 acc[4] = {0, 0, 0, 0};
            for (int d4 = 0; d4 < 32; d4++) {
                const ulonglong2 w = pmW2[d4 * DD + j];
                #pragma unroll
                for (int r = 0; r < 4; r++) {
                    const ulonglong2 sv = *(const ulonglong2*)&s_h1[(4 * g + r) * DD + 4 * d4];
                    acc[r] = fma2(sv.x, w.x, acc[r]);
                    acc[r] = fma2(sv.y, w.y, acc[r]);
                }
            }
            const float b = mb2[j];
            #pragma unroll
            for (int r = 0; r < 4; r++)
                s_slots[(4 * g + r) * DD + j] += sum2(acc[r]) + b;
        }
        __syncthreads();
    }

    norm_store128(&s_slots[warp * DD], out + e * (NS * DD) + warp * DD, lane);
}

// ---------------------------------------------------------------------------
// Kernel 3: persistent temporal blend, split by row-halves.
// 512 CTAs = (batch b, row-half). 256 threads = 128 cols x 2 groups of 4 rows.
// Rows are independent chains: out[b,t,n,:] depends only on out[b,t-1,n,:].
// ---------------------------------------------------------------------------
__global__ __launch_bounds__(256) void temporal_kernel(float* __restrict__ out)
{
    __shared__ __align__(16) float s_prev[8 * DD];
    const int tid = threadIdx.x;
    const int j = tid & 127;
    const int gg = tid >> 7;               // 0..1 -> local rows gg*4..gg*4+3
    const int b = blockIdx.x >> 1;
    const int half = blockIdx.x & 1;       // rows half*8..half*8+7
    float* base = out + ((long)b * 64) * (NS * DD) + half * 8 * DD;

    for (int i = tid; i < 8 * DD; i += 256) s_prev[i] = base[i];
    __syncthreads();

    for (int t = 1; t < 64; t++) {
        float* cur = base + t * (NS * DD);
        float c[4];
        #pragma unroll
        for (int r = 0; r < 4; r++) c[r] = cur[(gg * 4 + r) * DD + j];

        u64 acc[4] = {0, 0, 0, 0};
        for (int d4 = 0; d4 < 32; d4++) {
            const ulonglong2 w = pWt[d4 * DD + j];
            #pragma unroll
            for (int r = 0; r < 4; r++) {
                const ulonglong2 s = *(const ulonglong2*)&s_prev[(gg * 4 + r) * DD + 4 * d4];
                acc[r] = fma2(s.x, w.x, acc[r]);
                acc[r] = fma2(s.y, w.y, acc[r]);
            }
        }
        __syncthreads();
        #pragma unroll
        for (int r = 0; r < 4; r++) {
            const float v = 0.7f * c[r] + 0.3f * tanha(sum2(acc[r]));
            cur[(gg * 4 + r) * DD + j] = v;
            s_prev[(gg * 4 + r) * DD + j] = v;
        }
        __syncthreads();
    }
}

// ---------------------------------------------------------------------------
extern "C" void kernel_launch(void* const* d_in, const int* in_sizes, int n_in,
                              void* d_out, int out_size)
{
    const float* obs    = (const float*)d_in[0];
    const float* eW1    = (const float*)d_in[1];
    const float* eb1    = (const float*)d_in[2];
    const float* eW2    = (const float*)d_in[3];
    const float* eb2    = (const float*)d_in[4];
    const float* skipW  = (const float*)d_in[5];
    const float* smu    = (const float*)d_in[6];
    const float* Wk     = (const float*)d_in[7];
    const float* Wv     = (const float*)d_in[8];
    const float* Wq     = (const float*)d_in[9];
    const float* gWih   = (const float*)d_in[10];
    const float* gWhh   = (const float*)d_in[11];
    const float* gbih   = (const float*)d_in[12];
    const float* gbhh   = (const float*)d_in[13];
    const float* mW1    = (const float*)d_in[14];
    const float* mb1    = (const float*)d_in[15];
    const float* mW2    = (const float*)d_in[16];
    const float* mb2    = (const float*)d_in[17];
    const float* lin_g  = (const float*)d_in[18];
    const float* lin_b  = (const float*)d_in[19];
    const float* lsl_g  = (const float*)d_in[20];
    const float* lsl_b  = (const float*)d_in[21];
    const float* lml_g  = (const float*)d_in[22];
    const float* lml_b  = (const float*)d_in[23];
    const float* Wt     = (const float*)d_in[24];
    float* out = (float*)d_out;

    pack_all<<<(106496 + 255) / 256, 256>>>(eW1, eW2, skipW, Wk, Wv, Wq,
                                            gWih, gWhh, mW1, mW2, Wt);

    enc_kernel<<<BT / 8, 256>>>(obs, eb1, eb2);

    slot_kernel<<<BT, 512>>>(smu, gbih, gbhh, mb1, mb2,
                             lin_g, lin_b, lsl_g, lsl_b, lml_g, lml_b, out);

    temporal_kernel<<<512, 256>>>(out);
}

// round 10
// speedup vs baseline: 3.2668x; 1.8691x over previous
#include <cuda_runtime.h>
#include <cuda_bf16.h>
#include <stdint.h>
#include <math.h>

#define BT 16384
#define DOBS 512
#define DD 128
#define NS 16
#define HH 256

typedef unsigned long long u64;
typedef unsigned int u32;
typedef unsigned short u16;

__device__ __forceinline__ u64 fma2(u64 a, u64 b, u64 c) {
    u64 d;
    asm("fma.rn.f32x2 %0, %1, %2, %3;" : "=l"(d) : "l"(a), "l"(b), "l"(c));
    return d;
}
__device__ __forceinline__ float sum2(u64 a) {
    float2 f = *(float2*)&a;
    return f.x + f.y;
}
__device__ __forceinline__ u64 pack2(float lo, float hi) {
    u64 r;
    asm("mov.b64 %0, {%1, %2};" : "=l"(r) : "f"(lo), "f"(hi));
    return r;
}
__device__ __forceinline__ float tanha(float x) {
    float y;
    asm("tanh.approx.f32 %0, %1;" : "=f"(y) : "f"(x));
    return y;
}
__device__ __forceinline__ float sigm(float x) { return 0.5f * tanha(0.5f * x) + 0.5f; }

__device__ __forceinline__ u32 split_pair(float v0, float v1, u32& lo_out) {
    __nv_bfloat16 h0 = __float2bfloat16(v0), h1 = __float2bfloat16(v1);
    __nv_bfloat16 l0 = __float2bfloat16(v0 - __bfloat162float(h0));
    __nv_bfloat16 l1 = __float2bfloat16(v1 - __bfloat162float(h1));
    lo_out = (u32)__bfloat16_as_ushort(l0) | ((u32)__bfloat16_as_ushort(l1) << 16);
    return (u32)__bfloat16_as_ushort(h0) | ((u32)__bfloat16_as_ushort(h1) << 16);
}
__device__ __forceinline__ float2 unsplit(u32 hi, u32 lo) {
    float2 r;
    r.x = __bfloat162float(__ushort_as_bfloat16((u16)(hi & 0xffff)))
        + __bfloat162float(__ushort_as_bfloat16((u16)(lo & 0xffff)));
    r.y = __bfloat162float(__ushort_as_bfloat16((u16)(hi >> 16)))
        + __bfloat162float(__ushort_as_bfloat16((u16)(lo >> 16)));
    return r;
}

// ---------------- mma / ldmatrix helpers (sm_80+ PTX; compiles for compute_103) ----
__device__ __forceinline__ u32 smem_u32(const void* p) {
    u32 a;
    asm("{ .reg .u64 t; cvta.to.shared.u64 t, %1; cvt.u32.u64 %0, t; }" : "=r"(a) : "l"(p));
    return a;
}
__device__ __forceinline__ void ldsm_x4(u32& a0, u32& a1, u32& a2, u32& a3, u32 ad) {
    asm volatile("ldmatrix.sync.aligned.m8n8.x4.shared.b16 {%0,%1,%2,%3}, [%4];"
                 : "=r"(a0), "=r"(a1), "=r"(a2), "=r"(a3) : "r"(ad));
}
__device__ __forceinline__ void ldsm_x2t(u32& b0, u32& b1, u32 ad) {
    asm volatile("ldmatrix.sync.aligned.m8n8.x2.trans.shared.b16 {%0,%1}, [%2];"
                 : "=r"(b0), "=r"(b1) : "r"(ad));
}
__device__ __forceinline__ void mma_bf16(float* d, u32 a0, u32 a1, u32 a2, u32 a3,
                                         u32 b0, u32 b1) {
    asm volatile(
        "mma.sync.aligned.m16n8k16.row.col.f32.bf16.bf16.f32 "
        "{%0,%1,%2,%3}, {%4,%5,%6,%7}, {%8,%9}, {%0,%1,%2,%3};"
        : "+f"(d[0]), "+f"(d[1]), "+f"(d[2]), "+f"(d[3])
        : "r"(a0), "r"(a1), "r"(a2), "r"(a3), "r"(b0), "r"(b1));
}

// one B tile pass: NT n-tiles, 8 k-steps. DUAL: also multiply A-lo into same acc.
template<int NT, bool DUAL>
__device__ __forceinline__ void gemm_tile(u32 aH, u32 aL, u32 bBase, u32 bsB, float* acc) {
    #pragma unroll
    for (int k = 0; k < 8; k++) {
        u32 a0, a1, a2, a3, l0, l1, l2, l3;
        ldsm_x4(a0, a1, a2, a3, aH + k * 32);
        if (DUAL) ldsm_x4(l0, l1, l2, l3, aL + k * 32);
        #pragma unroll
        for (int n = 0; n < NT; n++) {
            u32 b0, b1;
            ldsm_x2t(b0, b1, bBase + (u32)(k * 16) * bsB + n * 16);
            mma_bf16(acc + n * 4, a0, a1, a2, a3, b0, b1);
            if (DUAL) mma_bf16(acc + n * 4, l0, l1, l2, l3, b0, b1);
        }
    }
}

// ---------------- device scratch ----------------
__device__ float g_z[BT * DD];
__device__ float g_wqk[BT * DD];
__device__ float g_vwih[BT * 384];

__device__ ulonglong2 pW1[128 * 256];
__device__ ulonglong2 pW2[64 * 128];
__device__ ulonglong2 pSkip[128 * 128];
__device__ ulonglong2 pWk[32 * 128];
__device__ ulonglong2 pWv[32 * 128];
__device__ ulonglong2 pWqT[32 * 128];
__device__ ulonglong2 pWih[32 * 384];
__device__ ulonglong2 pWt[32 * 128];

// bf16 B tiles for mma: gBg[gate][half][hi/lo][k=128][n=72 padded]
__device__ u16 gBg[3 * 2 * 2 * 128 * 72];
// gBm[w1/w2][hi/lo][k=128][n=136 padded]
__device__ u16 gBm[2 * 2 * 128 * 136];

// ---------------- pack ----------------
__device__ __forceinline__ void pack_elem(const float* __restrict__ s0, ulonglong2* __restrict__ dst, int C, int idx) {
    int c = idx % C, k4 = idx / C;
    const float* s = s0 + (4 * k4) * C + c;
    ulonglong2 v;
    v.x = pack2(s[0], s[C]);
    v.y = pack2(s[2 * C], s[3 * C]);
    dst[idx] = v;
}
__device__ __forceinline__ void packT_elem(const float* __restrict__ s0, ulonglong2* __restrict__ dst, int K, int C4, int idx) {
    int i = idx % K, j4 = idx / K;
    const float* s = s0 + i * (C4 * 4) + 4 * j4;
    ulonglong2 v;
    v.x = pack2(s[0], s[1]);
    v.y = pack2(s[2], s[3]);
    dst[idx] = v;
}
__device__ __forceinline__ u16 bf_hi(float w) {
    return __bfloat16_as_ushort(__float2bfloat16(w));
}
__device__ __forceinline__ u16 bf_lo(float w) {
    float hf = __bfloat162float(__float2bfloat16(w));
    return __bfloat16_as_ushort(__float2bfloat16(w - hf));
}

__global__ __launch_bounds__(256) void pack_all(
    const float* __restrict__ eW1, const float* __restrict__ eW2, const float* __restrict__ skipW,
    const float* __restrict__ Wk, const float* __restrict__ Wv, const float* __restrict__ Wq,
    const float* __restrict__ gWih, const float* __restrict__ gWhh,
    const float* __restrict__ mW1, const float* __restrict__ mW2, const float* __restrict__ Wt)
{
    int idx = blockIdx.x * 256 + threadIdx.x;
    if (idx < 32768) { pack_elem(eW1, pW1, 256, idx); return; }   idx -= 32768;
    if (idx < 8192)  { pack_elem(eW2, pW2, 128, idx); return; }   idx -= 8192;
    if (idx < 16384) { pack_elem(skipW, pSkip, 128, idx); return; } idx -= 16384;
    if (idx < 4096)  { pack_elem(Wk, pWk, 128, idx); return; }    idx -= 4096;
    if (idx < 4096)  { pack_elem(Wv, pWv, 128, idx); return; }    idx -= 4096;
    if (idx < 4096)  { packT_elem(Wq, pWqT, 128, 32, idx); return; } idx -= 4096;
    if (idx < 12288) { pack_elem(gWih, pWih, 384, idx); return; } idx -= 12288;
    if (idx < 4096)  { pack_elem(Wt, pWt, 128, idx); return; }    idx -= 4096;
    // gBg: [g][h][s][k][72]
    if (idx < 110592) {
        const int g = idx / 36864, r = idx % 36864;
        const int h = r / 18432, r2 = r % 18432;
        const int s = r2 / 9216, r3 = r2 % 9216;
        const int k = r3 / 72, n = r3 % 72;
        float w = (n < 64) ? gWhh[k * 384 + g * 128 + h * 64 + n] : 0.f;
        gBg[idx] = s ? bf_lo(w) : bf_hi(w);
        return;
    }
    idx -= 110592;
    // gBm: [m][s][k][136]
    if (idx < 69632) {
        const int m = idx / 34816, r = idx % 34816;
        const int s = r / 17408, r2 = r % 17408;
        const int k = r2 / 136, n = r2 % 136;
        float w = (n < 128) ? (m ? mW2[k * 128 + n] : mW1[k * 128 + n]) : 0.f;
        gBm[110592 * 0 + idx] = s ? bf_lo(w) : bf_hi(w);   // flat into gBm
        return;
    }
}

// ---------------------------------------------------------------------------
// Kernel 1: encoder (proven)
// ---------------------------------------------------------------------------
__global__ __launch_bounds__(256) void enc_kernel(
    const float* __restrict__ obs, const float* __restrict__ b1, const float* __restrict__ b2)
{
    __shared__ __align__(16) float s_obs[8 * DOBS];
    __shared__ __align__(16) float s_h[8 * HH];
    __shared__ __align__(16) float s_p1[8 * DD];
    const int tid = threadIdx.x;
    const long e0 = (long)blockIdx.x * 8;
    const float* op = obs + e0 * DOBS;
    for (int i = tid; i < 8 * DOBS / 4; i += 256)
        ((float4*)s_obs)[i] = ((const float4*)op)[i];
    __syncthreads();
    {
        const int j = tid;
        u64 acc[8] = {0, 0, 0, 0, 0, 0, 0, 0};
        for (int d4 = 0; d4 < 128; d4++) {
            const ulonglong2 w = pW1[d4 * HH + j];
            #pragma unroll
            for (int r = 0; r < 8; r++) {
                const ulonglong2 s = *(const ulonglong2*)&s_obs[r * DOBS + 4 * d4];
                acc[r] = fma2(s.x, w.x, acc[r]);
                acc[r] = fma2(s.y, w.y, acc[r]);
            }
        }
        const float bj = b1[j];
        #pragma unroll
        for (int r = 0; r < 8; r++) {
            const float a = sum2(acc[r]) + bj;
            s_h[r * HH + j] = 0.5f * a * (1.f + erff(a * 0.70710678118654752f));
        }
    }
    __syncthreads();
    const int j = tid & 127;
    const int half = tid >> 7;
    u64 acc[8] = {0, 0, 0, 0, 0, 0, 0, 0};
    if (half == 0) {
        for (int d4 = 0; d4 < 64; d4++) {
            const ulonglong2 w = pW2[d4 * DD + j];
            #pragma unroll
            for (int r = 0; r < 8; r++) {
                const ulonglong2 s = *(const ulonglong2*)&s_h[r * HH + 4 * d4];
                acc[r] = fma2(s.x, w.x, acc[r]);
                acc[r] = fma2(s.y, w.y, acc[r]);
            }
        }
        for (int d4 = 0; d4 < 32; d4++) {
            const ulonglong2 w = pSkip[d4 * DD + j];
            #pragma unroll
            for (int r = 0; r < 8; r++) {
                const ulonglong2 s = *(const ulonglong2*)&s_obs[r * DOBS + 4 * d4];
                acc[r] = fma2(s.x, w.x, acc[r]);
                acc[r] = fma2(s.y, w.y, acc[r]);
            }
        }
    } else {
        for (int d4 = 32; d4 < 128; d4++) {
            const ulonglong2 w = pSkip[d4 * DD + j];
            #pragma unroll
            for (int r = 0; r < 8; r++) {
                const ulonglong2 s = *(const ulonglong2*)&s_obs[r * DOBS + 4 * d4];
                acc[r] = fma2(s.x, w.x, acc[r]);
                acc[r] = fma2(s.y, w.y, acc[r]);
            }
        }
        #pragma unroll
        for (int r = 0; r < 8; r++) s_p1[r * DD + j] = sum2(acc[r]);
    }
    __syncthreads();
    if (half == 0) {
        const float bj = b2[j];
        #pragma unroll
        for (int r = 0; r < 8; r++)
            g_z[(e0 + r) * DD + j] = tanha(sum2(acc[r]) + s_p1[r * DD + j] + bj);
    }
}

// ---------------------------------------------------------------------------
// Kernel 2: prologue — LN(z), k, v, wqk, vwih -> global. (proven)
// ---------------------------------------------------------------------------
__global__ __launch_bounds__(256) void prolog_kernel(
    const float* __restrict__ lin_g, const float* __restrict__ lin_b)
{
    __shared__ __align__(16) float inp[2][DD], kk[2][DD], vv[2][DD];
    __shared__ float red[2][12];
    const int tid = threadIdx.x, lane = tid & 31, warp = tid >> 5;
    const int el = tid >> 7, j = tid & 127;
    const long ent = (long)blockIdx.x * 2 + el;
    const float zv = g_z[ent * DD + j];
    {
        float s1 = zv, s2 = zv * zv;
        #pragma unroll
        for (int off = 16; off > 0; off >>= 1) {
            s1 += __shfl_down_sync(0xffffffffu, s1, off);
            s2 += __shfl_down_sync(0xffffffffu, s2, off);
        }
        if (lane == 0) { red[el][warp & 3] = s1; red[el][4 + (warp & 3)] = s2; }
    }
    __syncthreads();
    if (j == 0) {
        float s = red[el][0] + red[el][1] + red[el][2] + red[el][3];
        float q = red[el][4] + red[el][5] + red[el][6] + red[el][7];
        const float mu = s * (1.f / 128.f);
        red[el][8] = mu;
        red[el][9] = rsqrtf(q * (1.f / 128.f) - mu * mu + 1e-5f);
    }
    __syncthreads();
    inp[el][j] = (zv - red[el][8]) * red[el][9] * lin_g[j] + lin_b[j];
    __syncthreads();
    u64 acc = 0;
    for (int d4 = 0; d4 < 32; d4++) {
        const ulonglong2 s = *(const ulonglong2*)&inp[el][4 * d4];
        const ulonglong2 w = pWk[d4 * DD + j];
        acc = fma2(s.x, w.x, acc);
        acc = fma2(s.y, w.y, acc);
    }
    kk[el][j] = sum2(acc);
    acc = 0;
    for (int d4 = 0; d4 < 32; d4++) {
        const ulonglong2 s = *(const ulonglong2*)&inp[el][4 * d4];
        const ulonglong2 w = pWv[d4 * DD + j];
        acc = fma2(s.x, w.x, acc);
        acc = fma2(s.y, w.y, acc);
    }
    vv[el][j] = sum2(acc);
    __syncthreads();
    acc = 0;
    for (int j4 = 0; j4 < 32; j4++) {
        const ulonglong2 s = *(const ulonglong2*)&kk[el][4 * j4];
        const ulonglong2 w = pWqT[j4 * DD + j];
        acc = fma2(s.x, w.x, acc);
        acc = fma2(s.y, w.y, acc);
    }
    g_wqk[ent * DD + j] = sum2(acc);
    #pragma unroll
    for (int pp = 0; pp < 3; pp++) {
        const int c = j + 128 * pp;
        u64 a2 = 0;
        for (int d4 = 0; d4 < 32; d4++) {
            const ulonglong2 s = *(const ulonglong2*)&vv[el][4 * d4];
            const ulonglong2 w = pWih[d4 * 384 + c];
            a2 = fma2(s.x, w.x, a2);
            a2 = fma2(s.y, w.y, a2);
        }
        g_vwih[ent * 384 + c] = sum2(a2);
    }
}

// ---------------------------------------------------------------------------
// Kernel 3: mma.sync slot attention. 8 entries/CTA (M=128), 256 thr = 8 warps.
// warp e owns entry e (rows 16e..16e+15). A always in SLOT smem (bf16 hi/lo).
// ---------------------------------------------------------------------------
#define AST 136        // A row stride (bf16 elems)
#define SMEM_DYN 202240

__global__ __launch_bounds__(256) void slot_mma(
    const float* __restrict__ slot_mu,
    const float* __restrict__ bih, const float* __restrict__ bhh,
    const float* __restrict__ mb1, const float* __restrict__ mb2,
    const float* __restrict__ lsl_g, const float* __restrict__ lsl_b,
    const float* __restrict__ lml_g, const float* __restrict__ lml_b,
    float* __restrict__ out)
{
    extern __shared__ __align__(16) char dyn[];
    u16* SLH = (u16*)(dyn + 36864);
    u16* SLL = (u16*)(dyn + 71680);
    u16* WKH = (u16*)(dyn + 106496);
    u16* WKL = (u16*)(dyn + 141312);
    float* sVwih = (float*)(dyn + 176128);   // 8x384
    float* sWqk  = (float*)(dyn + 188416);   // 8x128
    float* sStat = (float*)(dyn + 192512);   // 128x4
    float* sLog  = (float*)(dyn + 194560);   // 128x2
    float* sAttn = (float*)(dyn + 195584);   // 128
    float* sPar  = (float*)(dyn + 196096);   // 1536 floats

    const int tid = threadIdx.x, lane = tid & 31, warp = tid >> 5;
    const int e = warp;
    const int rowT = tid & 127, h2 = tid >> 7;
    const long blk = blockIdx.x;
    const float invscale = 0.088388347648318447f;

    // params + per-entry vectors
    for (int i = tid; i < 384; i += 256) { sPar[i] = bih[i]; sPar[384 + i] = bhh[i]; }
    if (tid < 128) {
        sPar[768 + tid] = mb1[tid];  sPar[896 + tid] = mb2[tid];
        sPar[1024 + tid] = lsl_g[tid]; sPar[1152 + tid] = lsl_b[tid];
        sPar[1280 + tid] = lml_g[tid]; sPar[1408 + tid] = lml_b[tid];
    }
    for (int i = tid; i < 8 * 384; i += 256) sVwih[i] = g_vwih[blk * (8 * 384) + i];
    for (int i = tid; i < 8 * 128; i += 256) sWqk[i] = g_wqk[blk * (8 * 128) + i];

    // init SLOT from slot_mu (+stats)
    {
        float s1 = 0.f, s2 = 0.f;
        const float* mu = slot_mu + (rowT & 15) * DD + h2 * 64;
        for (int q = 0; q < 32; q++) {
            const float v0 = mu[2 * q], v1 = mu[2 * q + 1];
            u32 lo; u32 hi = split_pair(v0, v1, lo);
            *(u32*)&SLH[rowT * AST + h2 * 64 + 2 * q] = hi;
            *(u32*)&SLL[rowT * AST + h2 * 64 + 2 * q] = lo;
            s1 += v0 + v1;  s2 += v0 * v0 + v1 * v1;
        }
        sStat[rowT * 4 + 2 * h2] = s1;  sStat[rowT * 4 + 2 * h2 + 1] = s2;
    }
    __syncthreads();

    // ldmatrix lane addresses
    const u32 aRow = (u32)(e * 16 + (lane & 7) + ((lane >> 3) & 1) * 8);
    const u32 aOffB = aRow * (AST * 2) + (u32)(((lane >> 4) & 1) * 16);
    const u32 adSLH = smem_u32(SLH) + aOffB;
    const u32 adSLL = smem_u32(SLL) + aOffB;
    const u32 bRow = (u32)((lane & 7) + ((lane >> 3) & 1) * 8);
    const u32 adBg_h = smem_u32(dyn) + bRow * 144;
    const u32 adBg_l = adBg_h + 18432;
    const u32 adBm = smem_u32(dyn) + bRow * 272;

    const int lq = lane >> 2, lc = (lane & 3) * 2;
    const int r0 = e * 16 + lq, r1 = r0 + 8;

    for (int it = 0; it < 3; it++) {
        // ---- logits (fold LN_sl) ----
        {
            const float mu = (sStat[rowT * 4] + sStat[rowT * 4 + 2]) * (1.f / 128.f);
            const float rs = rsqrtf((sStat[rowT * 4 + 1] + sStat[rowT * 4 + 3]) * (1.f / 128.f) - mu * mu + 1e-5f);
            float pd = 0.f;
            for (int q = 0; q < 32; q++) {
                const int j = h2 * 64 + 2 * q;
                float2 v = unsplit(*(u32*)&SLH[rowT * AST + j], *(u32*)&SLL[rowT * AST + j]);
                pd += ((v.x - mu) * rs * sPar[1024 + j] + sPar[1152 + j]) * sWqk[(rowT >> 4) * 128 + j];
                pd += ((v.y - mu) * rs * sPar[1024 + j + 1] + sPar[1152 + j + 1]) * sWqk[(rowT >> 4) * 128 + j + 1];
            }
            sLog[rowT * 2 + h2] = pd;
        }
        __syncthreads();
        if (lane < 16) {
            const int r2 = warp * 16 + lane;
            const float l = (sLog[r2 * 2] + sLog[r2 * 2 + 1]) * invscale;
            float m = l;
            #pragma unroll
            for (int off = 8; off > 0; off >>= 1) m = fmaxf(m, __shfl_xor_sync(0xffffu, m, off));
            const float ex = __expf(l - m);
            float ss = ex;
            #pragma unroll
            for (int off = 8; off > 0; off >>= 1) ss += __shfl_xor_sync(0xffffu, ss, off);
            sAttn[r2] = ex / ss;
        }
        __syncthreads();

        // ---- gates + GRU, per 64-col half ----
        for (int half = 0; half < 2; half++) {
            float accR[32], accZ[32], accN[32];
            #pragma unroll
            for (int g3 = 0; g3 < 3; g3++) {
                {   // copy B half-tile (hi+lo = 36864B)
                    const uint4* src = (const uint4*)(gBg + (g3 * 2 + half) * 18432);
                    uint4* dst = (uint4*)dyn;
                    for (int i = tid; i < 2304; i += 256) dst[i] = src[i];
                }
                __syncthreads();
                float* acc = (g3 == 0) ? accR : (g3 == 1) ? accZ : accN;
                #pragma unroll
                for (int i = 0; i < 32; i++) acc[i] = 0.f;
                gemm_tile<8, true>(adSLH, adSLL, adBg_h, 144, acc);
                gemm_tile<8, false>(adSLH, 0, adBg_l, 144, acc);
                __syncthreads();
            }
            // GRU epilogue on fragments
            const int cb = half * 64;
            const float a0f = sAttn[r0], a1f = sAttn[r1];
            float s1[2] = {0.f, 0.f}, s2[2] = {0.f, 0.f};
            #pragma unroll
            for (int i = 0; i < 8; i++) {
                const int j0 = cb + 8 * i + lc;
                #pragma unroll
                for (int p2 = 0; p2 < 2; p2++) {
                    const int row = p2 ? r1 : r0;
                    const float af = p2 ? a1f : a0f;
                    float2 hv = unsplit(*(u32*)&SLH[row * AST + j0], *(u32*)&SLL[row * AST + j0]);
                    float nvv[2];
                    #pragma unroll
                    for (int c = 0; c < 2; c++) {
                        const int j = j0 + c;
                        const float gr = accR[i * 4 + p2 * 2 + c] + sPar[384 + j];
                        const float gz = accZ[i * 4 + p2 * 2 + c] + sPar[512 + j];
                        const float gn = accN[i * 4 + p2 * 2 + c] + sPar[640 + j];
                        const float rr = sigm(af * sVwih[e * 384 + j] + sPar[j] + gr);
                        const float zz = sigm(af * sVwih[e * 384 + 128 + j] + sPar[128 + j] + gz);
                        const float nn = tanha(af * sVwih[e * 384 + 256 + j] + sPar[256 + j] + rr * gn);
                        const float h = c ? hv.y : hv.x;
                        nvv[c] = (1.f - zz) * nn + zz * h;
                    }
                    u32 lo; u32 hi = split_pair(nvv[0], nvv[1], lo);
                    *(u32*)&WKH[row * AST + j0] = hi;
                    *(u32*)&WKL[row * AST + j0] = lo;
                    s1[p2] += nvv[0] + nvv[1];
                    s2[p2] += nvv[0] * nvv[0] + nvv[1] * nvv[1];
                }
            }
            #pragma unroll
            for (int p2 = 0; p2 < 2; p2++) {
                s1[p2] += __shfl_xor_sync(0xffffffffu, s1[p2], 1);
                s1[p2] += __shfl_xor_sync(0xffffffffu, s1[p2], 2);
                s2[p2] += __shfl_xor_sync(0xffffffffu, s2[p2], 1);
                s2[p2] += __shfl_xor_sync(0xffffffffu, s2[p2], 2);
            }
            if ((lane & 3) == 0) {
                sStat[r0 * 4 + 2 * half] = s1[0];  sStat[r0 * 4 + 2 * half + 1] = s2[0];
                sStat[r1 * 4 + 2 * half] = s1[1];  sStat[r1 * 4 + 2 * half + 1] = s2[1];
            }
        }
        __syncthreads();

        // ---- ln_mlp: WORK -> SLOT (split bf16) ----
        {
            const float mu = (sStat[rowT * 4] + sStat[rowT * 4 + 2]) * (1.f / 128.f);
            const float rs = rsqrtf((sStat[rowT * 4 + 1] + sStat[rowT * 4 + 3]) * (1.f / 128.f) - mu * mu + 1e-5f);
            for (int q = 0; q < 32; q++) {
                const int j = h2 * 64 + 2 * q;
                float2 v = unsplit(*(u32*)&WKH[rowT * AST + j], *(u32*)&WKL[rowT * AST + j]);
                const float l0 = (v.x - mu) * rs * sPar[1280 + j] + sPar[1408 + j];
                const float l1 = (v.y - mu) * rs * sPar[1280 + j + 1] + sPar[1408 + j + 1];
                u32 lo; u32 hi = split_pair(l0, l1, lo);
                *(u32*)&SLH[rowT * AST + j] = hi;
                *(u32*)&SLL[rowT * AST + j] = lo;
            }
        }
        __syncthreads();

        // ---- W1 ----
        float acc[64];
        {
            const uint4* src = (const uint4*)(gBm + 0 * 17408);
            uint4* dst = (uint4*)dyn;
            for (int i = tid; i < 2176; i += 256) dst[i] = src[i];
        }
        __syncthreads();
        #pragma unroll
        for (int i = 0; i < 64; i++) acc[i] = 0.f;
        gemm_tile<16, true>(adSLH, adSLL, adBm, 272, acc);
        __syncthreads();
        {
            const uint4* src = (const uint4*)(gBm + 1 * 17408);
            uint4* dst = (uint4*)dyn;
            for (int i = tid; i < 2176; i += 256) dst[i] = src[i];
        }
        __syncthreads();
        gemm_tile<16, false>(adSLH, 0, adBm, 272, acc);
        __syncthreads();
        // h1 = relu(acc + b1) -> SLOT
        #pragma unroll
        for (int i = 0; i < 16; i++) {
            const int j0 = 8 * i + lc;
            #pragma unroll
            for (int p2 = 0; p2 < 2; p2++) {
                const int row = p2 ? r1 : r0;
                const float v0 = fmaxf(acc[i * 4 + p2 * 2] + sPar[768 + j0], 0.f);
                const float v1 = fmaxf(acc[i * 4 + p2 * 2 + 1] + sPar[768 + j0 + 1], 0.f);
                u32 lo; u32 hi = split_pair(v0, v1, lo);
                *(u32*)&SLH[row * AST + j0] = hi;
                *(u32*)&SLL[row * AST + j0] = lo;
            }
        }
        __syncthreads();

        // ---- W2 ----
        {
            const uint4* src = (const uint4*)(gBm + 2 * 17408);
            uint4* dst = (uint4*)dyn;
            for (int i = tid; i < 2176; i += 256) dst[i] = src[i];
        }
        __syncthreads();
        #pragma unroll
        for (int i = 0; i < 64; i++) acc[i] = 0.f;
        gemm_tile<16, true>(adSLH, adSLL, adBm, 272, acc);
        __syncthreads();
        {
            const uint4* src = (const uint4*)(gBm + 3 * 17408);
            uint4* dst = (uint4*)dyn;
            for (int i = tid; i < 2176; i += 256) dst[i] = src[i];
        }
        __syncthreads();
        gemm_tile<16, false>(adSLH, 0, adBm, 272, acc);
        __syncthreads();
        // slots'' = WORK + acc + b2 -> SLOT, stats
        {
            float s1[2] = {0.f, 0.f}, s2[2] = {0.f, 0.f};
            #pragma unroll
            for (int i = 0; i < 16; i++) {
                const int j0 = 8 * i + lc;
                #pragma unroll
                for (int p2 = 0; p2 < 2; p2++) {
                    const int row = p2 ? r1 : r0;
                    float2 w = unsplit(*(u32*)&WKH[row * AST + j0], *(u32*)&WKL[row * AST + j0]);
                    const float v0 = w.x + acc[i * 4 + p2 * 2] + sPar[896 + j0];
                    const float v1 = w.y + acc[i * 4 + p2 * 2 + 1] + sPar[896 + j0 + 1];
                    u32 lo; u32 hi = split_pair(v0, v1, lo);
                    *(u32*)&SLH[row * AST + j0] = hi;
                    *(u32*)&SLL[row * AST + j0] = lo;
                    s1[p2] += v0 + v1;
                    s2[p2] += v0 * v0 + v1 * v1;
                }
            }
            #pragma unroll
            for (int p2 = 0; p2 < 2; p2++) {
                s1[p2] += __shfl_xor_sync(0xffffffffu, s1[p2], 1);
                s1[p2] += __shfl_xor_sync(0xffffffffu, s1[p2], 2);
                s2[p2] += __shfl_xor_sync(0xffffffffu, s2[p2], 1);
                s2[p2] += __shfl_xor_sync(0xffffffffu, s2[p2], 2);
            }
            if ((lane & 3) == 0) {
                sStat[r0 * 4 + 0] = s1[0];  sStat[r0 * 4 + 1] = s2[0];
                sStat[r0 * 4 + 2] = 0.f;    sStat[r0 * 4 + 3] = 0.f;
                sStat[r1 * 4 + 0] = s1[1];  sStat[r1 * 4 + 1] = s2[1];
                sStat[r1 * 4 + 2] = 0.f;    sStat[r1 * 4 + 3] = 0.f;
            }
        }
        __syncthreads();
    }

    // ---- final F.normalize + store ----
    {
        const float qq = sStat[rowT * 4 + 1] + sStat[rowT * 4 + 3];
        const float inv = 1.f / fmaxf(sqrtf(qq), 1e-8f);
        float* dst = out + (blk * 8 + (rowT >> 4)) * (NS * DD) + (rowT & 15) * DD + h2 * 64;
        for (int q = 0; q < 32; q++) {
            const int j = h2 * 64 + 2 * q;
            float2 v = unsplit(*(u32*)&SLH[rowT * AST + j], *(u32*)&SLL[rowT * AST + j]);
            dst[2 * q] = v.x * inv;
            dst[2 * q + 1] = v.y * inv;
        }
    }
}

// ---------------------------------------------------------------------------
// Kernel 4: temporal blend (proven R6)
// ---------------------------------------------------------------------------
__global__ __launch_bounds__(256) void temporal_kernel(float* __restrict__ out)
{
    __shared__ __align__(16) float s_prev[8 * DD];
    const int tid = threadIdx.x;
    const int j = tid & 127;
    const int gg = tid >> 7;
    const int b = blockIdx.x >> 1;
    const int half = blockIdx.x & 1;
    float* base = out + ((long)b * 64) * (NS * DD) + half * 8 * DD;
    for (int i = tid; i < 8 * DD; i += 256) s_prev[i] = base[i];
    __syncthreads();
    for (int t = 1; t < 64; t++) {
        float* cur = base + t * (NS * DD);
        float c[4];
        #pragma unroll
        for (int r = 0; r < 4; r++) c[r] = cur[(gg * 4 + r) * DD + j];
        u64 acc[4] = {0, 0, 0, 0};
        for (int d4 = 0; d4 < 32; d4++) {
            const ulonglong2 w = pWt[d4 * DD + j];
            #pragma unroll
            for (int r = 0; r < 4; r++) {
                const ulonglong2 s = *(const ulonglong2*)&s_prev[(gg * 4 + r) * DD + 4 * d4];
                acc[r] = fma2(s.x, w.x, acc[r]);
                acc[r] = fma2(s.y, w.y, acc[r]);
            }
        }
        __syncthreads();
        #pragma unroll
        for (int r = 0; r < 4; r++) {
            const float v = 0.7f * c[r] + 0.3f * tanha(sum2(acc[r]));
            cur[(gg * 4 + r) * DD + j] = v;
            s_prev[(gg * 4 + r) * DD + j] = v;
        }
        __syncthreads();
    }
}

// ---------------------------------------------------------------------------
extern "C" void kernel_launch(void* const* d_in, const int* in_sizes, int n_in,
                              void* d_out, int out_size)
{
    const float* obs   = (const float*)d_in[0];
    const float* eW1   = (const float*)d_in[1];
    const float* eb1   = (const float*)d_in[2];
    const float* eW2   = (const float*)d_in[3];
    const float* eb2   = (const float*)d_in[4];
    const float* skipW = (const float*)d_in[5];
    const float* smu   = (const float*)d_in[6];
    const float* Wk    = (const float*)d_in[7];
    const float* Wv    = (const float*)d_in[8];
    const float* Wq    = (const float*)d_in[9];
    const float* gWih  = (const float*)d_in[10];
    const float* gWhh  = (const float*)d_in[11];
    const float* gbih  = (const float*)d_in[12];
    const float* gbhh  = (const float*)d_in[13];
    const float* mW1   = (const float*)d_in[14];
    const float* mb1   = (const float*)d_in[15];
    const float* mW2   = (const float*)d_in[16];
    const float* mb2   = (const float*)d_in[17];
    const float* lin_g = (const float*)d_in[18];
    const float* lin_b = (const float*)d_in[19];
    const float* lsl_g = (const float*)d_in[20];
    const float* lsl_b = (const float*)d_in[21];
    const float* lml_g = (const float*)d_in[22];
    const float* lml_b = (const float*)d_in[23];
    const float* Wt    = (const float*)d_in[24];
    float* out = (float*)d_out;

    static int init_done = 0;
    if (!init_done) {
        cudaFuncSetAttribute(slot_mma, cudaFuncAttributeMaxDynamicSharedMemorySize, SMEM_DYN);
        init_done = 1;
    }

    pack_all<<<(266240 + 255) / 256, 256>>>(eW1, eW2, skipW, Wk, Wv, Wq,
                                            gWih, gWhh, mW1, mW2, Wt);
    enc_kernel<<<BT / 8, 256>>>(obs, eb1, eb2);
    prolog_kernel<<<BT / 2, 256>>>(lin_g, lin_b);
    slot_mma<<<BT / 8, 256, SMEM_DYN>>>(smu, gbih, gbhh, mb1, mb2,
                                        lsl_g, lsl_b, lml_g, lml_b, out);
    temporal_kernel<<<512, 256>>>(out);
}

// round 11
// speedup vs baseline: 3.4647x; 1.0606x over previous
#include <cuda_runtime.h>
#include <cuda_bf16.h>
#include <stdint.h>
#include <math.h>

#define BT 16384
#define DOBS 512
#define DD 128
#define NS 16
#define HH 256

typedef unsigned long long u64;
typedef unsigned int u32;
typedef unsigned short u16;

__device__ __forceinline__ u64 fma2(u64 a, u64 b, u64 c) {
    u64 d;
    asm("fma.rn.f32x2 %0, %1, %2, %3;" : "=l"(d) : "l"(a), "l"(b), "l"(c));
    return d;
}
__device__ __forceinline__ float sum2(u64 a) {
    float2 f = *(float2*)&a;
    return f.x + f.y;
}
__device__ __forceinline__ u64 pack2(float lo, float hi) {
    u64 r;
    asm("mov.b64 %0, {%1, %2};" : "=l"(r) : "f"(lo), "f"(hi));
    return r;
}
__device__ __forceinline__ float tanha(float x) {
    float y;
    asm("tanh.approx.f32 %0, %1;" : "=f"(y) : "f"(x));
    return y;
}
__device__ __forceinline__ float sigm(float x) { return 0.5f * tanha(0.5f * x) + 0.5f; }

__device__ __forceinline__ u32 split_pair(float v0, float v1, u32& lo_out) {
    __nv_bfloat16 h0 = __float2bfloat16(v0), h1 = __float2bfloat16(v1);
    __nv_bfloat16 l0 = __float2bfloat16(v0 - __bfloat162float(h0));
    __nv_bfloat16 l1 = __float2bfloat16(v1 - __bfloat162float(h1));
    lo_out = (u32)__bfloat16_as_ushort(l0) | ((u32)__bfloat16_as_ushort(l1) << 16);
    return (u32)__bfloat16_as_ushort(h0) | ((u32)__bfloat16_as_ushort(h1) << 16);
}
__device__ __forceinline__ float2 unsplit(u32 hi, u32 lo) {
    float2 r;
    r.x = __bfloat162float(__ushort_as_bfloat16((u16)(hi & 0xffff)))
        + __bfloat162float(__ushort_as_bfloat16((u16)(lo & 0xffff)));
    r.y = __bfloat162float(__ushort_as_bfloat16((u16)(hi >> 16)))
        + __bfloat162float(__ushort_as_bfloat16((u16)(lo >> 16)));
    return r;
}

// ---------------- mma / ldmatrix / cp.async helpers ----------------
__device__ __forceinline__ u32 smem_u32(const void* p) {
    u32 a;
    asm("{ .reg .u64 t; cvta.to.shared.u64 t, %1; cvt.u32.u64 %0, t; }" : "=r"(a) : "l"(p));
    return a;
}
__device__ __forceinline__ void ldsm_x4(u32& a0, u32& a1, u32& a2, u32& a3, u32 ad) {
    asm volatile("ldmatrix.sync.aligned.m8n8.x4.shared.b16 {%0,%1,%2,%3}, [%4];"
                 : "=r"(a0), "=r"(a1), "=r"(a2), "=r"(a3) : "r"(ad));
}
__device__ __forceinline__ void ldsm_x2t(u32& b0, u32& b1, u32 ad) {
    asm volatile("ldmatrix.sync.aligned.m8n8.x2.trans.shared.b16 {%0,%1}, [%2];"
                 : "=r"(b0), "=r"(b1) : "r"(ad));
}
__device__ __forceinline__ void mma_bf16(float* d, u32 a0, u32 a1, u32 a2, u32 a3,
                                         u32 b0, u32 b1) {
    asm volatile(
        "mma.sync.aligned.m16n8k16.row.col.f32.bf16.bf16.f32 "
        "{%0,%1,%2,%3}, {%4,%5,%6,%7}, {%8,%9}, {%0,%1,%2,%3};"
        : "+f"(d[0]), "+f"(d[1]), "+f"(d[2]), "+f"(d[3])
        : "r"(a0), "r"(a1), "r"(a2), "r"(a3), "r"(b0), "r"(b1));
}
__device__ __forceinline__ void cp16(u32 saddr, const void* g) {
    asm volatile("cp.async.cg.shared.global [%0], [%1], 16;" :: "r"(saddr), "l"(g));
}
#define CP_COMMIT() asm volatile("cp.async.commit_group;" ::: "memory")
#define CP_WAIT0()  asm volatile("cp.async.wait_group 0;" ::: "memory")

// one B block pass: 8 n-tiles, 8 k-steps. DUAL: also multiply A-lo into same acc.
template<bool DUAL>
__device__ __forceinline__ void gemm_blk(u32 aH, u32 aL, u32 bBase, float* acc) {
    #pragma unroll
    for (int k = 0; k < 8; k++) {
        u32 a0, a1, a2, a3, l0, l1, l2, l3;
        ldsm_x4(a0, a1, a2, a3, aH + k * 32);
        if (DUAL) ldsm_x4(l0, l1, l2, l3, aL + k * 32);
        #pragma unroll
        for (int n = 0; n < 8; n++) {
            u32 b0, b1;
            ldsm_x2t(b0, b1, bBase + (u32)(k * 16) * 144 + n * 16);
            mma_bf16(acc + n * 4, a0, a1, a2, a3, b0, b1);
            if (DUAL) mma_bf16(acc + n * 4, l0, l1, l2, l3, b0, b1);
        }
    }
}

// ---------------- device scratch ----------------
__device__ float g_z[BT * DD];
__device__ float g_wqk[BT * DD];
__device__ float g_vwih[BT * 384];

__device__ ulonglong2 pW1[128 * 256];
__device__ ulonglong2 pW2[64 * 128];
__device__ ulonglong2 pSkip[128 * 128];
__device__ ulonglong2 pWk[32 * 128];
__device__ ulonglong2 pWv[32 * 128];
__device__ ulonglong2 pWqT[32 * 128];
__device__ ulonglong2 pWih[32 * 384];
__device__ ulonglong2 pWt[32 * 128];

// 20 uniform B blocks, each [k=128][n=72] bf16 = 18432 B.
// blocks 0-11: gates  b = half*6 + g*2 + s   (s: 0=hi,1=lo), col = half*64+n
// blocks 12-19: mlp   b = 12 + m*4 + half*2 + s
__device__ u16 gBall[20 * 9216];

// ---------------- pack ----------------
__device__ __forceinline__ void pack_elem(const float* __restrict__ s0, ulonglong2* __restrict__ dst, int C, int idx) {
    int c = idx % C, k4 = idx / C;
    const float* s = s0 + (4 * k4) * C + c;
    ulonglong2 v;
    v.x = pack2(s[0], s[C]);
    v.y = pack2(s[2 * C], s[3 * C]);
    dst[idx] = v;
}
__device__ __forceinline__ void packT_elem(const float* __restrict__ s0, ulonglong2* __restrict__ dst, int K, int C4, int idx) {
    int i = idx % K, j4 = idx / K;
    const float* s = s0 + i * (C4 * 4) + 4 * j4;
    ulonglong2 v;
    v.x = pack2(s[0], s[1]);
    v.y = pack2(s[2], s[3]);
    dst[idx] = v;
}
__device__ __forceinline__ u16 bf_hi(float w) {
    return __bfloat16_as_ushort(__float2bfloat16(w));
}
__device__ __forceinline__ u16 bf_lo(float w) {
    float hf = __bfloat162float(__float2bfloat16(w));
    return __bfloat16_as_ushort(__float2bfloat16(w - hf));
}

__global__ __launch_bounds__(256) void pack_all(
    const float* __restrict__ eW1, const float* __restrict__ eW2, const float* __restrict__ skipW,
    const float* __restrict__ Wk, const float* __restrict__ Wv, const float* __restrict__ Wq,
    const float* __restrict__ gWih, const float* __restrict__ gWhh,
    const float* __restrict__ mW1, const float* __restrict__ mW2, const float* __restrict__ Wt)
{
    int idx = blockIdx.x * 256 + threadIdx.x;
    if (idx < 32768) { pack_elem(eW1, pW1, 256, idx); return; }   idx -= 32768;
    if (idx < 8192)  { pack_elem(eW2, pW2, 128, idx); return; }   idx -= 8192;
    if (idx < 16384) { pack_elem(skipW, pSkip, 128, idx); return; } idx -= 16384;
    if (idx < 4096)  { pack_elem(Wk, pWk, 128, idx); return; }    idx -= 4096;
    if (idx < 4096)  { pack_elem(Wv, pWv, 128, idx); return; }    idx -= 4096;
    if (idx < 4096)  { packT_elem(Wq, pWqT, 128, 32, idx); return; } idx -= 4096;
    if (idx < 12288) { pack_elem(gWih, pWih, 384, idx); return; } idx -= 12288;
    if (idx < 4096)  { pack_elem(Wt, pWt, 128, idx); return; }    idx -= 4096;
    if (idx >= 184320) return;
    const int b = idx / 9216, r = idx % 9216;
    const int k = r / 72, n = r % 72;
    float w = 0.f;
    int s;
    if (b < 12) {
        const int half = b / 6, rem = b % 6, g = rem >> 1;
        s = rem & 1;
        if (n < 64) w = gWhh[k * 384 + g * 128 + half * 64 + n];
    } else {
        const int bb = b - 12, m = bb >> 2, half = (bb >> 1) & 1;
        s = bb & 1;
        if (n < 64) w = (m ? mW2 : mW1)[k * 128 + half * 64 + n];
    }
    gBall[idx] = s ? bf_lo(w) : bf_hi(w);
}

// ---------------------------------------------------------------------------
// Kernel 1: encoder (proven)
// ---------------------------------------------------------------------------
__global__ __launch_bounds__(256) void enc_kernel(
    const float* __restrict__ obs, const float* __restrict__ b1, const float* __restrict__ b2)
{
    __shared__ __align__(16) float s_obs[8 * DOBS];
    __shared__ __align__(16) float s_h[8 * HH];
    __shared__ __align__(16) float s_p1[8 * DD];
    const int tid = threadIdx.x;
    const long e0 = (long)blockIdx.x * 8;
    const float* op = obs + e0 * DOBS;
    for (int i = tid; i < 8 * DOBS / 4; i += 256)
        ((float4*)s_obs)[i] = ((const float4*)op)[i];
    __syncthreads();
    {
        const int j = tid;
        u64 acc[8] = {0, 0, 0, 0, 0, 0, 0, 0};
        for (int d4 = 0; d4 < 128; d4++) {
            const ulonglong2 w = pW1[d4 * HH + j];
            #pragma unroll
            for (int r = 0; r < 8; r++) {
                const ulonglong2 s = *(const ulonglong2*)&s_obs[r * DOBS + 4 * d4];
                acc[r] = fma2(s.x, w.x, acc[r]);
                acc[r] = fma2(s.y, w.y, acc[r]);
            }
        }
        const float bj = b1[j];
        #pragma unroll
        for (int r = 0; r < 8; r++) {
            const float a = sum2(acc[r]) + bj;
            s_h[r * HH + j] = 0.5f * a * (1.f + erff(a * 0.70710678118654752f));
        }
    }
    __syncthreads();
    const int j = tid & 127;
    const int half = tid >> 7;
    u64 acc[8] = {0, 0, 0, 0, 0, 0, 0, 0};
    if (half == 0) {
        for (int d4 = 0; d4 < 64; d4++) {
            const ulonglong2 w = pW2[d4 * DD + j];
            #pragma unroll
            for (int r = 0; r < 8; r++) {
                const ulonglong2 s = *(const ulonglong2*)&s_h[r * HH + 4 * d4];
                acc[r] = fma2(s.x, w.x, acc[r]);
                acc[r] = fma2(s.y, w.y, acc[r]);
            }
        }
        for (int d4 = 0; d4 < 32; d4++) {
            const ulonglong2 w = pSkip[d4 * DD + j];
            #pragma unroll
            for (int r = 0; r < 8; r++) {
                const ulonglong2 s = *(const ulonglong2*)&s_obs[r * DOBS + 4 * d4];
                acc[r] = fma2(s.x, w.x, acc[r]);
                acc[r] = fma2(s.y, w.y, acc[r]);
            }
        }
    } else {
        for (int d4 = 32; d4 < 128; d4++) {
            const ulonglong2 w = pSkip[d4 * DD + j];
            #pragma unroll
            for (int r = 0; r < 8; r++) {
                const ulonglong2 s = *(const ulonglong2*)&s_obs[r * DOBS + 4 * d4];
                acc[r] = fma2(s.x, w.x, acc[r]);
                acc[r] = fma2(s.y, w.y, acc[r]);
            }
        }
        #pragma unroll
        for (int r = 0; r < 8; r++) s_p1[r * DD + j] = sum2(acc[r]);
    }
    __syncthreads();
    if (half == 0) {
        const float bj = b2[j];
        #pragma unroll
        for (int r = 0; r < 8; r++)
            g_z[(e0 + r) * DD + j] = tanha(sum2(acc[r]) + s_p1[r * DD + j] + bj);
    }
}

// ---------------------------------------------------------------------------
// Kernel 2: prologue — LN(z), k, v, wqk, vwih -> global. (proven)
// ---------------------------------------------------------------------------
__global__ __launch_bounds__(256) void prolog_kernel(
    const float* __restrict__ lin_g, const float* __restrict__ lin_b)
{
    __shared__ __align__(16) float inp[2][DD], kk[2][DD], vv[2][DD];
    __shared__ float red[2][12];
    const int tid = threadIdx.x, lane = tid & 31, warp = tid >> 5;
    const int el = tid >> 7, j = tid & 127;
    const long ent = (long)blockIdx.x * 2 + el;
    const float zv = g_z[ent * DD + j];
    {
        float s1 = zv, s2 = zv * zv;
        #pragma unroll
        for (int off = 16; off > 0; off >>= 1) {
            s1 += __shfl_down_sync(0xffffffffu, s1, off);
            s2 += __shfl_down_sync(0xffffffffu, s2, off);
        }
        if (lane == 0) { red[el][warp & 3] = s1; red[el][4 + (warp & 3)] = s2; }
    }
    __syncthreads();
    if (j == 0) {
        float s = red[el][0] + red[el][1] + red[el][2] + red[el][3];
        float q = red[el][4] + red[el][5] + red[el][6] + red[el][7];
        const float mu = s * (1.f / 128.f);
        red[el][8] = mu;
        red[el][9] = rsqrtf(q * (1.f / 128.f) - mu * mu + 1e-5f);
    }
    __syncthreads();
    inp[el][j] = (zv - red[el][8]) * red[el][9] * lin_g[j] + lin_b[j];
    __syncthreads();
    u64 acc = 0;
    for (int d4 = 0; d4 < 32; d4++) {
        const ulonglong2 s = *(const ulonglong2*)&inp[el][4 * d4];
        const ulonglong2 w = pWk[d4 * DD + j];
        acc = fma2(s.x, w.x, acc);
        acc = fma2(s.y, w.y, acc);
    }
    kk[el][j] = sum2(acc);
    acc = 0;
    for (int d4 = 0; d4 < 32; d4++) {
        const ulonglong2 s = *(const ulonglong2*)&inp[el][4 * d4];
        const ulonglong2 w = pWv[d4 * DD + j];
        acc = fma2(s.x, w.x, acc);
        acc = fma2(s.y, w.y, acc);
    }
    vv[el][j] = sum2(acc);
    __syncthreads();
    acc = 0;
    for (int j4 = 0; j4 < 32; j4++) {
        const ulonglong2 s = *(const ulonglong2*)&kk[el][4 * j4];
        const ulonglong2 w = pWqT[j4 * DD + j];
        acc = fma2(s.x, w.x, acc);
        acc = fma2(s.y, w.y, acc);
    }
    g_wqk[ent * DD + j] = sum2(acc);
    #pragma unroll
    for (int pp = 0; pp < 3; pp++) {
        const int c = j + 128 * pp;
        u64 a2 = 0;
        for (int d4 = 0; d4 < 32; d4++) {
            const ulonglong2 s = *(const ulonglong2*)&vv[el][4 * d4];
            const ulonglong2 w = pWih[d4 * 384 + c];
            a2 = fma2(s.x, w.x, a2);
            a2 = fma2(s.y, w.y, a2);
        }
        g_vwih[ent * 384 + c] = sum2(a2);
    }
}

// ---------------------------------------------------------------------------
// Kernel 3: mma.sync slot attention with cp.async double-buffered B streaming.
// 8 entries/CTA (M=128), 256 threads = 8 warps; warp e owns entry e.
// ---------------------------------------------------------------------------
#define AST 136
#define SMEM_DYN 202240

__global__ __launch_bounds__(256) void slot_mma(
    const float* __restrict__ slot_mu,
    const float* __restrict__ bih, const float* __restrict__ bhh,
    const float* __restrict__ mb1, const float* __restrict__ mb2,
    const float* __restrict__ lsl_g, const float* __restrict__ lsl_b,
    const float* __restrict__ lml_g, const float* __restrict__ lml_b,
    float* __restrict__ out)
{
    extern __shared__ __align__(16) char dyn[];
    u16* SLH = (u16*)(dyn + 36864);
    u16* SLL = (u16*)(dyn + 71680);
    u16* WKH = (u16*)(dyn + 106496);
    u16* WKL = (u16*)(dyn + 141312);
    float* sVwih = (float*)(dyn + 176128);
    float* sWqk  = (float*)(dyn + 188416);
    float* sStat = (float*)(dyn + 192512);
    float* sLog  = (float*)(dyn + 194560);
    float* sAttn = (float*)(dyn + 195584);
    float* sPar  = (float*)(dyn + 196096);

    const int tid = threadIdx.x, lane = tid & 31, warp = tid >> 5;
    const int e = warp;
    const int rowT = tid & 127, h2 = tid >> 7;
    const long blk = blockIdx.x;
    const float invscale = 0.088388347648318447f;
    const u32 bufBase = smem_u32(dyn);

    // prefetch first B block immediately
    {
        const char* src = (const char*)gBall;
        for (int i = tid; i < 1152; i += 256) cp16(bufBase + (u32)i * 16, src + i * 16);
        CP_COMMIT();
    }

    for (int i = tid; i < 384; i += 256) { sPar[i] = bih[i]; sPar[384 + i] = bhh[i]; }
    if (tid < 128) {
        sPar[768 + tid] = mb1[tid];  sPar[896 + tid] = mb2[tid];
        sPar[1024 + tid] = lsl_g[tid]; sPar[1152 + tid] = lsl_b[tid];
        sPar[1280 + tid] = lml_g[tid]; sPar[1408 + tid] = lml_b[tid];
    }
    for (int i = tid; i < 8 * 384; i += 256) sVwih[i] = g_vwih[blk * (8 * 384) + i];
    for (int i = tid; i < 8 * 128; i += 256) sWqk[i] = g_wqk[blk * (8 * 128) + i];

    // init SLOT from slot_mu (+stats)
    {
        float s1 = 0.f, s2 = 0.f;
        const float* mu = slot_mu + (rowT & 15) * DD + h2 * 64;
        for (int q = 0; q < 32; q++) {
            const float v0 = mu[2 * q], v1 = mu[2 * q + 1];
            u32 lo; u32 hi = split_pair(v0, v1, lo);
            *(u32*)&SLH[rowT * AST + h2 * 64 + 2 * q] = hi;
            *(u32*)&SLL[rowT * AST + h2 * 64 + 2 * q] = lo;
            s1 += v0 + v1;  s2 += v0 * v0 + v1 * v1;
        }
        sStat[rowT * 4 + 2 * h2] = s1;  sStat[rowT * 4 + 2 * h2 + 1] = s2;
    }
    __syncthreads();

    const u32 aRow = (u32)(e * 16 + (lane & 7) + ((lane >> 3) & 1) * 8);
    const u32 aOffB = aRow * (AST * 2) + (u32)(((lane >> 4) & 1) * 16);
    const u32 adSLH = smem_u32(SLH) + aOffB;
    const u32 adSLL = smem_u32(SLL) + aOffB;
    const u32 bRow = (u32)((lane & 7) + ((lane >> 3) & 1) * 8);

    const int lq = lane >> 2, lc = (lane & 3) * 2;
    const int r0 = e * 16 + lq, r1 = r0 + 8;

    int cur = 0;

#define FETCHB(b) do { \
    const char* _src = (const char*)gBall + (size_t)(b) * 18432; \
    u32 _dst = bufBase + (u32)((b) & 1) * 18432; \
    for (int _i = tid; _i < 1152; _i += 256) cp16(_dst + (u32)_i * 16, _src + _i * 16); \
    CP_COMMIT(); \
} while (0)

#define PHASE(DUALF, ACC) do { \
    CP_WAIT0(); \
    __syncthreads(); \
    { int _nx = cur + 1; if (_nx == 20) _nx = 0; FETCHB(_nx); } \
    u32 _bAd = bufBase + (u32)(cur & 1) * 18432 + bRow * 144; \
    if (DUALF) gemm_blk<true>(adSLH, adSLL, _bAd, ACC); \
    else gemm_blk<false>(adSLH, 0u, _bAd, ACC); \
    cur = (cur + 1 == 20) ? 0 : cur + 1; \
} while (0)

    for (int it = 0; it < 3; it++) {
        // ---- logits (fold LN_sl) ----
        {
            const float mu = (sStat[rowT * 4] + sStat[rowT * 4 + 2]) * (1.f / 128.f);
            const float rs = rsqrtf((sStat[rowT * 4 + 1] + sStat[rowT * 4 + 3]) * (1.f / 128.f) - mu * mu + 1e-5f);
            float pd = 0.f;
            for (int q = 0; q < 32; q++) {
                const int j = h2 * 64 + 2 * q;
                float2 v = unsplit(*(u32*)&SLH[rowT * AST + j], *(u32*)&SLL[rowT * AST + j]);
                pd += ((v.x - mu) * rs * sPar[1024 + j] + sPar[1152 + j]) * sWqk[(rowT >> 4) * 128 + j];
                pd += ((v.y - mu) * rs * sPar[1024 + j + 1] + sPar[1152 + j + 1]) * sWqk[(rowT >> 4) * 128 + j + 1];
            }
            sLog[rowT * 2 + h2] = pd;
        }
        __syncthreads();
        if (lane < 16) {
            const int r2 = warp * 16 + lane;
            const float l = (sLog[r2 * 2] + sLog[r2 * 2 + 1]) * invscale;
            float m = l;
            #pragma unroll
            for (int off = 8; off > 0; off >>= 1) m = fmaxf(m, __shfl_xor_sync(0xffffu, m, off));
            const float ex = __expf(l - m);
            float ss = ex;
            #pragma unroll
            for (int off = 8; off > 0; off >>= 1) ss += __shfl_xor_sync(0xffffu, ss, off);
            sAttn[r2] = ex / ss;
        }
        __syncthreads();

        // ---- gates (blocks 0..11) + GRU per half ----
        for (int half = 0; half < 2; half++) {
            float accR[32], accZ[32], accN[32];
            #pragma unroll
            for (int i = 0; i < 32; i++) { accR[i] = 0.f; accZ[i] = 0.f; accN[i] = 0.f; }
            PHASE(true, accR);  PHASE(false, accR);
            PHASE(true, accZ);  PHASE(false, accZ);
            PHASE(true, accN);  PHASE(false, accN);

            const int cb = half * 64;
            const float a0f = sAttn[r0], a1f = sAttn[r1];
            float s1[2] = {0.f, 0.f}, s2[2] = {0.f, 0.f};
            #pragma unroll
            for (int i = 0; i < 8; i++) {
                const int j0 = cb + 8 * i + lc;
                #pragma unroll
                for (int p2 = 0; p2 < 2; p2++) {
                    const int row = p2 ? r1 : r0;
                    const float af = p2 ? a1f : a0f;
                    float2 hv = unsplit(*(u32*)&SLH[row * AST + j0], *(u32*)&SLL[row * AST + j0]);
                    float nvv[2];
                    #pragma unroll
                    for (int c = 0; c < 2; c++) {
                        const int j = j0 + c;
                        const float gr = accR[i * 4 + p2 * 2 + c] + sPar[384 + j];
                        const float gz = accZ[i * 4 + p2 * 2 + c] + sPar[512 + j];
                        const float gn = accN[i * 4 + p2 * 2 + c] + sPar[640 + j];
                        const float rr = sigm(af * sVwih[e * 384 + j] + sPar[j] + gr);
                        const float zz = sigm(af * sVwih[e * 384 + 128 + j] + sPar[128 + j] + gz);
                        const float nn = tanha(af * sVwih[e * 384 + 256 + j] + sPar[256 + j] + rr * gn);
                        const float h = c ? hv.y : hv.x;
                        nvv[c] = (1.f - zz) * nn + zz * h;
                    }
                    u32 lo; u32 hi = split_pair(nvv[0], nvv[1], lo);
                    *(u32*)&WKH[row * AST + j0] = hi;
                    *(u32*)&WKL[row * AST + j0] = lo;
                    s1[p2] += nvv[0] + nvv[1];
                    s2[p2] += nvv[0] * nvv[0] + nvv[1] * nvv[1];
                }
            }
            #pragma unroll
            for (int p2 = 0; p2 < 2; p2++) {
                s1[p2] += __shfl_xor_sync(0xffffffffu, s1[p2], 1);
                s1[p2] += __shfl_xor_sync(0xffffffffu, s1[p2], 2);
                s2[p2] += __shfl_xor_sync(0xffffffffu, s2[p2], 1);
                s2[p2] += __shfl_xor_sync(0xffffffffu, s2[p2], 2);
            }
            if ((lane & 3) == 0) {
                sStat[r0 * 4 + 2 * half] = s1[0];  sStat[r0 * 4 + 2 * half + 1] = s2[0];
                sStat[r1 * 4 + 2 * half] = s1[1];  sStat[r1 * 4 + 2 * half + 1] = s2[1];
            }
        }
        __syncthreads();

        // ---- ln_mlp: WORK -> SLOT ----
        {
            const float mu = (sStat[rowT * 4] + sStat[rowT * 4 + 2]) * (1.f / 128.f);
            const float rs = rsqrtf((sStat[rowT * 4 + 1] + sStat[rowT * 4 + 3]) * (1.f / 128.f) - mu * mu + 1e-5f);
            for (int q = 0; q < 32; q++) {
                const int j = h2 * 64 + 2 * q;
                float2 v = unsplit(*(u32*)&WKH[rowT * AST + j], *(u32*)&WKL[rowT * AST + j]);
                const float l0 = (v.x - mu) * rs * sPar[1280 + j] + sPar[1408 + j];
                const float l1 = (v.y - mu) * rs * sPar[1280 + j + 1] + sPar[1408 + j + 1];
                u32 lo; u32 hi = split_pair(l0, l1, lo);
                *(u32*)&SLH[rowT * AST + j] = hi;
                *(u32*)&SLL[rowT * AST + j] = lo;
            }
        }
        // (phase pre-compute sync orders these writes before W1 reads)

        // ---- W1 (blocks 12..15) ----
        float accA[32], accB[32];
        #pragma unroll
        for (int i = 0; i < 32; i++) { accA[i] = 0.f; accB[i] = 0.f; }
        PHASE(true, accA);  PHASE(false, accA);
        PHASE(true, accB);  PHASE(false, accB);
        __syncthreads();  // all W1 reads of SLOT done
        // h1 = relu(acc + b1) -> SLOT
        #pragma unroll
        for (int half = 0; half < 2; half++) {
            float* acc = half ? accB : accA;
            #pragma unroll
            for (int i = 0; i < 8; i++) {
                const int j0 = half * 64 + 8 * i + lc;
                #pragma unroll
                for (int p2 = 0; p2 < 2; p2++) {
                    const int row = p2 ? r1 : r0;
                    const float v0 = fmaxf(acc[i * 4 + p2 * 2] + sPar[768 + j0], 0.f);
                    const float v1 = fmaxf(acc[i * 4 + p2 * 2 + 1] + sPar[768 + j0 + 1], 0.f);
                    u32 lo; u32 hi = split_pair(v0, v1, lo);
                    *(u32*)&SLH[row * AST + j0] = hi;
                    *(u32*)&SLL[row * AST + j0] = lo;
                }
            }
        }

        // ---- W2 (blocks 16..19) ----
        #pragma unroll
        for (int i = 0; i < 32; i++) { accA[i] = 0.f; accB[i] = 0.f; }
        PHASE(true, accA);  PHASE(false, accA);
        PHASE(true, accB);  PHASE(false, accB);
        // residual: slots'' = WORK + acc + b2 -> SLOT, stats (own rows only; no sync needed)
        {
            float s1[2] = {0.f, 0.f}, s2[2] = {0.f, 0.f};
            #pragma unroll
            for (int half = 0; half < 2; half++) {
                float* acc = half ? accB : accA;
                float t1[2] = {0.f, 0.f}, t2[2] = {0.f, 0.f};
                #pragma unroll
                for (int i = 0; i < 8; i++) {
                    const int j0 = half * 64 + 8 * i + lc;
                    #pragma unroll
                    for (int p2 = 0; p2 < 2; p2++) {
                        const int row = p2 ? r1 : r0;
                        float2 w = unsplit(*(u32*)&WKH[row * AST + j0], *(u32*)&WKL[row * AST + j0]);
                        const float v0 = w.x + acc[i * 4 + p2 * 2] + sPar[896 + j0];
                        const float v1 = w.y + acc[i * 4 + p2 * 2 + 1] + sPar[896 + j0 + 1];
                        u32 lo; u32 hi = split_pair(v0, v1, lo);
                        *(u32*)&SLH[row * AST + j0] = hi;
                        *(u32*)&SLL[row * AST + j0] = lo;
                        t1[p2] += v0 + v1;
                        t2[p2] += v0 * v0 + v1 * v1;
                    }
                }
                #pragma unroll
                for (int p2 = 0; p2 < 2; p2++) {
                    t1[p2] += __shfl_xor_sync(0xffffffffu, t1[p2], 1);
                    t1[p2] += __shfl_xor_sync(0xffffffffu, t1[p2], 2);
                    t2[p2] += __shfl_xor_sync(0xffffffffu, t2[p2], 1);
                    t2[p2] += __shfl_xor_sync(0xffffffffu, t2[p2], 2);
                }
                if ((lane & 3) == 0) {
                    sStat[r0 * 4 + 2 * half] = t1[0];  sStat[r0 * 4 + 2 * half + 1] = t2[0];
                    sStat[r1 * 4 + 2 * half] = t1[1];  sStat[r1 * 4 + 2 * half + 1] = t2[1];
                }
                s1[0] += 0.f; s2[0] += 0.f; (void)s1; (void)s2;
            }
        }
        __syncthreads();  // stats + SLOT visible for next iter / final normalize
    }

    // ---- final F.normalize + store ----
    {
        const float qq = sStat[rowT * 4 + 1] + sStat[rowT * 4 + 3];
        const float inv = 1.f / fmaxf(sqrtf(qq), 1e-8f);
        float* dst = out + (blk * 8 + (rowT >> 4)) * (NS * DD) + (rowT & 15) * DD + h2 * 64;
        for (int q = 0; q < 32; q++) {
            const int j = h2 * 64 + 2 * q;
            float2 v = unsplit(*(u32*)&SLH[rowT * AST + j], *(u32*)&SLL[rowT * AST + j]);
            dst[2 * q] = v.x * inv;
            dst[2 * q + 1] = v.y * inv;
        }
    }
#undef PHASE
#undef FETCHB
}

// ---------------------------------------------------------------------------
// Kernel 4: temporal blend — 256 CTAs (one per batch), 128 threads,
// each thread owns column j for all 16 slot rows (Wt loads amortize 16x).
// ---------------------------------------------------------------------------
__global__ __launch_bounds__(128) void temporal_kernel(float* __restrict__ out)
{
    __shared__ __align__(16) float s_prev[NS * DD];
    const int j = threadIdx.x;
    const long b = blockIdx.x;
    float* base = out + b * 64 * (NS * DD);
    for (int i = j; i < NS * DD; i += 128) s_prev[i] = base[i];
    __syncthreads();
    for (int t = 1; t < 64; t++) {
        float* cur = base + t * (NS * DD);
        u64 acc[16];
        #pragma unroll
        for (int r = 0; r < 16; r++) acc[r] = 0;
        for (int d4 = 0; d4 < 32; d4++) {
            const ulonglong2 w = pWt[d4 * DD + j];
            #pragma unroll
            for (int r = 0; r < 16; r++) {
                const ulonglong2 s = *(const ulonglong2*)&s_prev[r * DD + 4 * d4];
                acc[r] = fma2(s.x, w.x, acc[r]);
                acc[r] = fma2(s.y, w.y, acc[r]);
            }
        }
        __syncthreads();
        #pragma unroll
        for (int r = 0; r < 16; r++) {
            const float v = 0.7f * cur[r * DD + j] + 0.3f * tanha(sum2(acc[r]));
            cur[r * DD + j] = v;
            s_prev[r * DD + j] = v;
        }
        __syncthreads();
    }
}

// ---------------------------------------------------------------------------
extern "C" void kernel_launch(void* const* d_in, const int* in_sizes, int n_in,
                              void* d_out, int out_size)
{
    const float* obs   = (const float*)d_in[0];
    const float* eW1   = (const float*)d_in[1];
    const float* eb1   = (const float*)d_in[2];
    const float* eW2   = (const float*)d_in[3];
    const float* eb2   = (const float*)d_in[4];
    const float* skipW = (const float*)d_in[5];
    const float* smu   = (const float*)d_in[6];
    const float* Wk    = (const float*)d_in[7];
    const float* Wv    = (const float*)d_in[8];
    const float* Wq    = (const float*)d_in[9];
    const float* gWih  = (const float*)d_in[10];
    const float* gWhh  = (const float*)d_in[11];
    const float* gbih  = (const float*)d_in[12];
    const float* gbhh  = (const float*)d_in[13];
    const float* mW1   = (const float*)d_in[14];
    const float* mb1   = (const float*)d_in[15];
    const float* mW2   = (const float*)d_in[16];
    const float* mb2   = (const float*)d_in[17];
    const float* lin_g = (const float*)d_in[18];
    const float* lin_b = (const float*)d_in[19];
    const float* lsl_g = (const float*)d_in[20];
    const float* lsl_b = (const float*)d_in[21];
    const float* lml_g = (const float*)d_in[22];
    const float* lml_b = (const float*)d_in[23];
    const float* Wt    = (const float*)d_in[24];
    float* out = (float*)d_out;

    static int init_done = 0;
    if (!init_done) {
        cudaFuncSetAttribute(slot_mma, cudaFuncAttributeMaxDynamicSharedMemorySize, SMEM_DYN);
        init_done = 1;
    }

    pack_all<<<(270336 + 255) / 256, 256>>>(eW1, eW2, skipW, Wk, Wv, Wq,
                                            gWih, gWhh, mW1, mW2, Wt);
    enc_kernel<<<BT / 8, 256>>>(obs, eb1, eb2);
    prolog_kernel<<<BT / 2, 256>>>(lin_g, lin_b);
    slot_mma<<<BT / 8, 256, SMEM_DYN>>>(smu, gbih, gbhh, mb1, mb2,
                                        lsl_g, lsl_b, lml_g, lml_b, out);
    temporal_kernel<<<256, 128>>>(out);
}

// round 13
// speedup vs baseline: 4.1541x; 1.1990x over previous
#include <cuda_runtime.h>
#include <cuda_bf16.h>
#include <stdint.h>
#include <math.h>

#define BT 16384
#define DOBS 512
#define DD 128
#define NS 16
#define HH 256

typedef unsigned long long u64;
typedef unsigned int u32;
typedef unsigned short u16;

__device__ __forceinline__ u64 fma2(u64 a, u64 b, u64 c) {
    u64 d;
    asm("fma.rn.f32x2 %0, %1, %2, %3;" : "=l"(d) : "l"(a), "l"(b), "l"(c));
    return d;
}
__device__ __forceinline__ float sum2(u64 a) {
    float2 f = *(float2*)&a;
    return f.x + f.y;
}
__device__ __forceinline__ u64 pack2(float lo, float hi) {
    u64 r;
    asm("mov.b64 %0, {%1, %2};" : "=l"(r) : "f"(lo), "f"(hi));
    return r;
}
__device__ __forceinline__ float tanha(float x) {
    float y;
    asm("tanh.approx.f32 %0, %1;" : "=f"(y) : "f"(x));
    return y;
}
__device__ __forceinline__ float sigm(float x) { return 0.5f * tanha(0.5f * x) + 0.5f; }

__device__ __forceinline__ u32 split_pair(float v0, float v1, u32& lo_out) {
    __nv_bfloat16 h0 = __float2bfloat16(v0), h1 = __float2bfloat16(v1);
    __nv_bfloat16 l0 = __float2bfloat16(v0 - __bfloat162float(h0));
    __nv_bfloat16 l1 = __float2bfloat16(v1 - __bfloat162float(h1));
    lo_out = (u32)__bfloat16_as_ushort(l0) | ((u32)__bfloat16_as_ushort(l1) << 16);
    return (u32)__bfloat16_as_ushort(h0) | ((u32)__bfloat16_as_ushort(h1) << 16);
}
__device__ __forceinline__ float2 unsplit(u32 hi, u32 lo) {
    float2 r;
    r.x = __bfloat162float(__ushort_as_bfloat16((u16)(hi & 0xffff)))
        + __bfloat162float(__ushort_as_bfloat16((u16)(lo & 0xffff)));
    r.y = __bfloat162float(__ushort_as_bfloat16((u16)(hi >> 16)))
        + __bfloat162float(__ushort_as_bfloat16((u16)(lo >> 16)));
    return r;
}

// ---------------- mma / ldmatrix / cp.async helpers ----------------
__device__ __forceinline__ u32 smem_u32(const void* p) {
    u32 a;
    asm("{ .reg .u64 t; cvta.to.shared.u64 t, %1; cvt.u32.u64 %0, t; }" : "=r"(a) : "l"(p));
    return a;
}
__device__ __forceinline__ void mma_bf16(float* d, u32 a0, u32 a1, u32 a2, u32 a3,
                                         u32 b0, u32 b1) {
    asm volatile(
        "mma.sync.aligned.m16n8k16.row.col.f32.bf16.bf16.f32 "
        "{%0,%1,%2,%3}, {%4,%5,%6,%7}, {%8,%9}, {%0,%1,%2,%3};"
        : "+f"(d[0]), "+f"(d[1]), "+f"(d[2]), "+f"(d[3])
        : "r"(a0), "r"(a1), "r"(a2), "r"(a3), "r"(b0), "r"(b1));
}
__device__ __forceinline__ void cp16(u32 saddr, const void* g) {
    asm volatile("cp.async.cg.shared.global [%0], [%1], 16;" :: "r"(saddr), "l"(g));
}
#define CP_COMMIT() asm volatile("cp.async.commit_group;" ::: "memory")
#define CP_WAIT1()  asm volatile("cp.async.wait_group 1;" ::: "memory")

// One B block (k=128, n=64, row stride 144B). A fragments from registers.
template<bool DUAL>
__device__ __forceinline__ void gemm_blk2(const u32* Ah, const u32* Al, u32 bAd, float* acc) {
    #pragma unroll
    for (int k = 0; k < 8; k++) {
        #pragma unroll
        for (int q = 0; q < 4; q++) {
            u32 b0, b1, b2, b3;
            asm volatile("ldmatrix.sync.aligned.m8n8.x4.trans.shared.b16 {%0,%1,%2,%3}, [%4];"
                : "=r"(b0), "=r"(b1), "=r"(b2), "=r"(b3) : "r"(bAd + (u32)(k * 2304 + q * 32)));
            mma_bf16(acc + (q * 2) * 4,     Ah[k * 4], Ah[k * 4 + 1], Ah[k * 4 + 2], Ah[k * 4 + 3], b0, b1);
            mma_bf16(acc + (q * 2 + 1) * 4, Ah[k * 4], Ah[k * 4 + 1], Ah[k * 4 + 2], Ah[k * 4 + 3], b2, b3);
            if (DUAL) {
                mma_bf16(acc + (q * 2) * 4,     Al[k * 4], Al[k * 4 + 1], Al[k * 4 + 2], Al[k * 4 + 3], b0, b1);
                mma_bf16(acc + (q * 2 + 1) * 4, Al[k * 4], Al[k * 4 + 1], Al[k * 4 + 2], Al[k * 4 + 3], b2, b3);
            }
        }
    }
}

// ---------------- device scratch ----------------
__device__ float g_z[BT * DD];
__device__ float g_wqk[BT * DD];
__device__ float g_vwih[BT * 384];

__device__ ulonglong2 pW1[128 * 256];
__device__ ulonglong2 pW2[64 * 128];
__device__ ulonglong2 pSkip[128 * 128];
__device__ ulonglong2 pWk[32 * 128];
__device__ ulonglong2 pWv[32 * 128];
__device__ ulonglong2 pWqT[32 * 128];
__device__ ulonglong2 pWih[32 * 384];
__device__ ulonglong2 pWt[32 * 128];

// 20 uniform B blocks, each [k=128][n=72] bf16 = 18432 B.
__device__ u16 gBall[20 * 9216];

// ---------------- pack ----------------
__device__ __forceinline__ void pack_elem(const float* __restrict__ s0, ulonglong2* __restrict__ dst, int C, int idx) {
    int c = idx % C, k4 = idx / C;
    const float* s = s0 + (4 * k4) * C + c;
    ulonglong2 v;
    v.x = pack2(s[0], s[C]);
    v.y = pack2(s[2 * C], s[3 * C]);
    dst[idx] = v;
}
__device__ __forceinline__ void packT_elem(const float* __restrict__ s0, ulonglong2* __restrict__ dst, int K, int C4, int idx) {
    int i = idx % K, j4 = idx / K;
    const float* s = s0 + i * (C4 * 4) + 4 * j4;
    ulonglong2 v;
    v.x = pack2(s[0], s[1]);
    v.y = pack2(s[2], s[3]);
    dst[idx] = v;
}
__device__ __forceinline__ u16 bf_hi(float w) {
    return __bfloat16_as_ushort(__float2bfloat16(w));
}
__device__ __forceinline__ u16 bf_lo(float w) {
    float hf = __bfloat162float(__float2bfloat16(w));
    return __bfloat16_as_ushort(__float2bfloat16(w - hf));
}

__global__ __launch_bounds__(256) void pack_all(
    const float* __restrict__ eW1, const float* __restrict__ eW2, const float* __restrict__ skipW,
    const float* __restrict__ Wk, const float* __restrict__ Wv, const float* __restrict__ Wq,
    const float* __restrict__ gWih, const float* __restrict__ gWhh,
    const float* __restrict__ mW1, const float* __restrict__ mW2, const float* __restrict__ Wt)
{
    int idx = blockIdx.x * 256 + threadIdx.x;
    if (idx < 32768) { pack_elem(eW1, pW1, 256, idx); return; }   idx -= 32768;
    if (idx < 8192)  { pack_elem(eW2, pW2, 128, idx); return; }   idx -= 8192;
    if (idx < 16384) { pack_elem(skipW, pSkip, 128, idx); return; } idx -= 16384;
    if (idx < 4096)  { pack_elem(Wk, pWk, 128, idx); return; }    idx -= 4096;
    if (idx < 4096)  { pack_elem(Wv, pWv, 128, idx); return; }    idx -= 4096;
    if (idx < 4096)  { packT_elem(Wq, pWqT, 128, 32, idx); return; } idx -= 4096;
    if (idx < 12288) { pack_elem(gWih, pWih, 384, idx); return; } idx -= 12288;
    if (idx < 4096)  { pack_elem(Wt, pWt, 128, idx); return; }    idx -= 4096;
    if (idx >= 184320) return;
    const int b = idx / 9216, r = idx % 9216;
    const int k = r / 72, n = r % 72;
    float w = 0.f;
    int s;
    if (b < 12) {
        const int half = b / 6, rem = b % 6, g = rem >> 1;
        s = rem & 1;
        if (n < 64) w = gWhh[k * 384 + g * 128 + half * 64 + n];
    } else {
        const int bb = b - 12, m = bb >> 2, half = (bb >> 1) & 1;
        s = bb & 1;
        if (n < 64) w = (m ? mW2 : mW1)[k * 128 + half * 64 + n];
    }
    gBall[idx] = s ? bf_lo(w) : bf_hi(w);
}

// ---------------------------------------------------------------------------
// Kernel 1: encoder (proven)
// ---------------------------------------------------------------------------
__global__ __launch_bounds__(256) void enc_kernel(
    const float* __restrict__ obs, const float* __restrict__ b1, const float* __restrict__ b2)
{
    __shared__ __align__(16) float s_obs[8 * DOBS];
    __shared__ __align__(16) float s_h[8 * HH];
    __shared__ __align__(16) float s_p1[8 * DD];
    const int tid = threadIdx.x;
    const long e0 = (long)blockIdx.x * 8;
    const float* op = obs + e0 * DOBS;
    for (int i = tid; i < 8 * DOBS / 4; i += 256)
        ((float4*)s_obs)[i] = ((const float4*)op)[i];
    __syncthreads();
    {
        const int j = tid;
        u64 acc[8] = {0, 0, 0, 0, 0, 0, 0, 0};
        for (int d4 = 0; d4 < 128; d4++) {
            const ulonglong2 w = pW1[d4 * HH + j];
            #pragma unroll
            for (int r = 0; r < 8; r++) {
                const ulonglong2 s = *(const ulonglong2*)&s_obs[r * DOBS + 4 * d4];
                acc[r] = fma2(s.x, w.x, acc[r]);
                acc[r] = fma2(s.y, w.y, acc[r]);
            }
        }
        const float bj = b1[j];
        #pragma unroll
        for (int r = 0; r < 8; r++) {
            const float a = sum2(acc[r]) + bj;
            s_h[r * HH + j] = 0.5f * a * (1.f + erff(a * 0.70710678118654752f));
        }
    }
    __syncthreads();
    const int j = tid & 127;
    const int half = tid >> 7;
    u64 acc[8] = {0, 0, 0, 0, 0, 0, 0, 0};
    if (half == 0) {
        for (int d4 = 0; d4 < 64; d4++) {
            const ulonglong2 w = pW2[d4 * DD + j];
            #pragma unroll
            for (int r = 0; r < 8; r++) {
                const ulonglong2 s = *(const ulonglong2*)&s_h[r * HH + 4 * d4];
                acc[r] = fma2(s.x, w.x, acc[r]);
                acc[r] = fma2(s.y, w.y, acc[r]);
            }
        }
        for (int d4 = 0; d4 < 32; d4++) {
            const ulonglong2 w = pSkip[d4 * DD + j];
            #pragma unroll
            for (int r = 0; r < 8; r++) {
                const ulonglong2 s = *(const ulonglong2*)&s_obs[r * DOBS + 4 * d4];
                acc[r] = fma2(s.x, w.x, acc[r]);
                acc[r] = fma2(s.y, w.y, acc[r]);
            }
        }
    } else {
        for (int d4 = 32; d4 < 128; d4++) {
            const ulonglong2 w = pSkip[d4 * DD + j];
            #pragma unroll
            for (int r = 0; r < 8; r++) {
                const ulonglong2 s = *(const ulonglong2*)&s_obs[r * DOBS + 4 * d4];
                acc[r] = fma2(s.x, w.x, acc[r]);
                acc[r] = fma2(s.y, w.y, acc[r]);
            }
        }
        #pragma unroll
        for (int r = 0; r < 8; r++) s_p1[r * DD + j] = sum2(acc[r]);
    }
    __syncthreads();
    if (half == 0) {
        const float bj = b2[j];
        #pragma unroll
        for (int r = 0; r < 8; r++)
            g_z[(e0 + r) * DD + j] = tanha(sum2(acc[r]) + s_p1[r * DD + j] + bj);
    }
}

// ---------------------------------------------------------------------------
// Kernel 2: prologue — LN(z), k, v, wqk, vwih -> global. (proven)
// ---------------------------------------------------------------------------
__global__ __launch_bounds__(256) void prolog_kernel(
    const float* __restrict__ lin_g, const float* __restrict__ lin_b)
{
    __shared__ __align__(16) float inp[2][DD], kk[2][DD], vv[2][DD];
    __shared__ float red[2][12];
    const int tid = threadIdx.x, lane = tid & 31, warp = tid >> 5;
    const int el = tid >> 7, j = tid & 127;
    const long ent = (long)blockIdx.x * 2 + el;
    const float zv = g_z[ent * DD + j];
    {
        float s1 = zv, s2 = zv * zv;
        #pragma unroll
        for (int off = 16; off > 0; off >>= 1) {
            s1 += __shfl_down_sync(0xffffffffu, s1, off);
            s2 += __shfl_down_sync(0xffffffffu, s2, off);
        }
        if (lane == 0) { red[el][warp & 3] = s1; red[el][4 + (warp & 3)] = s2; }
    }
    __syncthreads();
    if (j == 0) {
        float s = red[el][0] + red[el][1] + red[el][2] + red[el][3];
        float q = red[el][4] + red[el][5] + red[el][6] + red[el][7];
        const float mu = s * (1.f / 128.f);
        red[el][8] = mu;
        red[el][9] = rsqrtf(q * (1.f / 128.f) - mu * mu + 1e-5f);
    }
    __syncthreads();
    inp[el][j] = (zv - red[el][8]) * red[el][9] * lin_g[j] + lin_b[j];
    __syncthreads();
    u64 acc = 0;
    for (int d4 = 0; d4 < 32; d4++) {
        const ulonglong2 s = *(const ulonglong2*)&inp[el][4 * d4];
        const ulonglong2 w = pWk[d4 * DD + j];
        acc = fma2(s.x, w.x, acc);
        acc = fma2(s.y, w.y, acc);
    }
    kk[el][j] = sum2(acc);
    acc = 0;
    for (int d4 = 0; d4 < 32; d4++) {
        const ulonglong2 s = *(const ulonglong2*)&inp[el][4 * d4];
        const ulonglong2 w = pWv[d4 * DD + j];
        acc = fma2(s.x, w.x, acc);
        acc = fma2(s.y, w.y, acc);
    }
    vv[el][j] = sum2(acc);
    __syncthreads();
    acc = 0;
    for (int j4 = 0; j4 < 32; j4++) {
        const ulonglong2 s = *(const ulonglong2*)&kk[el][4 * j4];
        const ulonglong2 w = pWqT[j4 * DD + j];
        acc = fma2(s.x, w.x, acc);
        acc = fma2(s.y, w.y, acc);
    }
    g_wqk[ent * DD + j] = sum2(acc);
    #pragma unroll
    for (int pp = 0; pp < 3; pp++) {
        const int c = j + 128 * pp;
        u64 a2 = 0;
        for (int d4 = 0; d4 < 32; d4++) {
            const ulonglong2 s = *(const ulonglong2*)&vv[el][4 * d4];
            const ulonglong2 w = pWih[d4 * 384 + c];
            a2 = fma2(s.x, w.x, a2);
            a2 = fma2(s.y, w.y, a2);
        }
        g_vwih[ent * 384 + c] = sum2(a2);
    }
}

// ---------------------------------------------------------------------------
// Kernel 3: register-resident mma.sync slot attention. 8 entries/CTA,
// 256 threads = 8 warps; warp e owns entry e. Slots live in registers; A
// fragments built from registers. B streams through a 3-deep cp.async ring.
// ---------------------------------------------------------------------------
#define SMEM_DYN 77824

__global__ __launch_bounds__(256) void slot_mma(
    const float* __restrict__ slot_mu,
    const float* __restrict__ bih, const float* __restrict__ bhh,
    const float* __restrict__ mb1, const float* __restrict__ mb2,
    const float* __restrict__ lsl_g, const float* __restrict__ lsl_b,
    const float* __restrict__ lml_g, const float* __restrict__ lml_b,
    float* __restrict__ out)
{
    extern __shared__ __align__(16) char dyn[];
    // [0, 55296): B ring (3 x 18432)
    float* sWqk  = (float*)(dyn + 55296);
    float* sVwih = (float*)(dyn + 59392);
    float* sPar  = (float*)(dyn + 71680);

    const int tid = threadIdx.x, lane = tid & 31, warp = tid >> 5;
    const int e = warp;
    const int lq = lane >> 2, lc = (lane & 3) * 2;
    const long blk = blockIdx.x;
    const float invscale = 0.088388347648318447f;
    const u32 ring = smem_u32(dyn);

    // prefetch B blocks 0, 1
    {
        const char* s0 = (const char*)gBall;
        for (int i = tid; i < 1152; i += 256) cp16(ring + (u32)i * 16, s0 + i * 16);
        CP_COMMIT();
        const char* s1 = (const char*)gBall + 18432;
        for (int i = tid; i < 1152; i += 256) cp16(ring + 18432u + (u32)i * 16, s1 + i * 16);
        CP_COMMIT();
    }

    for (int i = tid; i < 384; i += 256) { sPar[i] = bih[i]; sPar[384 + i] = bhh[i]; }
    if (tid < 128) {
        sPar[768 + tid] = mb1[tid];  sPar[896 + tid] = mb2[tid];
        sPar[1024 + tid] = lsl_g[tid]; sPar[1152 + tid] = lsl_b[tid];
        sPar[1280 + tid] = lml_g[tid]; sPar[1408 + tid] = lml_b[tid];
    }
    for (int i = tid; i < 8 * 384; i += 256) sVwih[i] = g_vwih[blk * (8 * 384) + i];
    for (int i = tid; i < 8 * 128; i += 256) sWqk[i] = g_wqk[blk * (8 * 128) + i];

    // slots in registers: sl[i2*4 + p2*2 + c] = slots[row lq+8*p2][col 8*i2+lc+c]
    float sl[64];
    #pragma unroll
    for (int i2 = 0; i2 < 16; i2++)
        #pragma unroll
        for (int p2 = 0; p2 < 2; p2++) {
            const float* src = slot_mu + (lq + 8 * p2) * DD + 8 * i2 + lc;
            sl[i2 * 4 + p2 * 2 + 0] = src[0];
            sl[i2 * 4 + p2 * 2 + 1] = src[1];
        }

    // CRITICAL: make sPar/sVwih/sWqk visible to all warps before first use
    __syncthreads();

    const u32 bLane = (u32)((lane & 15) * 144 + ((lane >> 4) & 1) * 16);
    int fb = 2, fs = 2, cs = 0;   // next fetch block / fetch slot / compute slot

#define PHASE(DUALF, AHP, ALP, ACC) do { \
    CP_WAIT1(); \
    __syncthreads(); \
    { const char* _s = (const char*)gBall + fb * 18432; \
      u32 _d = ring + (u32)fs * 18432u; \
      for (int _i = tid; _i < 1152; _i += 256) cp16(_d + (u32)_i * 16, _s + _i * 16); \
      CP_COMMIT(); \
      fb++; if (fb == 20) fb = 0; \
      fs++; if (fs == 3) fs = 0; } \
    gemm_blk2<DUALF>(AHP, ALP, ring + (u32)cs * 18432u + bLane, ACC); \
    cs++; if (cs == 3) cs = 0; \
} while (0)

    u32 Ah[32], Al[32];

    for (int it = 0; it < 3; it++) {
        // ---- stats of sl (per row, quad-reduce) ----
        float mu_[2], rs_[2];
        #pragma unroll
        for (int p2 = 0; p2 < 2; p2++) {
            float s = 0.f, q = 0.f;
            #pragma unroll
            for (int i2 = 0; i2 < 16; i2++) {
                const float v0 = sl[i2 * 4 + p2 * 2], v1 = sl[i2 * 4 + p2 * 2 + 1];
                s += v0 + v1;  q += v0 * v0 + v1 * v1;
            }
            s += __shfl_xor_sync(0xffffffffu, s, 1);
            s += __shfl_xor_sync(0xffffffffu, s, 2);
            q += __shfl_xor_sync(0xffffffffu, q, 1);
            q += __shfl_xor_sync(0xffffffffu, q, 2);
            mu_[p2] = s * (1.f / 128.f);
            rs_[p2] = rsqrtf(q * (1.f / 128.f) - mu_[p2] * mu_[p2] + 1e-5f);
        }
        // ---- logits (fold LN_sl) + softmax (warp-local) ----
        float pd0 = 0.f, pd1 = 0.f;
        #pragma unroll
        for (int i2 = 0; i2 < 16; i2++) {
            const int j0 = 8 * i2 + lc;
            const float g0 = sPar[1024 + j0], g1 = sPar[1024 + j0 + 1];
            const float bb0 = sPar[1152 + j0], bb1 = sPar[1152 + j0 + 1];
            const float w0 = sWqk[e * 128 + j0], w1 = sWqk[e * 128 + j0 + 1];
            pd0 += ((sl[i2 * 4 + 0] - mu_[0]) * rs_[0] * g0 + bb0) * w0
                 + ((sl[i2 * 4 + 1] - mu_[0]) * rs_[0] * g1 + bb1) * w1;
            pd1 += ((sl[i2 * 4 + 2] - mu_[1]) * rs_[1] * g0 + bb0) * w0
                 + ((sl[i2 * 4 + 3] - mu_[1]) * rs_[1] * g1 + bb1) * w1;
        }
        pd0 += __shfl_xor_sync(0xffffffffu, pd0, 1);
        pd0 += __shfl_xor_sync(0xffffffffu, pd0, 2);
        pd1 += __shfl_xor_sync(0xffffffffu, pd1, 1);
        pd1 += __shfl_xor_sync(0xffffffffu, pd1, 2);
        const float l0 = pd0 * invscale, l1 = pd1 * invscale;
        float m = fmaxf(l0, l1);
        m = fmaxf(m, __shfl_xor_sync(0xffffffffu, m, 4));
        m = fmaxf(m, __shfl_xor_sync(0xffffffffu, m, 8));
        m = fmaxf(m, __shfl_xor_sync(0xffffffffu, m, 16));
        const float ex0 = __expf(l0 - m), ex1 = __expf(l1 - m);
        float ssum = ex0 + ex1;
        ssum += __shfl_xor_sync(0xffffffffu, ssum, 4);
        ssum += __shfl_xor_sync(0xffffffffu, ssum, 8);
        ssum += __shfl_xor_sync(0xffffffffu, ssum, 16);
        const float a0 = ex0 / ssum, a1 = ex1 / ssum;

        // ---- build A fragments from sl (hi/lo split) ----
        #pragma unroll
        for (int t = 0; t < 32; t++)
            Ah[t] = split_pair(sl[2 * t], sl[2 * t + 1], Al[t]);

        // ---- gates: 12 B blocks, GRU per half (all in registers) ----
        float nv0[32];
        #pragma unroll
        for (int h = 0; h < 2; h++) {
            float aR[32], aZ[32], aN[32];
            #pragma unroll
            for (int i = 0; i < 32; i++) { aR[i] = 0.f; aZ[i] = 0.f; aN[i] = 0.f; }
            PHASE(true, Ah, Al, aR);  PHASE(false, Ah, Al, aR);
            PHASE(true, Ah, Al, aZ);  PHASE(false, Ah, Al, aZ);
            PHASE(true, Ah, Al, aN);  PHASE(false, Ah, Al, aN);

            const int cb = 64 * h;
            #pragma unroll
            for (int tl = 0; tl < 16; tl++) {
                const int n = tl >> 1, p2 = tl & 1;
                const int j0 = cb + 8 * n + lc;
                const int tg = 16 * h + tl;
                const float2 hv = unsplit(Ah[tg], Al[tg]);   // old slot (split-exact)
                const float af = p2 ? a1 : a0;
                #pragma unroll
                for (int c = 0; c < 2; c++) {
                    const int j = j0 + c;
                    const float gr = aR[2 * tl + c] + sPar[384 + j];
                    const float gz = aZ[2 * tl + c] + sPar[512 + j];
                    const float gn = aN[2 * tl + c] + sPar[640 + j];
                    const float rr = sigm(af * sVwih[e * 384 + j] + sPar[j] + gr);
                    const float zz = sigm(af * sVwih[e * 384 + 128 + j] + sPar[128 + j] + gz);
                    const float nn = tanha(af * sVwih[e * 384 + 256 + j] + sPar[256 + j] + rr * gn);
                    const float hh = c ? hv.y : hv.x;
                    const float nv = (1.f - zz) * nn + zz * hh;
                    if (h == 0) nv0[2 * tl + c] = nv;
                    else        sl[32 + 2 * tl + c] = nv;
                }
            }
        }
        #pragma unroll
        for (int t = 0; t < 32; t++) sl[t] = nv0[t];

        // ---- stats of new sl, build A = LN_mlp(sl) directly ----
        #pragma unroll
        for (int p2 = 0; p2 < 2; p2++) {
            float s = 0.f, q = 0.f;
            #pragma unroll
            for (int i2 = 0; i2 < 16; i2++) {
                const float v0 = sl[i2 * 4 + p2 * 2], v1 = sl[i2 * 4 + p2 * 2 + 1];
                s += v0 + v1;  q += v0 * v0 + v1 * v1;
            }
            s += __shfl_xor_sync(0xffffffffu, s, 1);
            s += __shfl_xor_sync(0xffffffffu, s, 2);
            q += __shfl_xor_sync(0xffffffffu, q, 1);
            q += __shfl_xor_sync(0xffffffffu, q, 2);
            mu_[p2] = s * (1.f / 128.f);
            rs_[p2] = rsqrtf(q * (1.f / 128.f) - mu_[p2] * mu_[p2] + 1e-5f);
        }
        #pragma unroll
        for (int t = 0; t < 32; t++) {
            const int i2 = t >> 1, p2 = t & 1;
            const int j0 = 8 * i2 + lc;
            const float v0 = (sl[2 * t] - mu_[p2]) * rs_[p2] * sPar[1280 + j0] + sPar[1408 + j0];
            const float v1 = (sl[2 * t + 1] - mu_[p2]) * rs_[p2] * sPar[1280 + j0 + 1] + sPar[1408 + j0 + 1];
            Ah[t] = split_pair(v0, v1, Al[t]);
        }

        // ---- W1 (4 blocks) ----
        float accM[64];
        #pragma unroll
        for (int i = 0; i < 64; i++) accM[i] = 0.f;
        PHASE(true, Ah, Al, accM);       PHASE(false, Ah, Al, accM);
        PHASE(true, Ah, Al, accM + 32);  PHASE(false, Ah, Al, accM + 32);

        // h1 = relu(accM + b1) -> A fragments
        #pragma unroll
        for (int t = 0; t < 32; t++) {
            const int i2 = t >> 1;
            const int j0 = 8 * i2 + lc;
            const float v0 = fmaxf(accM[2 * t] + sPar[768 + j0], 0.f);
            const float v1 = fmaxf(accM[2 * t + 1] + sPar[768 + j0 + 1], 0.f);
            Ah[t] = split_pair(v0, v1, Al[t]);
        }

        // ---- W2 (4 blocks) ----
        #pragma unroll
        for (int i = 0; i < 64; i++) accM[i] = 0.f;
        PHASE(true, Ah, Al, accM);       PHASE(false, Ah, Al, accM);
        PHASE(true, Ah, Al, accM + 32);  PHASE(false, Ah, Al, accM + 32);

        // residual
        #pragma unroll
        for (int t = 0; t < 32; t++) {
            const int i2 = t >> 1;
            const int j0 = 8 * i2 + lc;
            sl[2 * t]     += accM[2 * t] + sPar[896 + j0];
            sl[2 * t + 1] += accM[2 * t + 1] + sPar[896 + j0 + 1];
        }
    }

    // ---- final F.normalize + store ----
    #pragma unroll
    for (int p2 = 0; p2 < 2; p2++) {
        float q = 0.f;
        #pragma unroll
        for (int i2 = 0; i2 < 16; i2++) {
            const float v0 = sl[i2 * 4 + p2 * 2], v1 = sl[i2 * 4 + p2 * 2 + 1];
            q += v0 * v0 + v1 * v1;
        }
        q += __shfl_xor_sync(0xffffffffu, q, 1);
        q += __shfl_xor_sync(0xffffffffu, q, 2);
        const float inv = 1.f / fmaxf(sqrtf(q), 1e-8f);
        float* dst = out + (blk * 8 + e) * (NS * DD) + (lq + 8 * p2) * DD;
        #pragma unroll
        for (int i2 = 0; i2 < 16; i2++) {
            float2 v;
            v.x = sl[i2 * 4 + p2 * 2] * inv;
            v.y = sl[i2 * 4 + p2 * 2 + 1] * inv;
            *(float2*)(dst + 8 * i2 + lc) = v;
        }
    }
#undef PHASE
}

// ---------------------------------------------------------------------------
// Kernel 4: temporal blend — 256 CTAs x 256 threads; thread (j, gg) owns
// column j of 8 rows.
// ---------------------------------------------------------------------------
__global__ __launch_bounds__(256) void temporal_kernel(float* __restrict__ out)
{
    __shared__ __align__(16) float s_prev[NS * DD];
    const int tid = threadIdx.x;
    const int j = tid & 127;
    const int gg = tid >> 7;               // rows gg*8 .. gg*8+7
    const long b = blockIdx.x;
    float* base = out + b * 64 * (NS * DD);
    for (int i = tid; i < NS * DD / 4; i += 256)
        ((float4*)s_prev)[i] = ((const float4*)base)[i];
    __syncthreads();
    for (int t = 1; t < 64; t++) {
        float* cur = base + t * (NS * DD);
        u64 acc[8] = {0, 0, 0, 0, 0, 0, 0, 0};
        for (int d4 = 0; d4 < 32; d4++) {
            const ulonglong2 w = pWt[d4 * DD + j];
            #pragma unroll
            for (int r = 0; r < 8; r++) {
                const ulonglong2 s = *(const ulonglong2*)&s_prev[(gg * 8 + r) * DD + 4 * d4];
                acc[r] = fma2(s.x, w.x, acc[r]);
                acc[r] = fma2(s.y, w.y, acc[r]);
            }
        }
        __syncthreads();
        #pragma unroll
        for (int r = 0; r < 8; r++) {
            const float v = 0.7f * cur[(gg * 8 + r) * DD + j] + 0.3f * tanha(sum2(acc[r]));
            cur[(gg * 8 + r) * DD + j] = v;
            s_prev[(gg * 8 + r) * DD + j] = v;
        }
        __syncthreads();
    }
}

// ---------------------------------------------------------------------------
extern "C" void kernel_launch(void* const* d_in, const int* in_sizes, int n_in,
                              void* d_out, int out_size)
{
    const float* obs   = (const float*)d_in[0];
    const float* eW1   = (const float*)d_in[1];
    const float* eb1   = (const float*)d_in[2];
    const float* eW2   = (const float*)d_in[3];
    const float* eb2   = (const float*)d_in[4];
    const float* skipW = (const float*)d_in[5];
    const float* smu   = (const float*)d_in[6];
    const float* Wk    = (const float*)d_in[7];
    const float* Wv    = (const float*)d_in[8];
    const float* Wq    = (const float*)d_in[9];
    const float* gWih  = (const float*)d_in[10];
    const float* gWhh  = (const float*)d_in[11];
    const float* gbih  = (const float*)d_in[12];
    const float* gbhh  = (const float*)d_in[13];
    const float* mW1   = (const float*)d_in[14];
    const float* mb1   = (const float*)d_in[15];
    const float* mW2   = (const float*)d_in[16];
    const float* mb2   = (const float*)d_in[17];
    const float* lin_g = (const float*)d_in[18];
    const float* lin_b = (const float*)d_in[19];
    const float* lsl_g = (const float*)d_in[20];
    const float* lsl_b = (const float*)d_in[21];
    const float* lml_g = (const float*)d_in[22];
    const float* lml_b = (const float*)d_in[23];
    const float* Wt    = (const float*)d_in[24];
    float* out = (float*)d_out;

    static int init_done = 0;
    if (!init_done) {
        cudaFuncSetAttribute(slot_mma, cudaFuncAttributeMaxDynamicSharedMemorySize, SMEM_DYN);
        init_done = 1;
    }

    pack_all<<<(270336 + 255) / 256, 256>>>(eW1, eW2, skipW, Wk, Wv, Wq,
                                            gWih, gWhh, mW1, mW2, Wt);
    enc_kernel<<<BT / 8, 256>>>(obs, eb1, eb2);
    prolog_kernel<<<BT / 2, 256>>>(lin_g, lin_b);
    slot_mma<<<BT / 8, 256, SMEM_DYN>>>(smu, gbih, gbhh, mb1, mb2,
                                        lsl_g, lsl_b, lml_g, lml_b, out);
    temporal_kernel<<<256, 256>>>(out);
}

// round 14
// speedup vs baseline: 4.2156x; 1.0148x over previous
#include <cuda_runtime.h>
#include <cuda_bf16.h>
#include <stdint.h>
#include <math.h>

#define BT 16384
#define DOBS 512
#define DD 128
#define NS 16
#define HH 256

typedef unsigned long long u64;
typedef unsigned int u32;
typedef unsigned short u16;

__device__ __forceinline__ u64 fma2(u64 a, u64 b, u64 c) {
    u64 d;
    asm("fma.rn.f32x2 %0, %1, %2, %3;" : "=l"(d) : "l"(a), "l"(b), "l"(c));
    return d;
}
__device__ __forceinline__ float sum2(u64 a) {
    float2 f = *(float2*)&a;
    return f.x + f.y;
}
__device__ __forceinline__ u64 pack2(float lo, float hi) {
    u64 r;
    asm("mov.b64 %0, {%1, %2};" : "=l"(r) : "f"(lo), "f"(hi));
    return r;
}
__device__ __forceinline__ float tanha(float x) {
    float y;
    asm("tanh.approx.f32 %0, %1;" : "=f"(y) : "f"(x));
    return y;
}
__device__ __forceinline__ float sigm(float x) { return 0.5f * tanha(0.5f * x) + 0.5f; }

__device__ __forceinline__ u32 split_pair(float v0, float v1, u32& lo_out) {
    __nv_bfloat16 h0 = __float2bfloat16(v0), h1 = __float2bfloat16(v1);
    __nv_bfloat16 l0 = __float2bfloat16(v0 - __bfloat162float(h0));
    __nv_bfloat16 l1 = __float2bfloat16(v1 - __bfloat162float(h1));
    lo_out = (u32)__bfloat16_as_ushort(l0) | ((u32)__bfloat16_as_ushort(l1) << 16);
    return (u32)__bfloat16_as_ushort(h0) | ((u32)__bfloat16_as_ushort(h1) << 16);
}
__device__ __forceinline__ float2 unsplit(u32 hi, u32 lo) {
    float2 r;
    r.x = __bfloat162float(__ushort_as_bfloat16((u16)(hi & 0xffff)))
        + __bfloat162float(__ushort_as_bfloat16((u16)(lo & 0xffff)));
    r.y = __bfloat162float(__ushort_as_bfloat16((u16)(hi >> 16)))
        + __bfloat162float(__ushort_as_bfloat16((u16)(lo >> 16)));
    return r;
}

// ---------------- mma / ldmatrix / cp.async helpers ----------------
__device__ __forceinline__ u32 smem_u32(const void* p) {
    u32 a;
    asm("{ .reg .u64 t; cvta.to.shared.u64 t, %1; cvt.u32.u64 %0, t; }" : "=r"(a) : "l"(p));
    return a;
}
__device__ __forceinline__ void mma_bf16(float* d, u32 a0, u32 a1, u32 a2, u32 a3,
                                         u32 b0, u32 b1) {
    asm volatile(
        "mma.sync.aligned.m16n8k16.row.col.f32.bf16.bf16.f32 "
        "{%0,%1,%2,%3}, {%4,%5,%6,%7}, {%8,%9}, {%0,%1,%2,%3};"
        : "+f"(d[0]), "+f"(d[1]), "+f"(d[2]), "+f"(d[3])
        : "r"(a0), "r"(a1), "r"(a2), "r"(a3), "r"(b0), "r"(b1));
}
__device__ __forceinline__ void cp16(u32 saddr, const void* g) {
    asm volatile("cp.async.cg.shared.global [%0], [%1], 16;" :: "r"(saddr), "l"(g));
}
#define CP_COMMIT() asm volatile("cp.async.commit_group;" ::: "memory")
#define CP_WAIT1()  asm volatile("cp.async.wait_group 1;" ::: "memory")

// One B block (k=128, n=64, row stride 144B). A fragments from registers.
template<bool DUAL>
__device__ __forceinline__ void gemm_blk2(const u32* Ah, const u32* Al, u32 bAd, float* acc) {
    #pragma unroll
    for (int k = 0; k < 8; k++) {
        #pragma unroll
        for (int q = 0; q < 4; q++) {
            u32 b0, b1, b2, b3;
            asm volatile("ldmatrix.sync.aligned.m8n8.x4.trans.shared.b16 {%0,%1,%2,%3}, [%4];"
                : "=r"(b0), "=r"(b1), "=r"(b2), "=r"(b3) : "r"(bAd + (u32)(k * 2304 + q * 32)));
            mma_bf16(acc + (q * 2) * 4,     Ah[k * 4], Ah[k * 4 + 1], Ah[k * 4 + 2], Ah[k * 4 + 3], b0, b1);
            mma_bf16(acc + (q * 2 + 1) * 4, Ah[k * 4], Ah[k * 4 + 1], Ah[k * 4 + 2], Ah[k * 4 + 3], b2, b3);
            if (DUAL) {
                mma_bf16(acc + (q * 2) * 4,     Al[k * 4], Al[k * 4 + 1], Al[k * 4 + 2], Al[k * 4 + 3], b0, b1);
                mma_bf16(acc + (q * 2 + 1) * 4, Al[k * 4], Al[k * 4 + 1], Al[k * 4 + 2], Al[k * 4 + 3], b2, b3);
            }
        }
    }
}

// ---------------- device scratch ----------------
__device__ float g_z[BT * DD];
__device__ float g_wqk[BT * DD];
__device__ float g_vwih[BT * 384];

__device__ ulonglong2 pW1[128 * 256];
__device__ ulonglong2 pW2[64 * 128];
__device__ ulonglong2 pSkip[128 * 128];
__device__ ulonglong2 pWk[32 * 128];
__device__ ulonglong2 pWv[32 * 128];
__device__ ulonglong2 pWqT[32 * 128];
__device__ ulonglong2 pWih[32 * 384];
__device__ ulonglong2 pWt[32 * 128];

// 20 uniform B blocks, each [k=128][n=72] bf16 = 18432 B.
__device__ u16 gBall[20 * 9216];
// Wt B blocks (same format): [h0_hi, h0_lo, h1_hi, h1_lo]
__device__ u16 gWtB[4 * 9216];

// ---------------- pack ----------------
__device__ __forceinline__ void pack_elem(const float* __restrict__ s0, ulonglong2* __restrict__ dst, int C, int idx) {
    int c = idx % C, k4 = idx / C;
    const float* s = s0 + (4 * k4) * C + c;
    ulonglong2 v;
    v.x = pack2(s[0], s[C]);
    v.y = pack2(s[2 * C], s[3 * C]);
    dst[idx] = v;
}
__device__ __forceinline__ void packT_elem(const float* __restrict__ s0, ulonglong2* __restrict__ dst, int K, int C4, int idx) {
    int i = idx % K, j4 = idx / K;
    const float* s = s0 + i * (C4 * 4) + 4 * j4;
    ulonglong2 v;
    v.x = pack2(s[0], s[1]);
    v.y = pack2(s[2], s[3]);
    dst[idx] = v;
}
__device__ __forceinline__ u16 bf_hi(float w) {
    return __bfloat16_as_ushort(__float2bfloat16(w));
}
__device__ __forceinline__ u16 bf_lo(float w) {
    float hf = __bfloat162float(__float2bfloat16(w));
    return __bfloat16_as_ushort(__float2bfloat16(w - hf));
}

__global__ __launch_bounds__(256) void pack_all(
    const float* __restrict__ eW1, const float* __restrict__ eW2, const float* __restrict__ skipW,
    const float* __restrict__ Wk, const float* __restrict__ Wv, const float* __restrict__ Wq,
    const float* __restrict__ gWih, const float* __restrict__ gWhh,
    const float* __restrict__ mW1, const float* __restrict__ mW2, const float* __restrict__ Wt)
{
    int idx = blockIdx.x * 256 + threadIdx.x;
    if (idx < 32768) { pack_elem(eW1, pW1, 256, idx); return; }   idx -= 32768;
    if (idx < 8192)  { pack_elem(eW2, pW2, 128, idx); return; }   idx -= 8192;
    if (idx < 16384) { pack_elem(skipW, pSkip, 128, idx); return; } idx -= 16384;
    if (idx < 4096)  { pack_elem(Wk, pWk, 128, idx); return; }    idx -= 4096;
    if (idx < 4096)  { pack_elem(Wv, pWv, 128, idx); return; }    idx -= 4096;
    if (idx < 4096)  { packT_elem(Wq, pWqT, 128, 32, idx); return; } idx -= 4096;
    if (idx < 12288) { pack_elem(gWih, pWih, 384, idx); return; } idx -= 12288;
    if (idx < 4096)  { pack_elem(Wt, pWt, 128, idx); return; }    idx -= 4096;
    if (idx < 184320) {
        const int b = idx / 9216, r = idx % 9216;
        const int k = r / 72, n = r % 72;
        float w = 0.f;
        int s;
        if (b < 12) {
            const int half = b / 6, rem = b % 6, g = rem >> 1;
            s = rem & 1;
            if (n < 64) w = gWhh[k * 384 + g * 128 + half * 64 + n];
        } else {
            const int bb = b - 12, m = bb >> 2, half = (bb >> 1) & 1;
            s = bb & 1;
            if (n < 64) w = (m ? mW2 : mW1)[k * 128 + half * 64 + n];
        }
        gBall[idx] = s ? bf_lo(w) : bf_hi(w);
        return;
    }
    idx -= 184320;
    if (idx < 36864) {
        const int b = idx / 9216, r = idx % 9216;
        const int half = b >> 1, s = b & 1;
        const int k = r / 72, n = r % 72;
        float w = (n < 64) ? Wt[k * 128 + half * 64 + n] : 0.f;
        gWtB[idx] = s ? bf_lo(w) : bf_hi(w);
    }
}

// ---------------------------------------------------------------------------
// Kernel 1: encoder (proven)
// ---------------------------------------------------------------------------
__global__ __launch_bounds__(256) void enc_kernel(
    const float* __restrict__ obs, const float* __restrict__ b1, const float* __restrict__ b2)
{
    __shared__ __align__(16) float s_obs[8 * DOBS];
    __shared__ __align__(16) float s_h[8 * HH];
    __shared__ __align__(16) float s_p1[8 * DD];
    const int tid = threadIdx.x;
    const long e0 = (long)blockIdx.x * 8;
    const float* op = obs + e0 * DOBS;
    for (int i = tid; i < 8 * DOBS / 4; i += 256)
        ((float4*)s_obs)[i] = ((const float4*)op)[i];
    __syncthreads();
    {
        const int j = tid;
        u64 acc[8] = {0, 0, 0, 0, 0, 0, 0, 0};
        for (int d4 = 0; d4 < 128; d4++) {
            const ulonglong2 w = pW1[d4 * HH + j];
            #pragma unroll
            for (int r = 0; r < 8; r++) {
                const ulonglong2 s = *(const ulonglong2*)&s_obs[r * DOBS + 4 * d4];
                acc[r] = fma2(s.x, w.x, acc[r]);
                acc[r] = fma2(s.y, w.y, acc[r]);
            }
        }
        const float bj = b1[j];
        #pragma unroll
        for (int r = 0; r < 8; r++) {
            const float a = sum2(acc[r]) + bj;
            s_h[r * HH + j] = 0.5f * a * (1.f + erff(a * 0.70710678118654752f));
        }
    }
    __syncthreads();
    const int j = tid & 127;
    const int half = tid >> 7;
    u64 acc[8] = {0, 0, 0, 0, 0, 0, 0, 0};
    if (half == 0) {
        for (int d4 = 0; d4 < 64; d4++) {
            const ulonglong2 w = pW2[d4 * DD + j];
            #pragma unroll
            for (int r = 0; r < 8; r++) {
                const ulonglong2 s = *(const ulonglong2*)&s_h[r * HH + 4 * d4];
                acc[r] = fma2(s.x, w.x, acc[r]);
                acc[r] = fma2(s.y, w.y, acc[r]);
            }
        }
        for (int d4 = 0; d4 < 32; d4++) {
            const ulonglong2 w = pSkip[d4 * DD + j];
            #pragma unroll
            for (int r = 0; r < 8; r++) {
                const ulonglong2 s = *(const ulonglong2*)&s_obs[r * DOBS + 4 * d4];
                acc[r] = fma2(s.x, w.x, acc[r]);
                acc[r] = fma2(s.y, w.y, acc[r]);
            }
        }
    } else {
        for (int d4 = 32; d4 < 128; d4++) {
            const ulonglong2 w = pSkip[d4 * DD + j];
            #pragma unroll
            for (int r = 0; r < 8; r++) {
                const ulonglong2 s = *(const ulonglong2*)&s_obs[r * DOBS + 4 * d4];
                acc[r] = fma2(s.x, w.x, acc[r]);
                acc[r] = fma2(s.y, w.y, acc[r]);
            }
        }
        #pragma unroll
        for (int r = 0; r < 8; r++) s_p1[r * DD + j] = sum2(acc[r]);
    }
    __syncthreads();
    if (half == 0) {
        const float bj = b2[j];
        #pragma unroll
        for (int r = 0; r < 8; r++)
            g_z[(e0 + r) * DD + j] = tanha(sum2(acc[r]) + s_p1[r * DD + j] + bj);
    }
}

// ---------------------------------------------------------------------------
// Kernel 2: prologue (proven)
// ---------------------------------------------------------------------------
__global__ __launch_bounds__(256) void prolog_kernel(
    const float* __restrict__ lin_g, const float* __restrict__ lin_b)
{
    __shared__ __align__(16) float inp[2][DD], kk[2][DD], vv[2][DD];
    __shared__ float red[2][12];
    const int tid = threadIdx.x, lane = tid & 31, warp = tid >> 5;
    const int el = tid >> 7, j = tid & 127;
    const long ent = (long)blockIdx.x * 2 + el;
    const float zv = g_z[ent * DD + j];
    {
        float s1 = zv, s2 = zv * zv;
        #pragma unroll
        for (int off = 16; off > 0; off >>= 1) {
            s1 += __shfl_down_sync(0xffffffffu, s1, off);
            s2 += __shfl_down_sync(0xffffffffu, s2, off);
        }
        if (lane == 0) { red[el][warp & 3] = s1; red[el][4 + (warp & 3)] = s2; }
    }
    __syncthreads();
    if (j == 0) {
        float s = red[el][0] + red[el][1] + red[el][2] + red[el][3];
        float q = red[el][4] + red[el][5] + red[el][6] + red[el][7];
        const float mu = s * (1.f / 128.f);
        red[el][8] = mu;
        red[el][9] = rsqrtf(q * (1.f / 128.f) - mu * mu + 1e-5f);
    }
    __syncthreads();
    inp[el][j] = (zv - red[el][8]) * red[el][9] * lin_g[j] + lin_b[j];
    __syncthreads();
    u64 acc = 0;
    for (int d4 = 0; d4 < 32; d4++) {
        const ulonglong2 s = *(const ulonglong2*)&inp[el][4 * d4];
        const ulonglong2 w = pWk[d4 * DD + j];
        acc = fma2(s.x, w.x, acc);
        acc = fma2(s.y, w.y, acc);
    }
    kk[el][j] = sum2(acc);
    acc = 0;
    for (int d4 = 0; d4 < 32; d4++) {
        const ulonglong2 s = *(const ulonglong2*)&inp[el][4 * d4];
        const ulonglong2 w = pWv[d4 * DD + j];
        acc = fma2(s.x, w.x, acc);
        acc = fma2(s.y, w.y, acc);
    }
    vv[el][j] = sum2(acc);
    __syncthreads();
    acc = 0;
    for (int j4 = 0; j4 < 32; j4++) {
        const ulonglong2 s = *(const ulonglong2*)&kk[el][4 * j4];
        const ulonglong2 w = pWqT[j4 * DD + j];
        acc = fma2(s.x, w.x, acc);
        acc = fma2(s.y, w.y, acc);
    }
    g_wqk[ent * DD + j] = sum2(acc);
    #pragma unroll
    for (int pp = 0; pp < 3; pp++) {
        const int c = j + 128 * pp;
        u64 a2 = 0;
        for (int d4 = 0; d4 < 32; d4++) {
            const ulonglong2 s = *(const ulonglong2*)&vv[el][4 * d4];
            const ulonglong2 w = pWih[d4 * 384 + c];
            a2 = fma2(s.x, w.x, a2);
            a2 = fma2(s.y, w.y, a2);
        }
        g_vwih[ent * 384 + c] = sum2(a2);
    }
}

// ---------------------------------------------------------------------------
// Kernel 3: register-resident mma.sync slot attention (proven R13)
// ---------------------------------------------------------------------------
#define SMEM_DYN 77824

__global__ __launch_bounds__(256) void slot_mma(
    const float* __restrict__ slot_mu,
    const float* __restrict__ bih, const float* __restrict__ bhh,
    const float* __restrict__ mb1, const float* __restrict__ mb2,
    const float* __restrict__ lsl_g, const float* __restrict__ lsl_b,
    const float* __restrict__ lml_g, const float* __restrict__ lml_b,
    float* __restrict__ out)
{
    extern __shared__ __align__(16) char dyn[];
    float* sWqk  = (float*)(dyn + 55296);
    float* sVwih = (float*)(dyn + 59392);
    float* sPar  = (float*)(dyn + 71680);

    const int tid = threadIdx.x, lane = tid & 31, warp = tid >> 5;
    const int e = warp;
    const int lq = lane >> 2, lc = (lane & 3) * 2;
    const long blk = blockIdx.x;
    const float invscale = 0.088388347648318447f;
    const u32 ring = smem_u32(dyn);

    // prefetch B blocks 0, 1
    {
        const char* s0 = (const char*)gBall;
        for (int i = tid; i < 1152; i += 256) cp16(ring + (u32)i * 16, s0 + i * 16);
        CP_COMMIT();
        const char* s1 = (const char*)gBall + 18432;
        for (int i = tid; i < 1152; i += 256) cp16(ring + 18432u + (u32)i * 16, s1 + i * 16);
        CP_COMMIT();
    }

    for (int i = tid; i < 384; i += 256) { sPar[i] = bih[i]; sPar[384 + i] = bhh[i]; }
    if (tid < 128) {
        sPar[768 + tid] = mb1[tid];  sPar[896 + tid] = mb2[tid];
        sPar[1024 + tid] = lsl_g[tid]; sPar[1152 + tid] = lsl_b[tid];
        sPar[1280 + tid] = lml_g[tid]; sPar[1408 + tid] = lml_b[tid];
    }
    for (int i = tid; i < 8 * 384; i += 256) sVwih[i] = g_vwih[blk * (8 * 384) + i];
    for (int i = tid; i < 8 * 128; i += 256) sWqk[i] = g_wqk[blk * (8 * 128) + i];

    float sl[64];
    #pragma unroll
    for (int i2 = 0; i2 < 16; i2++)
        #pragma unroll
        for (int p2 = 0; p2 < 2; p2++) {
            const float* src = slot_mu + (lq + 8 * p2) * DD + 8 * i2 + lc;
            sl[i2 * 4 + p2 * 2 + 0] = src[0];
            sl[i2 * 4 + p2 * 2 + 1] = src[1];
        }

    __syncthreads();   // sPar/sVwih/sWqk visible before first use

    const u32 bLane = (u32)((lane & 15) * 144 + ((lane >> 4) & 1) * 16);
    int fb = 2, fs = 2, cs = 0;

#define PHASE(DUALF, AHP, ALP, ACC) do { \
    CP_WAIT1(); \
    __syncthreads(); \
    { const char* _s = (const char*)gBall + fb * 18432; \
      u32 _d = ring + (u32)fs * 18432u; \
      for (int _i = tid; _i < 1152; _i += 256) cp16(_d + (u32)_i * 16, _s + _i * 16); \
      CP_COMMIT(); \
      fb++; if (fb == 20) fb = 0; \
      fs++; if (fs == 3) fs = 0; } \
    gemm_blk2<DUALF>(AHP, ALP, ring + (u32)cs * 18432u + bLane, ACC); \
    cs++; if (cs == 3) cs = 0; \
} while (0)

    u32 Ah[32], Al[32];

    for (int it = 0; it < 3; it++) {
        float mu_[2], rs_[2];
        #pragma unroll
        for (int p2 = 0; p2 < 2; p2++) {
            float s = 0.f, q = 0.f;
            #pragma unroll
            for (int i2 = 0; i2 < 16; i2++) {
                const float v0 = sl[i2 * 4 + p2 * 2], v1 = sl[i2 * 4 + p2 * 2 + 1];
                s += v0 + v1;  q += v0 * v0 + v1 * v1;
            }
            s += __shfl_xor_sync(0xffffffffu, s, 1);
            s += __shfl_xor_sync(0xffffffffu, s, 2);
            q += __shfl_xor_sync(0xffffffffu, q, 1);
            q += __shfl_xor_sync(0xffffffffu, q, 2);
            mu_[p2] = s * (1.f / 128.f);
            rs_[p2] = rsqrtf(q * (1.f / 128.f) - mu_[p2] * mu_[p2] + 1e-5f);
        }
        float pd0 = 0.f, pd1 = 0.f;
        #pragma unroll
        for (int i2 = 0; i2 < 16; i2++) {
            const int j0 = 8 * i2 + lc;
            const float g0 = sPar[1024 + j0], g1 = sPar[1024 + j0 + 1];
            const float bb0 = sPar[1152 + j0], bb1 = sPar[1152 + j0 + 1];
            const float w0 = sWqk[e * 128 + j0], w1 = sWqk[e * 128 + j0 + 1];
            pd0 += ((sl[i2 * 4 + 0] - mu_[0]) * rs_[0] * g0 + bb0) * w0
                 + ((sl[i2 * 4 + 1] - mu_[0]) * rs_[0] * g1 + bb1) * w1;
            pd1 += ((sl[i2 * 4 + 2] - mu_[1]) * rs_[1] * g0 + bb0) * w0
                 + ((sl[i2 * 4 + 3] - mu_[1]) * rs_[1] * g1 + bb1) * w1;
        }
        pd0 += __shfl_xor_sync(0xffffffffu, pd0, 1);
        pd0 += __shfl_xor_sync(0xffffffffu, pd0, 2);
        pd1 += __shfl_xor_sync(0xffffffffu, pd1, 1);
        pd1 += __shfl_xor_sync(0xffffffffu, pd1, 2);
        const float l0 = pd0 * invscale, l1 = pd1 * invscale;
        float m = fmaxf(l0, l1);
        m = fmaxf(m, __shfl_xor_sync(0xffffffffu, m, 4));
        m = fmaxf(m, __shfl_xor_sync(0xffffffffu, m, 8));
        m = fmaxf(m, __shfl_xor_sync(0xffffffffu, m, 16));
        const float ex0 = __expf(l0 - m), ex1 = __expf(l1 - m);
        float ssum = ex0 + ex1;
        ssum += __shfl_xor_sync(0xffffffffu, ssum, 4);
        ssum += __shfl_xor_sync(0xffffffffu, ssum, 8);
        ssum += __shfl_xor_sync(0xffffffffu, ssum, 16);
        const float a0 = ex0 / ssum, a1 = ex1 / ssum;

        #pragma unroll
        for (int t = 0; t < 32; t++)
            Ah[t] = split_pair(sl[2 * t], sl[2 * t + 1], Al[t]);

        float nv0[32];
        #pragma unroll
        for (int h = 0; h < 2; h++) {
            float aR[32], aZ[32], aN[32];
            #pragma unroll
            for (int i = 0; i < 32; i++) { aR[i] = 0.f; aZ[i] = 0.f; aN[i] = 0.f; }
            PHASE(true, Ah, Al, aR);  PHASE(false, Ah, Al, aR);
            PHASE(true, Ah, Al, aZ);  PHASE(false, Ah, Al, aZ);
            PHASE(true, Ah, Al, aN);  PHASE(false, Ah, Al, aN);

            const int cb = 64 * h;
            #pragma unroll
            for (int tl = 0; tl < 16; tl++) {
                const int n = tl >> 1, p2 = tl & 1;
                const int j0 = cb + 8 * n + lc;
                const int tg = 16 * h + tl;
                const float2 hv = unsplit(Ah[tg], Al[tg]);
                const float af = p2 ? a1 : a0;
                #pragma unroll
                for (int c = 0; c < 2; c++) {
                    const int j = j0 + c;
                    const float gr = aR[2 * tl + c] + sPar[384 + j];
                    const float gz = aZ[2 * tl + c] + sPar[512 + j];
                    const float gn = aN[2 * tl + c] + sPar[640 + j];
                    const float rr = sigm(af * sVwih[e * 384 + j] + sPar[j] + gr);
                    const float zz = sigm(af * sVwih[e * 384 + 128 + j] + sPar[128 + j] + gz);
                    const float nn = tanha(af * sVwih[e * 384 + 256 + j] + sPar[256 + j] + rr * gn);
                    const float hh = c ? hv.y : hv.x;
                    const float nv = (1.f - zz) * nn + zz * hh;
                    if (h == 0) nv0[2 * tl + c] = nv;
                    else        sl[32 + 2 * tl + c] = nv;
                }
            }
        }
        #pragma unroll
        for (int t = 0; t < 32; t++) sl[t] = nv0[t];

        #pragma unroll
        for (int p2 = 0; p2 < 2; p2++) {
            float s = 0.f, q = 0.f;
            #pragma unroll
            for (int i2 = 0; i2 < 16; i2++) {
                const float v0 = sl[i2 * 4 + p2 * 2], v1 = sl[i2 * 4 + p2 * 2 + 1];
                s += v0 + v1;  q += v0 * v0 + v1 * v1;
            }
            s += __shfl_xor_sync(0xffffffffu, s, 1);
            s += __shfl_xor_sync(0xffffffffu, s, 2);
            q += __shfl_xor_sync(0xffffffffu, q, 1);
            q += __shfl_xor_sync(0xffffffffu, q, 2);
            mu_[p2] = s * (1.f / 128.f);
            rs_[p2] = rsqrtf(q * (1.f / 128.f) - mu_[p2] * mu_[p2] + 1e-5f);
        }
        #pragma unroll
        for (int t = 0; t < 32; t++) {
            const int i2 = t >> 1, p2 = t & 1;
            const int j0 = 8 * i2 + lc;
            const float v0 = (sl[2 * t] - mu_[p2]) * rs_[p2] * sPar[1280 + j0] + sPar[1408 + j0];
            const float v1 = (sl[2 * t + 1] - mu_[p2]) * rs_[p2] * sPar[1280 + j0 + 1] + sPar[1408 + j0 + 1];
            Ah[t] = split_pair(v0, v1, Al[t]);
        }

        float accM[64];
        #pragma unroll
        for (int i = 0; i < 64; i++) accM[i] = 0.f;
        PHASE(true, Ah, Al, accM);       PHASE(false, Ah, Al, accM);
        PHASE(true, Ah, Al, accM + 32);  PHASE(false, Ah, Al, accM + 32);

        #pragma unroll
        for (int t = 0; t < 32; t++) {
            const int i2 = t >> 1;
            const int j0 = 8 * i2 + lc;
            const float v0 = fmaxf(accM[2 * t] + sPar[768 + j0], 0.f);
            const float v1 = fmaxf(accM[2 * t + 1] + sPar[768 + j0 + 1], 0.f);
            Ah[t] = split_pair(v0, v1, Al[t]);
        }

        #pragma unroll
        for (int i = 0; i < 64; i++) accM[i] = 0.f;
        PHASE(true, Ah, Al, accM);       PHASE(false, Ah, Al, accM);
        PHASE(true, Ah, Al, accM + 32);  PHASE(false, Ah, Al, accM + 32);

        #pragma unroll
        for (int t = 0; t < 32; t++) {
            const int i2 = t >> 1;
            const int j0 = 8 * i2 + lc;
            sl[2 * t]     += accM[2 * t] + sPar[896 + j0];
            sl[2 * t + 1] += accM[2 * t + 1] + sPar[896 + j0 + 1];
        }
    }

    #pragma unroll
    for (int p2 = 0; p2 < 2; p2++) {
        float q = 0.f;
        #pragma unroll
        for (int i2 = 0; i2 < 16; i2++) {
            const float v0 = sl[i2 * 4 + p2 * 2], v1 = sl[i2 * 4 + p2 * 2 + 1];
            q += v0 * v0 + v1 * v1;
        }
        q += __shfl_xor_sync(0xffffffffu, q, 1);
        q += __shfl_xor_sync(0xffffffffu, q, 2);
        const float inv = 1.f / fmaxf(sqrtf(q), 1e-8f);
        float* dst = out + (blk * 8 + e) * (NS * DD) + (lq + 8 * p2) * DD;
        #pragma unroll
        for (int i2 = 0; i2 < 16; i2++) {
            float2 v;
            v.x = sl[i2 * 4 + p2 * 2] * inv;
            v.y = sl[i2 * 4 + p2 * 2 + 1] * inv;
            *(float2*)(dst + 8 * i2 + lc) = v;
        }
    }
#undef PHASE
}

// ---------------------------------------------------------------------------
// Kernel 4: temporal blend via mma.sync — warp b owns batch b's whole chain
// in registers. 32 CTAs x 8 warps; Wt B-blocks persistent in smem.
// ---------------------------------------------------------------------------
#define TSMEM 73728

__global__ __launch_bounds__(256) void temporal_mma(float* __restrict__ out)
{
    extern __shared__ __align__(16) char tdyn[];
    const int tid = threadIdx.x, lane = tid & 31, warp = tid >> 5;
    const long b = (long)blockIdx.x * 8 + warp;
    const int lq = lane >> 2, lc = (lane & 3) * 2;

    // load Wt B blocks once (73728 B)
    for (int i = tid; i < 4608; i += 256)
        ((uint4*)tdyn)[i] = ((const uint4*)gWtB)[i];
    __syncthreads();
    const u32 base = smem_u32(tdyn);
    const u32 bLane = (u32)((lane & 15) * 144 + ((lane >> 4) & 1) * 16);

    float* b0 = out + b * 64 * (NS * DD);

    // load t=0 slots into fragment-layout registers
    float sl[64];
    #pragma unroll
    for (int i2 = 0; i2 < 16; i2++)
        #pragma unroll
        for (int p2 = 0; p2 < 2; p2++) {
            const float2 v = *(const float2*)(b0 + (lq + 8 * p2) * DD + 8 * i2 + lc);
            sl[i2 * 4 + p2 * 2 + 0] = v.x;
            sl[i2 * 4 + p2 * 2 + 1] = v.y;
        }

    u32 Ah[32], Al[32];
    for (int t = 1; t < 64; t++) {
        #pragma unroll
        for (int q = 0; q < 32; q++)
            Ah[q] = split_pair(sl[2 * q], sl[2 * q + 1], Al[q]);

        float acc[64];
        #pragma unroll
        for (int i = 0; i < 64; i++) acc[i] = 0.f;
        gemm_blk2<true >(Ah, Al, base + 0u * 18432u + bLane, acc);
        gemm_blk2<false>(Ah, Al, base + 1u * 18432u + bLane, acc);
        gemm_blk2<true >(Ah, Al, base + 2u * 18432u + bLane, acc + 32);
        gemm_blk2<false>(Ah, Al, base + 3u * 18432u + bLane, acc + 32);

        float* cur = b0 + t * (NS * DD);
        #pragma unroll
        for (int q = 0; q < 32; q++) {
            const int i2 = q >> 1, p2 = q & 1;
            float* p = cur + (lq + 8 * p2) * DD + 8 * i2 + lc;
            const float2 c = *(const float2*)p;
            float2 v;
            v.x = 0.7f * c.x + 0.3f * tanha(acc[2 * q]);
            v.y = 0.7f * c.y + 0.3f * tanha(acc[2 * q + 1]);
            *(float2*)p = v;
            sl[2 * q] = v.x;
            sl[2 * q + 1] = v.y;
        }
    }
}

// ---------------------------------------------------------------------------
extern "C" void kernel_launch(void* const* d_in, const int* in_sizes, int n_in,
                              void* d_out, int out_size)
{
    const float* obs   = (const float*)d_in[0];
    const float* eW1   = (const float*)d_in[1];
    const float* eb1   = (const float*)d_in[2];
    const float* eW2   = (const float*)d_in[3];
    const float* eb2   = (const float*)d_in[4];
    const float* skipW = (const float*)d_in[5];
    const float* smu   = (const float*)d_in[6];
    const float* Wk    = (const float*)d_in[7];
    const float* Wv    = (const float*)d_in[8];
    const float* Wq    = (const float*)d_in[9];
    const float* gWih  = (const float*)d_in[10];
    const float* gWhh  = (const float*)d_in[11];
    const float* gbih  = (const float*)d_in[12];
    const float* gbhh  = (const float*)d_in[13];
    const float* mW1   = (const float*)d_in[14];
    const float* mb1   = (const float*)d_in[15];
    const float* mW2   = (const float*)d_in[16];
    const float* mb2   = (const float*)d_in[17];
    const float* lin_g = (const float*)d_in[18];
    const float* lin_b = (const float*)d_in[19];
    const float* lsl_g = (const float*)d_in[20];
    const float* lsl_b = (const float*)d_in[21];
    const float* lml_g = (const float*)d_in[22];
    const float* lml_b = (const float*)d_in[23];
    const float* Wt    = (const float*)d_in[24];
    float* out = (float*)d_out;

    static int init_done = 0;
    if (!init_done) {
        cudaFuncSetAttribute(slot_mma, cudaFuncAttributeMaxDynamicSharedMemorySize, SMEM_DYN);
        cudaFuncSetAttribute(temporal_mma, cudaFuncAttributeMaxDynamicSharedMemorySize, TSMEM);
        init_done = 1;
    }

    pack_all<<<(307200 + 255) / 256, 256>>>(eW1, eW2, skipW, Wk, Wv, Wq,
                                            gWih, gWhh, mW1, mW2, Wt);
    enc_kernel<<<BT / 8, 256>>>(obs, eb1, eb2);
    prolog_kernel<<<BT / 2, 256>>>(lin_g, lin_b);
    slot_mma<<<BT / 8, 256, SMEM_DYN>>>(smu, gbih, gbhh, mb1, mb2,
                                        lsl_g, lsl_b, lml_g, lml_b, out);
    temporal_mma<<<32, 256, TSMEM>>>(out);
}

// round 15
// speedup vs baseline: 4.5912x; 1.0891x over previous
#include <cuda_runtime.h>
#include <cuda_bf16.h>
#include <stdint.h>
#include <math.h>

#define BT 16384
#define DOBS 512
#define DD 128
#define NS 16
#define HH 256

typedef unsigned long long u64;
typedef unsigned int u32;
typedef unsigned short u16;

__device__ __forceinline__ u64 fma2(u64 a, u64 b, u64 c) {
    u64 d;
    asm("fma.rn.f32x2 %0, %1, %2, %3;" : "=l"(d) : "l"(a), "l"(b), "l"(c));
    return d;
}
__device__ __forceinline__ float sum2(u64 a) {
    float2 f = *(float2*)&a;
    return f.x + f.y;
}
__device__ __forceinline__ u64 pack2(float lo, float hi) {
    u64 r;
    asm("mov.b64 %0, {%1, %2};" : "=l"(r) : "f"(lo), "f"(hi));
    return r;
}
__device__ __forceinline__ float tanha(float x) {
    float y;
    asm("tanh.approx.f32 %0, %1;" : "=f"(y) : "f"(x));
    return y;
}
__device__ __forceinline__ float sigm(float x) { return 0.5f * tanha(0.5f * x) + 0.5f; }

// fast split: hi = truncated top-16 bits (PRMT pack), lo = exact residual (RN bf16x2)
__device__ __forceinline__ u32 split_pair(float v0, float v1, u32& lo_out) {
    const u32 b0 = __float_as_uint(v0), b1 = __float_as_uint(v1);
    u32 hi;
    asm("prmt.b32 %0, %1, %2, 0x7632;" : "=r"(hi) : "r"(b0), "r"(b1));
    const float l0 = v0 - __uint_as_float(b0 & 0xffff0000u);
    const float l1 = v1 - __uint_as_float(b1 & 0xffff0000u);
    asm("cvt.rn.bf16x2.f32 %0, %1, %2;" : "=r"(lo_out) : "f"(l1), "f"(l0));
    return hi;
}
__device__ __forceinline__ float2 unsplit(u32 hi, u32 lo) {
    float2 r;
    r.x = __bfloat162float(__ushort_as_bfloat16((u16)(hi & 0xffff)))
        + __bfloat162float(__ushort_as_bfloat16((u16)(lo & 0xffff)));
    r.y = __bfloat162float(__ushort_as_bfloat16((u16)(hi >> 16)))
        + __bfloat162float(__ushort_as_bfloat16((u16)(lo >> 16)));
    return r;
}

// ---------------- mma / ldmatrix / cp.async helpers ----------------
__device__ __forceinline__ u32 smem_u32(const void* p) {
    u32 a;
    asm("{ .reg .u64 t; cvta.to.shared.u64 t, %1; cvt.u32.u64 %0, t; }" : "=r"(a) : "l"(p));
    return a;
}
__device__ __forceinline__ void mma_bf16(float* d, u32 a0, u32 a1, u32 a2, u32 a3,
                                         u32 b0, u32 b1) {
    asm volatile(
        "mma.sync.aligned.m16n8k16.row.col.f32.bf16.bf16.f32 "
        "{%0,%1,%2,%3}, {%4,%5,%6,%7}, {%8,%9}, {%0,%1,%2,%3};"
        : "+f"(d[0]), "+f"(d[1]), "+f"(d[2]), "+f"(d[3])
        : "r"(a0), "r"(a1), "r"(a2), "r"(a3), "r"(b0), "r"(b1));
}
__device__ __forceinline__ void cp16(u32 saddr, const void* g) {
    asm volatile("cp.async.cg.shared.global [%0], [%1], 16;" :: "r"(saddr), "l"(g));
}
#define CP_COMMIT() asm volatile("cp.async.commit_group;" ::: "memory")
#define CP_WAIT1()  asm volatile("cp.async.wait_group 1;" ::: "memory")

// One B block (k=128, n=64, row stride 144B). A fragments from registers.
template<bool DUAL>
__device__ __forceinline__ void gemm_blk2(const u32* Ah, const u32* Al, u32 bAd, float* acc) {
    #pragma unroll
    for (int k = 0; k < 8; k++) {
        #pragma unroll
        for (int q = 0; q < 4; q++) {
            u32 b0, b1, b2, b3;
            asm volatile("ldmatrix.sync.aligned.m8n8.x4.trans.shared.b16 {%0,%1,%2,%3}, [%4];"
                : "=r"(b0), "=r"(b1), "=r"(b2), "=r"(b3) : "r"(bAd + (u32)(k * 2304 + q * 32)));
            mma_bf16(acc + (q * 2) * 4,     Ah[k * 4], Ah[k * 4 + 1], Ah[k * 4 + 2], Ah[k * 4 + 3], b0, b1);
            mma_bf16(acc + (q * 2 + 1) * 4, Ah[k * 4], Ah[k * 4 + 1], Ah[k * 4 + 2], Ah[k * 4 + 3], b2, b3);
            if (DUAL) {
                mma_bf16(acc + (q * 2) * 4,     Al[k * 4], Al[k * 4 + 1], Al[k * 4 + 2], Al[k * 4 + 3], b0, b1);
                mma_bf16(acc + (q * 2 + 1) * 4, Al[k * 4], Al[k * 4 + 1], Al[k * 4 + 2], Al[k * 4 + 3], b2, b3);
            }
        }
    }
}

// ---------------- device scratch ----------------
__device__ float g_z[BT * DD];
__device__ float g_wqk[BT * DD];
__device__ float g_vwih[BT * 384];

__device__ ulonglong2 pW1[128 * 256];
__device__ ulonglong2 pW2[64 * 128];
__device__ ulonglong2 pSkip[128 * 128];
__device__ ulonglong2 pWk[32 * 128];
__device__ ulonglong2 pWv[32 * 128];
__device__ ulonglong2 pWqT[32 * 128];
__device__ ulonglong2 pWih[32 * 384];
__device__ ulonglong2 pWt[32 * 128];

// 20 uniform B blocks ([k=128][n=72] bf16 = 18432 B), hi/lo pairs adjacent
// = 10 superblocks of 36864 B.
__device__ u16 gBall[20 * 9216];
// Wt B blocks: [h0_hi, h0_lo, h1_hi, h1_lo]
__device__ u16 gWtB[4 * 9216];

// ---------------- pack ----------------
__device__ __forceinline__ void pack_elem(const float* __restrict__ s0, ulonglong2* __restrict__ dst, int C, int idx) {
    int c = idx % C, k4 = idx / C;
    const float* s = s0 + (4 * k4) * C + c;
    ulonglong2 v;
    v.x = pack2(s[0], s[C]);
    v.y = pack2(s[2 * C], s[3 * C]);
    dst[idx] = v;
}
__device__ __forceinline__ void packT_elem(const float* __restrict__ s0, ulonglong2* __restrict__ dst, int K, int C4, int idx) {
    int i = idx % K, j4 = idx / K;
    const float* s = s0 + i * (C4 * 4) + 4 * j4;
    ulonglong2 v;
    v.x = pack2(s[0], s[1]);
    v.y = pack2(s[2], s[3]);
    dst[idx] = v;
}
__device__ __forceinline__ u16 bf_hi(float w) {
    return (u16)(__float_as_uint(w) >> 16);   // truncated hi (matches split_pair)
}
__device__ __forceinline__ u16 bf_lo(float w) {
    float hf = __uint_as_float(__float_as_uint(w) & 0xffff0000u);
    return __bfloat16_as_ushort(__float2bfloat16(w - hf));
}

__global__ __launch_bounds__(256) void pack_all(
    const float* __restrict__ eW1, const float* __restrict__ eW2, const float* __restrict__ skipW,
    const float* __restrict__ Wk, const float* __restrict__ Wv, const float* __restrict__ Wq,
    const float* __restrict__ gWih, const float* __restrict__ gWhh,
    const float* __restrict__ mW1, const float* __restrict__ mW2, const float* __restrict__ Wt)
{
    int idx = blockIdx.x * 256 + threadIdx.x;
    if (idx < 32768) { pack_elem(eW1, pW1, 256, idx); return; }   idx -= 32768;
    if (idx < 8192)  { pack_elem(eW2, pW2, 128, idx); return; }   idx -= 8192;
    if (idx < 16384) { pack_elem(skipW, pSkip, 128, idx); return; } idx -= 16384;
    if (idx < 4096)  { pack_elem(Wk, pWk, 128, idx); return; }    idx -= 4096;
    if (idx < 4096)  { pack_elem(Wv, pWv, 128, idx); return; }    idx -= 4096;
    if (idx < 4096)  { packT_elem(Wq, pWqT, 128, 32, idx); return; } idx -= 4096;
    if (idx < 12288) { pack_elem(gWih, pWih, 384, idx); return; } idx -= 12288;
    if (idx < 4096)  { pack_elem(Wt, pWt, 128, idx); return; }    idx -= 4096;
    if (idx < 184320) {
        const int b = idx / 9216, r = idx % 9216;
        const int k = r / 72, n = r % 72;
        float w = 0.f;
        int s;
        if (b < 12) {
            const int half = b / 6, rem = b % 6, g = rem >> 1;
            s = rem & 1;
            if (n < 64) w = gWhh[k * 384 + g * 128 + half * 64 + n];
        } else {
            const int bb = b - 12, m = bb >> 2, half = (bb >> 1) & 1;
            s = bb & 1;
            if (n < 64) w = (m ? mW2 : mW1)[k * 128 + half * 64 + n];
        }
        gBall[idx] = s ? bf_lo(w) : bf_hi(w);
        return;
    }
    idx -= 184320;
    if (idx < 36864) {
        const int b = idx / 9216, r = idx % 9216;
        const int half = b >> 1, s = b & 1;
        const int k = r / 72, n = r % 72;
        float w = (n < 64) ? Wt[k * 128 + half * 64 + n] : 0.f;
        gWtB[idx] = s ? bf_lo(w) : bf_hi(w);
    }
}

// ---------------------------------------------------------------------------
// Kernel 1: encoder (proven)
// ---------------------------------------------------------------------------
__global__ __launch_bounds__(256) void enc_kernel(
    const float* __restrict__ obs, const float* __restrict__ b1, const float* __restrict__ b2)
{
    __shared__ __align__(16) float s_obs[8 * DOBS];
    __shared__ __align__(16) float s_h[8 * HH];
    __shared__ __align__(16) float s_p1[8 * DD];
    const int tid = threadIdx.x;
    const long e0 = (long)blockIdx.x * 8;
    const float* op = obs + e0 * DOBS;
    for (int i = tid; i < 8 * DOBS / 4; i += 256)
        ((float4*)s_obs)[i] = ((const float4*)op)[i];
    __syncthreads();
    {
        const int j = tid;
        u64 acc[8] = {0, 0, 0, 0, 0, 0, 0, 0};
        for (int d4 = 0; d4 < 128; d4++) {
            const ulonglong2 w = pW1[d4 * HH + j];
            #pragma unroll
            for (int r = 0; r < 8; r++) {
                const ulonglong2 s = *(const ulonglong2*)&s_obs[r * DOBS + 4 * d4];
                acc[r] = fma2(s.x, w.x, acc[r]);
                acc[r] = fma2(s.y, w.y, acc[r]);
            }
        }
        const float bj = b1[j];
        #pragma unroll
        for (int r = 0; r < 8; r++) {
            const float a = sum2(acc[r]) + bj;
            s_h[r * HH + j] = 0.5f * a * (1.f + erff(a * 0.70710678118654752f));
        }
    }
    __syncthreads();
    const int j = tid & 127;
    const int half = tid >> 7;
    u64 acc[8] = {0, 0, 0, 0, 0, 0, 0, 0};
    if (half == 0) {
        for (int d4 = 0; d4 < 64; d4++) {
            const ulonglong2 w = pW2[d4 * DD + j];
            #pragma unroll
            for (int r = 0; r < 8; r++) {
                const ulonglong2 s = *(const ulonglong2*)&s_h[r * HH + 4 * d4];
                acc[r] = fma2(s.x, w.x, acc[r]);
                acc[r] = fma2(s.y, w.y, acc[r]);
            }
        }
        for (int d4 = 0; d4 < 32; d4++) {
            const ulonglong2 w = pSkip[d4 * DD + j];
            #pragma unroll
            for (int r = 0; r < 8; r++) {
                const ulonglong2 s = *(const ulonglong2*)&s_obs[r * DOBS + 4 * d4];
                acc[r] = fma2(s.x, w.x, acc[r]);
                acc[r] = fma2(s.y, w.y, acc[r]);
            }
        }
    } else {
        for (int d4 = 32; d4 < 128; d4++) {
            const ulonglong2 w = pSkip[d4 * DD + j];
            #pragma unroll
            for (int r = 0; r < 8; r++) {
                const ulonglong2 s = *(const ulonglong2*)&s_obs[r * DOBS + 4 * d4];
                acc[r] = fma2(s.x, w.x, acc[r]);
                acc[r] = fma2(s.y, w.y, acc[r]);
            }
        }
        #pragma unroll
        for (int r = 0; r < 8; r++) s_p1[r * DD + j] = sum2(acc[r]);
    }
    __syncthreads();
    if (half == 0) {
        const float bj = b2[j];
        #pragma unroll
        for (int r = 0; r < 8; r++)
            g_z[(e0 + r) * DD + j] = tanha(sum2(acc[r]) + s_p1[r * DD + j] + bj);
    }
}

// ---------------------------------------------------------------------------
// Kernel 2: prologue (proven)
// ---------------------------------------------------------------------------
__global__ __launch_bounds__(256) void prolog_kernel(
    const float* __restrict__ lin_g, const float* __restrict__ lin_b)
{
    __shared__ __align__(16) float inp[2][DD], kk[2][DD], vv[2][DD];
    __shared__ float red[2][12];
    const int tid = threadIdx.x, lane = tid & 31, warp = tid >> 5;
    const int el = tid >> 7, j = tid & 127;
    const long ent = (long)blockIdx.x * 2 + el;
    const float zv = g_z[ent * DD + j];
    {
        float s1 = zv, s2 = zv * zv;
        #pragma unroll
        for (int off = 16; off > 0; off >>= 1) {
            s1 += __shfl_down_sync(0xffffffffu, s1, off);
            s2 += __shfl_down_sync(0xffffffffu, s2, off);
        }
        if (lane == 0) { red[el][warp & 3] = s1; red[el][4 + (warp & 3)] = s2; }
    }
    __syncthreads();
    if (j == 0) {
        float s = red[el][0] + red[el][1] + red[el][2] + red[el][3];
        float q = red[el][4] + red[el][5] + red[el][6] + red[el][7];
        const float mu = s * (1.f / 128.f);
        red[el][8] = mu;
        red[el][9] = rsqrtf(q * (1.f / 128.f) - mu * mu + 1e-5f);
    }
    __syncthreads();
    inp[el][j] = (zv - red[el][8]) * red[el][9] * lin_g[j] + lin_b[j];
    __syncthreads();
    u64 acc = 0;
    for (int d4 = 0; d4 < 32; d4++) {
        const ulonglong2 s = *(const ulonglong2*)&inp[el][4 * d4];
        const ulonglong2 w = pWk[d4 * DD + j];
        acc = fma2(s.x, w.x, acc);
        acc = fma2(s.y, w.y, acc);
    }
    kk[el][j] = sum2(acc);
    acc = 0;
    for (int d4 = 0; d4 < 32; d4++) {
        const ulonglong2 s = *(const ulonglong2*)&inp[el][4 * d4];
        const ulonglong2 w = pWv[d4 * DD + j];
        acc = fma2(s.x, w.x, acc);
        acc = fma2(s.y, w.y, acc);
    }
    vv[el][j] = sum2(acc);
    __syncthreads();
    acc = 0;
    for (int j4 = 0; j4 < 32; j4++) {
        const ulonglong2 s = *(const ulonglong2*)&kk[el][4 * j4];
        const ulonglong2 w = pWqT[j4 * DD + j];
        acc = fma2(s.x, w.x, acc);
        acc = fma2(s.y, w.y, acc);
    }
    g_wqk[ent * DD + j] = sum2(acc);
    #pragma unroll
    for (int pp = 0; pp < 3; pp++) {
        const int c = j + 128 * pp;
        u64 a2 = 0;
        for (int d4 = 0; d4 < 32; d4++) {
            const ulonglong2 s = *(const ulonglong2*)&vv[el][4 * d4];
            const ulonglong2 w = pWih[d4 * 384 + c];
            a2 = fma2(s.x, w.x, a2);
            a2 = fma2(s.y, w.y, a2);
        }
        g_vwih[ent * 384 + c] = sum2(a2);
    }
}

// ---------------------------------------------------------------------------
// Kernel 3: register-resident mma.sync slot attention, superblock phases.
// ---------------------------------------------------------------------------
#define SMEM_DYN 133120

__global__ __launch_bounds__(256) void slot_mma(
    const float* __restrict__ slot_mu,
    const float* __restrict__ bih, const float* __restrict__ bhh,
    const float* __restrict__ mb1, const float* __restrict__ mb2,
    const float* __restrict__ lsl_g, const float* __restrict__ lsl_b,
    const float* __restrict__ lml_g, const float* __restrict__ lml_b,
    float* __restrict__ out)
{
    extern __shared__ __align__(16) char dyn[];
    // [0, 110592): superblock ring (3 x 36864)
    float* sWqk  = (float*)(dyn + 110592);
    float* sVwih = (float*)(dyn + 114688);
    float* sPar  = (float*)(dyn + 126976);

    const int tid = threadIdx.x, lane = tid & 31, warp = tid >> 5;
    const int e = warp;
    const int lq = lane >> 2, lc = (lane & 3) * 2;
    const long blk = blockIdx.x;
    const float invscale = 0.088388347648318447f;
    const u32 ring = smem_u32(dyn);

    // prefetch superblocks 0, 1
    {
        const char* s0 = (const char*)gBall;
        for (int i = tid; i < 2304; i += 256) cp16(ring + (u32)i * 16, s0 + i * 16);
        CP_COMMIT();
        const char* s1 = (const char*)gBall + 36864;
        for (int i = tid; i < 2304; i += 256) cp16(ring + 36864u + (u32)i * 16, s1 + i * 16);
        CP_COMMIT();
    }

    for (int i = tid; i < 384; i += 256) { sPar[i] = bih[i]; sPar[384 + i] = bhh[i]; }
    if (tid < 128) {
        sPar[768 + tid] = mb1[tid];  sPar[896 + tid] = mb2[tid];
        sPar[1024 + tid] = lsl_g[tid]; sPar[1152 + tid] = lsl_b[tid];
        sPar[1280 + tid] = lml_g[tid]; sPar[1408 + tid] = lml_b[tid];
    }
    for (int i = tid; i < 8 * 384; i += 256) sVwih[i] = g_vwih[blk * (8 * 384) + i];
    for (int i = tid; i < 8 * 128; i += 256) sWqk[i] = g_wqk[blk * (8 * 128) + i];

    float sl[64];
    #pragma unroll
    for (int i2 = 0; i2 < 16; i2++)
        #pragma unroll
        for (int p2 = 0; p2 < 2; p2++) {
            const float* src = slot_mu + (lq + 8 * p2) * DD + 8 * i2 + lc;
            sl[i2 * 4 + p2 * 2 + 0] = src[0];
            sl[i2 * 4 + p2 * 2 + 1] = src[1];
        }

    __syncthreads();   // sPar/sVwih/sWqk visible before first use

    const u32 bLane = (u32)((lane & 15) * 144 + ((lane >> 4) & 1) * 16);
    int fb = 2, fs = 2, cs = 0;   // next fetch superblock / fetch slot / compute slot

// one superblock phase: wait, fetch next, hi-pass (dual) + lo-pass into ACC
#define PHASE(AHP, ALP, ACC) do { \
    CP_WAIT1(); \
    __syncthreads(); \
    { const char* _s = (const char*)gBall + fb * 36864; \
      u32 _d = ring + (u32)fs * 36864u; \
      for (int _i = tid; _i < 2304; _i += 256) cp16(_d + (u32)_i * 16, _s + _i * 16); \
      CP_COMMIT(); \
      fb++; if (fb == 10) fb = 0; \
      fs++; if (fs == 3) fs = 0; } \
    { const u32 _b = ring + (u32)cs * 36864u + bLane; \
      gemm_blk2<true>(AHP, ALP, _b, ACC); \
      gemm_blk2<false>(AHP, ALP, _b + 18432u, ACC); } \
    cs++; if (cs == 3) cs = 0; \
} while (0)

    u32 Ah[32], Al[32];

    for (int it = 0; it < 3; it++) {
        float mu_[2], rs_[2];
        #pragma unroll
        for (int p2 = 0; p2 < 2; p2++) {
            float s = 0.f, q = 0.f;
            #pragma unroll
            for (int i2 = 0; i2 < 16; i2++) {
                const float v0 = sl[i2 * 4 + p2 * 2], v1 = sl[i2 * 4 + p2 * 2 + 1];
                s += v0 + v1;  q += v0 * v0 + v1 * v1;
            }
            s += __shfl_xor_sync(0xffffffffu, s, 1);
            s += __shfl_xor_sync(0xffffffffu, s, 2);
            q += __shfl_xor_sync(0xffffffffu, q, 1);
            q += __shfl_xor_sync(0xffffffffu, q, 2);
            mu_[p2] = s * (1.f / 128.f);
            rs_[p2] = rsqrtf(q * (1.f / 128.f) - mu_[p2] * mu_[p2] + 1e-5f);
        }
        float pd0 = 0.f, pd1 = 0.f;
        #pragma unroll
        for (int i2 = 0; i2 < 16; i2++) {
            const int j0 = 8 * i2 + lc;
            const float g0 = sPar[1024 + j0], g1 = sPar[1024 + j0 + 1];
            const float bb0 = sPar[1152 + j0], bb1 = sPar[1152 + j0 + 1];
            const float w0 = sWqk[e * 128 + j0], w1 = sWqk[e * 128 + j0 + 1];
            pd0 += ((sl[i2 * 4 + 0] - mu_[0]) * rs_[0] * g0 + bb0) * w0
                 + ((sl[i2 * 4 + 1] - mu_[0]) * rs_[0] * g1 + bb1) * w1;
            pd1 += ((sl[i2 * 4 + 2] - mu_[1]) * rs_[1] * g0 + bb0) * w0
                 + ((sl[i2 * 4 + 3] - mu_[1]) * rs_[1] * g1 + bb1) * w1;
        }
        pd0 += __shfl_xor_sync(0xffffffffu, pd0, 1);
        pd0 += __shfl_xor_sync(0xffffffffu, pd0, 2);
        pd1 += __shfl_xor_sync(0xffffffffu, pd1, 1);
        pd1 += __shfl_xor_sync(0xffffffffu, pd1, 2);
        const float l0 = pd0 * invscale, l1 = pd1 * invscale;
        float m = fmaxf(l0, l1);
        m = fmaxf(m, __shfl_xor_sync(0xffffffffu, m, 4));
        m = fmaxf(m, __shfl_xor_sync(0xffffffffu, m, 8));
        m = fmaxf(m, __shfl_xor_sync(0xffffffffu, m, 16));
        const float ex0 = __expf(l0 - m), ex1 = __expf(l1 - m);
        float ssum = ex0 + ex1;
        ssum += __shfl_xor_sync(0xffffffffu, ssum, 4);
        ssum += __shfl_xor_sync(0xffffffffu, ssum, 8);
        ssum += __shfl_xor_sync(0xffffffffu, ssum, 16);
        const float a0 = ex0 / ssum, a1 = ex1 / ssum;

        #pragma unroll
        for (int t = 0; t < 32; t++)
            Ah[t] = split_pair(sl[2 * t], sl[2 * t + 1], Al[t]);

        float nv0[32];
        #pragma unroll
        for (int h = 0; h < 2; h++) {
            float aR[32], aZ[32], aN[32];
            #pragma unroll
            for (int i = 0; i < 32; i++) { aR[i] = 0.f; aZ[i] = 0.f; aN[i] = 0.f; }
            PHASE(Ah, Al, aR);
            PHASE(Ah, Al, aZ);
            PHASE(Ah, Al, aN);

            const int cb = 64 * h;
            #pragma unroll
            for (int tl = 0; tl < 16; tl++) {
                const int n = tl >> 1, p2 = tl & 1;
                const int j0 = cb + 8 * n + lc;
                const int tg = 16 * h + tl;
                const float2 hv = unsplit(Ah[tg], Al[tg]);
                const float af = p2 ? a1 : a0;
                #pragma unroll
                for (int c = 0; c < 2; c++) {
                    const int j = j0 + c;
                    const float gr = aR[2 * tl + c] + sPar[384 + j];
                    const float gz = aZ[2 * tl + c] + sPar[512 + j];
                    const float gn = aN[2 * tl + c] + sPar[640 + j];
                    const float rr = sigm(af * sVwih[e * 384 + j] + sPar[j] + gr);
                    const float zz = sigm(af * sVwih[e * 384 + 128 + j] + sPar[128 + j] + gz);
                    const float nn = tanha(af * sVwih[e * 384 + 256 + j] + sPar[256 + j] + rr * gn);
                    const float hh = c ? hv.y : hv.x;
                    const float nv = (1.f - zz) * nn + zz * hh;
                    if (h == 0) nv0[2 * tl + c] = nv;
                    else        sl[32 + 2 * tl + c] = nv;
                }
            }
        }
        #pragma unroll
        for (int t = 0; t < 32; t++) sl[t] = nv0[t];

        #pragma unroll
        for (int p2 = 0; p2 < 2; p2++) {
            float s = 0.f, q = 0.f;
            #pragma unroll
            for (int i2 = 0; i2 < 16; i2++) {
                const float v0 = sl[i2 * 4 + p2 * 2], v1 = sl[i2 * 4 + p2 * 2 + 1];
                s += v0 + v1;  q += v0 * v0 + v1 * v1;
            }
            s += __shfl_xor_sync(0xffffffffu, s, 1);
            s += __shfl_xor_sync(0xffffffffu, s, 2);
            q += __shfl_xor_sync(0xffffffffu, q, 1);
            q += __shfl_xor_sync(0xffffffffu, q, 2);
            mu_[p2] = s * (1.f / 128.f);
            rs_[p2] = rsqrtf(q * (1.f / 128.f) - mu_[p2] * mu_[p2] + 1e-5f);
        }
        #pragma unroll
        for (int t = 0; t < 32; t++) {
            const int i2 = t >> 1, p2 = t & 1;
            const int j0 = 8 * i2 + lc;
            const float v0 = (sl[2 * t] - mu_[p2]) * rs_[p2] * sPar[1280 + j0] + sPar[1408 + j0];
            const float v1 = (sl[2 * t + 1] - mu_[p2]) * rs_[p2] * sPar[1280 + j0 + 1] + sPar[1408 + j0 + 1];
            Ah[t] = split_pair(v0, v1, Al[t]);
        }

        float accM[64];
        #pragma unroll
        for (int i = 0; i < 64; i++) accM[i] = 0.f;
        PHASE(Ah, Al, accM);
        PHASE(Ah, Al, accM + 32);

        #pragma unroll
        for (int t = 0; t < 32; t++) {
            const int i2 = t >> 1;
            const int j0 = 8 * i2 + lc;
            const float v0 = fmaxf(accM[2 * t] + sPar[768 + j0], 0.f);
            const float v1 = fmaxf(accM[2 * t + 1] + sPar[768 + j0 + 1], 0.f);
            Ah[t] = split_pair(v0, v1, Al[t]);
        }

        #pragma unroll
        for (int i = 0; i < 64; i++) accM[i] = 0.f;
        PHASE(Ah, Al, accM);
        PHASE(Ah, Al, accM + 32);

        #pragma unroll
        for (int t = 0; t < 32; t++) {
            const int i2 = t >> 1;
            const int j0 = 8 * i2 + lc;
            sl[2 * t]     += accM[2 * t] + sPar[896 + j0];
            sl[2 * t + 1] += accM[2 * t + 1] + sPar[896 + j0 + 1];
        }
    }

    #pragma unroll
    for (int p2 = 0; p2 < 2; p2++) {
        float q = 0.f;
        #pragma unroll
        for (int i2 = 0; i2 < 16; i2++) {
            const float v0 = sl[i2 * 4 + p2 * 2], v1 = sl[i2 * 4 + p2 * 2 + 1];
            q += v0 * v0 + v1 * v1;
        }
        q += __shfl_xor_sync(0xffffffffu, q, 1);
        q += __shfl_xor_sync(0xffffffffu, q, 2);
        const float inv = 1.f / fmaxf(sqrtf(q), 1e-8f);
        float* dst = out + (blk * 8 + e) * (NS * DD) + (lq + 8 * p2) * DD;
        #pragma unroll
        for (int i2 = 0; i2 < 16; i2++) {
            float2 v;
            v.x = sl[i2 * 4 + p2 * 2] * inv;
            v.y = sl[i2 * 4 + p2 * 2 + 1] * inv;
            *(float2*)(dst + 8 * i2 + lc) = v;
        }
    }
#undef PHASE
}

// ---------------------------------------------------------------------------
// Kernel 4: temporal blend via mma.sync (proven R14)
// ---------------------------------------------------------------------------
#define TSMEM 73728

__global__ __launch_bounds__(256) void temporal_mma(float* __restrict__ out)
{
    extern __shared__ __align__(16) char tdyn[];
    const int tid = threadIdx.x, lane = tid & 31, warp = tid >> 5;
    const long b = (long)blockIdx.x * 8 + warp;
    const int lq = lane >> 2, lc = (lane & 3) * 2;

    for (int i = tid; i < 4608; i += 256)
        ((uint4*)tdyn)[i] = ((const uint4*)gWtB)[i];
    __syncthreads();
    const u32 base = smem_u32(tdyn);
    const u32 bLane = (u32)((lane & 15) * 144 + ((lane >> 4) & 1) * 16);

    float* b0 = out + b * 64 * (NS * DD);

    float sl[64];
    #pragma unroll
    for (int i2 = 0; i2 < 16; i2++)
        #pragma unroll
        for (int p2 = 0; p2 < 2; p2++) {
            const float2 v = *(const float2*)(b0 + (lq + 8 * p2) * DD + 8 * i2 + lc);
            sl[i2 * 4 + p2 * 2 + 0] = v.x;
            sl[i2 * 4 + p2 * 2 + 1] = v.y;
        }

    u32 Ah[32], Al[32];
    for (int t = 1; t < 64; t++) {
        #pragma unroll
        for (int q = 0; q < 32; q++)
            Ah[q] = split_pair(sl[2 * q], sl[2 * q + 1], Al[q]);

        float acc[64];
        #pragma unroll
        for (int i = 0; i < 64; i++) acc[i] = 0.f;
        gemm_blk2<true >(Ah, Al, base + 0u * 18432u + bLane, acc);
        gemm_blk2<false>(Ah, Al, base + 1u * 18432u + bLane, acc);
        gemm_blk2<true >(Ah, Al, base + 2u * 18432u + bLane, acc + 32);
        gemm_blk2<false>(Ah, Al, base + 3u * 18432u + bLane, acc + 32);

        float* cur = b0 + t * (NS * DD);
        #pragma unroll
        for (int q = 0; q < 32; q++) {
            const int i2 = q >> 1, p2 = q & 1;
            float* p = cur + (lq + 8 * p2) * DD + 8 * i2 + lc;
            const float2 c = *(const float2*)p;
            float2 v;
            v.x = 0.7f * c.x + 0.3f * tanha(acc[2 * q]);
            v.y = 0.7f * c.y + 0.3f * tanha(acc[2 * q + 1]);
            *(float2*)p = v;
            sl[2 * q] = v.x;
            sl[2 * q + 1] = v.y;
        }
    }
}

// ---------------------------------------------------------------------------
extern "C" void kernel_launch(void* const* d_in, const int* in_sizes, int n_in,
                              void* d_out, int out_size)
{
    const float* obs   = (const float*)d_in[0];
    const float* eW1   = (const float*)d_in[1];
    const float* eb1   = (const float*)d_in[2];
    const float* eW2   = (const float*)d_in[3];
    const float* eb2   = (const float*)d_in[4];
    const float* skipW = (const float*)d_in[5];
    const float* smu   = (const float*)d_in[6];
    const float* Wk    = (const float*)d_in[7];
    const float* Wv    = (const float*)d_in[8];
    const float* Wq    = (const float*)d_in[9];
    const float* gWih  = (const float*)d_in[10];
    const float* gWhh  = (const float*)d_in[11];
    const float* gbih  = (const float*)d_in[12];
    const float* gbhh  = (const float*)d_in[13];
    const float* mW1   = (const float*)d_in[14];
    const float* mb1   = (const float*)d_in[15];
    const float* mW2   = (const float*)d_in[16];
    const float* mb2   = (const float*)d_in[17];
    const float* lin_g = (const float*)d_in[18];
    const float* lin_b = (const float*)d_in[19];
    const float* lsl_g = (const float*)d_in[20];
    const float* lsl_b = (const float*)d_in[21];
    const float* lml_g = (const float*)d_in[22];
    const float* lml_b = (const float*)d_in[23];
    const float* Wt    = (const float*)d_in[24];
    float* out = (float*)d_out;

    static int init_done = 0;
    if (!init_done) {
        cudaFuncSetAttribute(slot_mma, cudaFuncAttributeMaxDynamicSharedMemorySize, SMEM_DYN);
        cudaFuncSetAttribute(temporal_mma, cudaFuncAttributeMaxDynamicSharedMemorySize, TSMEM);
        init_done = 1;
    }

    pack_all<<<(307200 + 255) / 256, 256>>>(eW1, eW2, skipW, Wk, Wv, Wq,
                                            gWih, gWhh, mW1, mW2, Wt);
    enc_kernel<<<BT / 8, 256>>>(obs, eb1, eb2);
    prolog_kernel<<<BT / 2, 256>>>(lin_g, lin_b);
    slot_mma<<<BT / 8, 256, SMEM_DYN>>>(smu, gbih, gbhh, mb1, mb2,
                                        lsl_g, lsl_b, lml_g, lml_b, out);
    temporal_mma<<<32, 256, TSMEM>>>(out);
}

// round 16
// speedup vs baseline: 5.9890x; 1.3044x over previous
#include <cuda_runtime.h>
#include <cuda_bf16.h>
#include <stdint.h>
#include <math.h>

#define BT 16384
#define DOBS 512
#define DD 128
#define NS 16

typedef unsigned long long u64;
typedef unsigned int u32;
typedef unsigned short u16;

__device__ __forceinline__ float tanha(float x) {
    float y;
    asm("tanh.approx.f32 %0, %1;" : "=f"(y) : "f"(x));
    return y;
}
__device__ __forceinline__ float sigm(float x) { return 0.5f * tanha(0.5f * x) + 0.5f; }

// fast split: hi = truncated top-16 bits (PRMT pack), lo = exact residual (RN bf16x2)
__device__ __forceinline__ u32 split_pair(float v0, float v1, u32& lo_out) {
    const u32 b0 = __float_as_uint(v0), b1 = __float_as_uint(v1);
    u32 hi;
    asm("prmt.b32 %0, %1, %2, 0x7632;" : "=r"(hi) : "r"(b0), "r"(b1));
    const float l0 = v0 - __uint_as_float(b0 & 0xffff0000u);
    const float l1 = v1 - __uint_as_float(b1 & 0xffff0000u);
    asm("cvt.rn.bf16x2.f32 %0, %1, %2;" : "=r"(lo_out) : "f"(l1), "f"(l0));
    return hi;
}
__device__ __forceinline__ float2 unsplit(u32 hi, u32 lo) {
    float2 r;
    r.x = __bfloat162float(__ushort_as_bfloat16((u16)(hi & 0xffff)))
        + __bfloat162float(__ushort_as_bfloat16((u16)(lo & 0xffff)));
    r.y = __bfloat162float(__ushort_as_bfloat16((u16)(hi >> 16)))
        + __bfloat162float(__ushort_as_bfloat16((u16)(lo >> 16)));
    return r;
}

__device__ __forceinline__ u32 smem_u32(const void* p) {
    u32 a;
    asm("{ .reg .u64 t; cvta.to.shared.u64 t, %1; cvt.u32.u64 %0, t; }" : "=r"(a) : "l"(p));
    return a;
}
__device__ __forceinline__ void mma_bf16(float* d, u32 a0, u32 a1, u32 a2, u32 a3,
                                         u32 b0, u32 b1) {
    asm volatile(
        "mma.sync.aligned.m16n8k16.row.col.f32.bf16.bf16.f32 "
        "{%0,%1,%2,%3}, {%4,%5,%6,%7}, {%8,%9}, {%0,%1,%2,%3};"
        : "+f"(d[0]), "+f"(d[1]), "+f"(d[2]), "+f"(d[3])
        : "r"(a0), "r"(a1), "r"(a2), "r"(a3), "r"(b0), "r"(b1));
}
__device__ __forceinline__ void cp16(u32 saddr, const void* g) {
    asm volatile("cp.async.cg.shared.global [%0], [%1], 16;" :: "r"(saddr), "l"(g));
}
#define CP_COMMIT() asm volatile("cp.async.commit_group;" ::: "memory")
#define CP_WAIT1()  asm volatile("cp.async.wait_group 1;" ::: "memory")

// One B block (k=128, n=64, row stride 144B). A fragments from registers.
template<bool DUAL>
__device__ __forceinline__ void gemm_blk2(const u32* Ah, const u32* Al, u32 bAd, float* acc) {
    #pragma unroll
    for (int k = 0; k < 8; k++) {
        #pragma unroll
        for (int q = 0; q < 4; q++) {
            u32 b0, b1, b2, b3;
            asm volatile("ldmatrix.sync.aligned.m8n8.x4.trans.shared.b16 {%0,%1,%2,%3}, [%4];"
                : "=r"(b0), "=r"(b1), "=r"(b2), "=r"(b3) : "r"(bAd + (u32)(k * 2304 + q * 32)));
            mma_bf16(acc + (q * 2) * 4,     Ah[k * 4], Ah[k * 4 + 1], Ah[k * 4 + 2], Ah[k * 4 + 3], b0, b1);
            mma_bf16(acc + (q * 2 + 1) * 4, Ah[k * 4], Ah[k * 4 + 1], Ah[k * 4 + 2], Ah[k * 4 + 3], b2, b3);
            if (DUAL) {
                mma_bf16(acc + (q * 2) * 4,     Al[k * 4], Al[k * 4 + 1], Al[k * 4 + 2], Al[k * 4 + 3], b0, b1);
                mma_bf16(acc + (q * 2 + 1) * 4, Al[k * 4], Al[k * 4 + 1], Al[k * 4 + 2], Al[k * 4 + 3], b2, b3);
            }
        }
    }
}

// ---------------- device scratch ----------------
__device__ float g_wqk[BT * DD];
__device__ float g_vwih[BT * 384];

// 10 superblocks of 36864 B for slot kernel (hi/lo pairs adjacent)
__device__ u16 gBall[20 * 9216];
// 4 Wt blocks for temporal
__device__ u16 gWtB[4 * 9216];
// 40 superblocks for fused enc+prolog
__device__ u16 gBenc[40 * 18432];

__device__ __forceinline__ u16 bf_hi(float w) {
    return (u16)(__float_as_uint(w) >> 16);
}
__device__ __forceinline__ u16 bf_lo(float w) {
    float hf = __uint_as_float(__float_as_uint(w) & 0xffff0000u);
    return __bfloat16_as_ushort(__float2bfloat16(w - hf));
}

__global__ __launch_bounds__(256) void pack_all(
    const float* __restrict__ eW1, const float* __restrict__ eW2, const float* __restrict__ skipW,
    const float* __restrict__ Wk, const float* __restrict__ Wv, const float* __restrict__ Wq,
    const float* __restrict__ gWih, const float* __restrict__ gWhh,
    const float* __restrict__ mW1, const float* __restrict__ mW2, const float* __restrict__ Wt)
{
    int idx = blockIdx.x * 256 + threadIdx.x;
    // gBall (slot weights)
    if (idx < 184320) {
        const int b = idx / 9216, r = idx % 9216;
        const int k = r / 72, n = r % 72;
        float w = 0.f;
        int s;
        if (b < 12) {
            const int half = b / 6, rem = b % 6, g = rem >> 1;
            s = rem & 1;
            if (n < 64) w = gWhh[k * 384 + g * 128 + half * 64 + n];
        } else {
            const int bb = b - 12, m = bb >> 2, half = (bb >> 1) & 1;
            s = bb & 1;
            if (n < 64) w = (m ? mW2 : mW1)[k * 128 + half * 64 + n];
        }
        gBall[idx] = s ? bf_lo(w) : bf_hi(w);
        return;
    }
    idx -= 184320;
    // gWtB
    if (idx < 36864) {
        const int b = idx / 9216, r = idx % 9216;
        const int half = b >> 1, s = b & 1;
        const int k = r / 72, n = r % 72;
        float w = (n < 64) ? Wt[k * 128 + half * 64 + n] : 0.f;
        gWtB[idx] = s ? bf_lo(w) : bf_hi(w);
        return;
    }
    idx -= 36864;
    // gBenc: 40 superblocks (hi 9216 then lo 9216 each)
    if (idx < 737280) {
        const int p = idx / 18432, r2 = idx % 18432;
        const int s = r2 / 9216, r = r2 % 9216;
        const int k = r / 72, n = r % 72;
        float w = 0.f;
        if (n < 64) {
            if (p < 16) {
                const int grp = p >> 3, pp = p & 7, kc = pp >> 1, nh = pp & 1;
                w = eW1[(kc * 128 + k) * 256 + grp * 128 + nh * 64 + n];
            } else if (p < 20) {
                const int q = p - 16, kc = q & 1, nh = q >> 1;
                w = eW2[(kc * 128 + k) * 128 + nh * 64 + n];
            } else if (p < 28) {
                const int q = p - 20, kc = q >> 1, nh = q & 1;
                w = skipW[(kc * 128 + k) * 128 + nh * 64 + n];
            } else if (p < 30) {
                w = Wk[k * 128 + (p - 28) * 64 + n];
            } else if (p < 32) {
                w = Wv[k * 128 + (p - 30) * 64 + n];
            } else if (p < 34) {
                w = Wq[((p - 32) * 64 + n) * 128 + k];
            } else {
                w = gWih[k * 384 + (p - 34) * 64 + n];
            }
        }
        gBenc[idx] = s ? bf_lo(w) : bf_hi(w);
    }
}

// ---------------------------------------------------------------------------
// build obs A-fragments for k-chunk kc (16 rows from orow0)
// ---------------------------------------------------------------------------
__device__ __forceinline__ void build_obs(const float* __restrict__ orow0, int kc,
                                          int lq, int lc, u32* Oh, u32* Ol)
{
    #pragma unroll
    for (int kt = 0; kt < 8; kt++) {
        const int kb = kc * 128 + kt * 16;
        const float2 a = *(const float2*)(orow0 + lq * DOBS + kb + lc);
        const float2 b = *(const float2*)(orow0 + (lq + 8) * DOBS + kb + lc);
        const float2 c = *(const float2*)(orow0 + lq * DOBS + kb + 8 + lc);
        const float2 d = *(const float2*)(orow0 + (lq + 8) * DOBS + kb + 8 + lc);
        Oh[kt * 4 + 0] = split_pair(a.x, a.y, Ol[kt * 4 + 0]);
        Oh[kt * 4 + 1] = split_pair(b.x, b.y, Ol[kt * 4 + 1]);
        Oh[kt * 4 + 2] = split_pair(c.x, c.y, Ol[kt * 4 + 2]);
        Oh[kt * 4 + 3] = split_pair(d.x, d.y, Ol[kt * 4 + 3]);
    }
}

// ---------------------------------------------------------------------------
// Kernel 1: fused encoder + prologue, mma.sync. 128 CTAs x 8 warps;
// warp owns 16 entries (m16). 40 superblocks streamed via cp.async ring.
// ---------------------------------------------------------------------------
#define ESMEM 113664

__global__ __launch_bounds__(256) void encpro_mma(
    const float* __restrict__ obs,
    const float* __restrict__ eb1, const float* __restrict__ eb2,
    const float* __restrict__ lin_g, const float* __restrict__ lin_b)
{
    extern __shared__ __align__(16) char edyn[];
    float* sPar = (float*)(edyn + 110592);   // eb1[256]|eb2[128]|lin_g[128]|lin_b[128]

    const int tid = threadIdx.x, lane = tid & 31, warp = tid >> 5;
    const int lq = lane >> 2, lc = (lane & 3) * 2;
    const long ent0 = (long)blockIdx.x * 128 + warp * 16;
    const u32 ring = smem_u32(edyn);

    {
        const char* s0 = (const char*)gBenc;
        for (int i = tid; i < 2304; i += 256) cp16(ring + (u32)i * 16, s0 + i * 16);
        CP_COMMIT();
        const char* s1 = (const char*)gBenc + 36864;
        for (int i = tid; i < 2304; i += 256) cp16(ring + 36864u + (u32)i * 16, s1 + i * 16);
        CP_COMMIT();
    }
    if (tid < 256) sPar[tid] = eb1[tid];
    if (tid < 128) {
        sPar[256 + tid] = eb2[tid];
        sPar[384 + tid] = lin_g[tid];
        sPar[512 + tid] = lin_b[tid];
    }
    __syncthreads();

    const u32 bLane = (u32)((lane & 15) * 144 + ((lane >> 4) & 1) * 16);
    int fb = 2, fs = 2, cs = 0;

#define EPHASE(AHP, ALP, ACC) do { \
    CP_WAIT1(); \
    __syncthreads(); \
    { const char* _s = (const char*)gBenc + fb * 36864; \
      u32 _d = ring + (u32)fs * 36864u; \
      for (int _i = tid; _i < 2304; _i += 256) cp16(_d + (u32)_i * 16, _s + _i * 16); \
      CP_COMMIT(); \
      fb++; if (fb == 40) fb = 0; \
      fs++; if (fs == 3) fs = 0; } \
    { const u32 _b = ring + (u32)cs * 36864u + bLane; \
      gemm_blk2<true>(AHP, ALP, _b, ACC); \
      gemm_blk2<false>(AHP, ALP, _b + 18432u, ACC); } \
    cs++; if (cs == 3) cs = 0; \
} while (0)

    const float* orow0 = obs + ent0 * DOBS;
    u32 Oh[32], Ol[32], A1h[32], A1l[32], A2h[32], A2l[32];
    float acc[64];

    // ---- h group 1: cols 0..127 (phases 0-7) ----
    #pragma unroll
    for (int i = 0; i < 64; i++) acc[i] = 0.f;
    for (int kc = 0; kc < 4; kc++) {
        build_obs(orow0, kc, lq, lc, Oh, Ol);
        EPHASE(Oh, Ol, acc);
        EPHASE(Oh, Ol, acc + 32);
    }
    #pragma unroll
    for (int t = 0; t < 32; t++) {
        const int j0 = 8 * (t >> 1) + lc;
        float v0 = acc[2 * t] + sPar[j0];
        float v1 = acc[2 * t + 1] + sPar[j0 + 1];
        v0 = 0.5f * v0 * (1.f + erff(v0 * 0.70710678118654752f));
        v1 = 0.5f * v1 * (1.f + erff(v1 * 0.70710678118654752f));
        A1h[t] = split_pair(v0, v1, A1l[t]);
    }
    // ---- h group 2: cols 128..255 (phases 8-15) ----
    #pragma unroll
    for (int i = 0; i < 64; i++) acc[i] = 0.f;
    for (int kc = 0; kc < 4; kc++) {
        build_obs(orow0, kc, lq, lc, Oh, Ol);
        EPHASE(Oh, Ol, acc);
        EPHASE(Oh, Ol, acc + 32);
    }
    #pragma unroll
    for (int t = 0; t < 32; t++) {
        const int j0 = 8 * (t >> 1) + lc;
        float v0 = acc[2 * t] + sPar[128 + j0];
        float v1 = acc[2 * t + 1] + sPar[128 + j0 + 1];
        v0 = 0.5f * v0 * (1.f + erff(v0 * 0.70710678118654752f));
        v1 = 0.5f * v1 * (1.f + erff(v1 * 0.70710678118654752f));
        A2h[t] = split_pair(v0, v1, A2l[t]);
    }
    // ---- z = h@W2 (phases 16-19) + obs@skip (20-27) ----
    #pragma unroll
    for (int i = 0; i < 64; i++) acc[i] = 0.f;
    EPHASE(A1h, A1l, acc);       EPHASE(A2h, A2l, acc);
    EPHASE(A1h, A1l, acc + 32);  EPHASE(A2h, A2l, acc + 32);
    for (int kc = 0; kc < 4; kc++) {
        build_obs(orow0, kc, lq, lc, Oh, Ol);
        EPHASE(Oh, Ol, acc);
        EPHASE(Oh, Ol, acc + 32);
    }
    // ---- tanh + LN -> inp frags (reuse A1) ----
    float z[64];
    #pragma unroll
    for (int t = 0; t < 32; t++) {
        const int j0 = 8 * (t >> 1) + lc;
        z[2 * t]     = tanha(acc[2 * t] + sPar[256 + j0]);
        z[2 * t + 1] = tanha(acc[2 * t + 1] + sPar[256 + j0 + 1]);
    }
    float mu_[2], rs_[2];
    #pragma unroll
    for (int p2 = 0; p2 < 2; p2++) {
        float s = 0.f, q = 0.f;
        #pragma unroll
        for (int i2 = 0; i2 < 16; i2++) {
            const float v0 = z[i2 * 4 + p2 * 2], v1 = z[i2 * 4 + p2 * 2 + 1];
            s += v0 + v1;  q += v0 * v0 + v1 * v1;
        }
        s += __shfl_xor_sync(0xffffffffu, s, 1);
        s += __shfl_xor_sync(0xffffffffu, s, 2);
        q += __shfl_xor_sync(0xffffffffu, q, 1);
        q += __shfl_xor_sync(0xffffffffu, q, 2);
        mu_[p2] = s * (1.f / 128.f);
        rs_[p2] = rsqrtf(q * (1.f / 128.f) - mu_[p2] * mu_[p2] + 1e-5f);
    }
    #pragma unroll
    for (int t = 0; t < 32; t++) {
        const int p2 = t & 1;
        const int j0 = 8 * (t >> 1) + lc;
        const float v0 = (z[2 * t] - mu_[p2]) * rs_[p2] * sPar[384 + j0] + sPar[512 + j0];
        const float v1 = (z[2 * t + 1] - mu_[p2]) * rs_[p2] * sPar[384 + j0 + 1] + sPar[512 + j0 + 1];
        A1h[t] = split_pair(v0, v1, A1l[t]);
    }
    // ---- k (28-29) -> frags (A2) ----
    #pragma unroll
    for (int i = 0; i < 64; i++) acc[i] = 0.f;
    EPHASE(A1h, A1l, acc);  EPHASE(A1h, A1l, acc + 32);
    #pragma unroll
    for (int t = 0; t < 32; t++)
        A2h[t] = split_pair(acc[2 * t], acc[2 * t + 1], A2l[t]);
    // ---- v (30-31) -> frags (Oh) ----
    #pragma unroll
    for (int i = 0; i < 64; i++) acc[i] = 0.f;
    EPHASE(A1h, A1l, acc);  EPHASE(A1h, A1l, acc + 32);
    #pragma unroll
    for (int t = 0; t < 32; t++)
        Oh[t] = split_pair(acc[2 * t], acc[2 * t + 1], Ol[t]);
    // ---- wqk (32-33) -> store ----
    #pragma unroll
    for (int i = 0; i < 64; i++) acc[i] = 0.f;
    EPHASE(A2h, A2l, acc);  EPHASE(A2h, A2l, acc + 32);
    #pragma unroll
    for (int t = 0; t < 32; t++) {
        const int row = lq + 8 * (t & 1);
        const int j0 = 8 * (t >> 1) + lc;
        float2 v;  v.x = acc[2 * t];  v.y = acc[2 * t + 1];
        *(float2*)(g_wqk + (ent0 + row) * 128 + j0) = v;
    }
    // ---- vwih (34-39) -> store per 64-col half ----
    for (int h6 = 0; h6 < 6; h6++) {
        #pragma unroll
        for (int i = 0; i < 32; i++) acc[i] = 0.f;
        EPHASE(Oh, Ol, acc);
        #pragma unroll
        for (int t = 0; t < 16; t++) {
            const int row = lq + 8 * (t & 1);
            const int col = 8 * (t >> 1) + lc;
            float2 v;  v.x = acc[2 * t];  v.y = acc[2 * t + 1];
            *(float2*)(g_vwih + (ent0 + row) * 384 + h6 * 64 + col) = v;
        }
    }
#undef EPHASE
}

// ---------------------------------------------------------------------------
// Kernel 2: register-resident mma.sync slot attention (proven R15, unchanged)
// ---------------------------------------------------------------------------
#define SMEM_DYN 133120

__global__ __launch_bounds__(256) void slot_mma(
    const float* __restrict__ slot_mu,
    const float* __restrict__ bih, const float* __restrict__ bhh,
    const float* __restrict__ mb1, const float* __restrict__ mb2,
    const float* __restrict__ lsl_g, const float* __restrict__ lsl_b,
    const float* __restrict__ lml_g, const float* __restrict__ lml_b,
    float* __restrict__ out)
{
    extern __shared__ __align__(16) char dyn[];
    float* sWqk  = (float*)(dyn + 110592);
    float* sVwih = (float*)(dyn + 114688);
    float* sPar  = (float*)(dyn + 126976);

    const int tid = threadIdx.x, lane = tid & 31, warp = tid >> 5;
    const int e = warp;
    const int lq = lane >> 2, lc = (lane & 3) * 2;
    const long blk = blockIdx.x;
    const float invscale = 0.088388347648318447f;
    const u32 ring = smem_u32(dyn);

    {
        const char* s0 = (const char*)gBall;
        for (int i = tid; i < 2304; i += 256) cp16(ring + (u32)i * 16, s0 + i * 16);
        CP_COMMIT();
        const char* s1 = (const char*)gBall + 36864;
        for (int i = tid; i < 2304; i += 256) cp16(ring + 36864u + (u32)i * 16, s1 + i * 16);
        CP_COMMIT();
    }

    for (int i = tid; i < 384; i += 256) { sPar[i] = bih[i]; sPar[384 + i] = bhh[i]; }
    if (tid < 128) {
        sPar[768 + tid] = mb1[tid];  sPar[896 + tid] = mb2[tid];
        sPar[1024 + tid] = lsl_g[tid]; sPar[1152 + tid] = lsl_b[tid];
        sPar[1280 + tid] = lml_g[tid]; sPar[1408 + tid] = lml_b[tid];
    }
    for (int i = tid; i < 8 * 384; i += 256) sVwih[i] = g_vwih[blk * (8 * 384) + i];
    for (int i = tid; i < 8 * 128; i += 256) sWqk[i] = g_wqk[blk * (8 * 128) + i];

    float sl[64];
    #pragma unroll
    for (int i2 = 0; i2 < 16; i2++)
        #pragma unroll
        for (int p2 = 0; p2 < 2; p2++) {
            const float* src = slot_mu + (lq + 8 * p2) * DD + 8 * i2 + lc;
            sl[i2 * 4 + p2 * 2 + 0] = src[0];
            sl[i2 * 4 + p2 * 2 + 1] = src[1];
        }

    __syncthreads();

    const u32 bLane = (u32)((lane & 15) * 144 + ((lane >> 4) & 1) * 16);
    int fb = 2, fs = 2, cs = 0;

#define PHASE(AHP, ALP, ACC) do { \
    CP_WAIT1(); \
    __syncthreads(); \
    { const char* _s = (const char*)gBall + fb * 36864; \
      u32 _d = ring + (u32)fs * 36864u; \
      for (int _i = tid; _i < 2304; _i += 256) cp16(_d + (u32)_i * 16, _s + _i * 16); \
      CP_COMMIT(); \
      fb++; if (fb == 10) fb = 0; \
      fs++; if (fs == 3) fs = 0; } \
    { const u32 _b = ring + (u32)cs * 36864u + bLane; \
      gemm_blk2<true>(AHP, ALP, _b, ACC); \
      gemm_blk2<false>(AHP, ALP, _b + 18432u, ACC); } \
    cs++; if (cs == 3) cs = 0; \
} while (0)

    u32 Ah[32], Al[32];

    for (int it = 0; it < 3; it++) {
        float mu_[2], rs_[2];
        #pragma unroll
        for (int p2 = 0; p2 < 2; p2++) {
            float s = 0.f, q = 0.f;
            #pragma unroll
            for (int i2 = 0; i2 < 16; i2++) {
                const float v0 = sl[i2 * 4 + p2 * 2], v1 = sl[i2 * 4 + p2 * 2 + 1];
                s += v0 + v1;  q += v0 * v0 + v1 * v1;
            }
            s += __shfl_xor_sync(0xffffffffu, s, 1);
            s += __shfl_xor_sync(0xffffffffu, s, 2);
            q += __shfl_xor_sync(0xffffffffu, q, 1);
            q += __shfl_xor_sync(0xffffffffu, q, 2);
            mu_[p2] = s * (1.f / 128.f);
            rs_[p2] = rsqrtf(q * (1.f / 128.f) - mu_[p2] * mu_[p2] + 1e-5f);
        }
        float pd0 = 0.f, pd1 = 0.f;
        #pragma unroll
        for (int i2 = 0; i2 < 16; i2++) {
            const int j0 = 8 * i2 + lc;
            const float g0 = sPar[1024 + j0], g1 = sPar[1024 + j0 + 1];
            const float bb0 = sPar[1152 + j0], bb1 = sPar[1152 + j0 + 1];
            const float w0 = sWqk[e * 128 + j0], w1 = sWqk[e * 128 + j0 + 1];
            pd0 += ((sl[i2 * 4 + 0] - mu_[0]) * rs_[0] * g0 + bb0) * w0
                 + ((sl[i2 * 4 + 1] - mu_[0]) * rs_[0] * g1 + bb1) * w1;
            pd1 += ((sl[i2 * 4 + 2] - mu_[1]) * rs_[1] * g0 + bb0) * w0
                 + ((sl[i2 * 4 + 3] - mu_[1]) * rs_[1] * g1 + bb1) * w1;
        }
        pd0 += __shfl_xor_sync(0xffffffffu, pd0, 1);
        pd0 += __shfl_xor_sync(0xffffffffu, pd0, 2);
        pd1 += __shfl_xor_sync(0xffffffffu, pd1, 1);
        pd1 += __shfl_xor_sync(0xffffffffu, pd1, 2);
        const float l0 = pd0 * invscale, l1 = pd1 * invscale;
        float m = fmaxf(l0, l1);
        m = fmaxf(m, __shfl_xor_sync(0xffffffffu, m, 4));
        m = fmaxf(m, __shfl_xor_sync(0xffffffffu, m, 8));
        m = fmaxf(m, __shfl_xor_sync(0xffffffffu, m, 16));
        const float ex0 = __expf(l0 - m), ex1 = __expf(l1 - m);
        float ssum = ex0 + ex1;
        ssum += __shfl_xor_sync(0xffffffffu, ssum, 4);
        ssum += __shfl_xor_sync(0xffffffffu, ssum, 8);
        ssum += __shfl_xor_sync(0xffffffffu, ssum, 16);
        const float a0 = ex0 / ssum, a1 = ex1 / ssum;

        #pragma unroll
        for (int t = 0; t < 32; t++)
            Ah[t] = split_pair(sl[2 * t], sl[2 * t + 1], Al[t]);

        float nv0[32];
        #pragma unroll
        for (int h = 0; h < 2; h++) {
            float aR[32], aZ[32], aN[32];
            #pragma unroll
            for (int i = 0; i < 32; i++) { aR[i] = 0.f; aZ[i] = 0.f; aN[i] = 0.f; }
            PHASE(Ah, Al, aR);
            PHASE(Ah, Al, aZ);
            PHASE(Ah, Al, aN);

            const int cb = 64 * h;
            #pragma unroll
            for (int tl = 0; tl < 16; tl++) {
                const int n = tl >> 1, p2 = tl & 1;
                const int j0 = cb + 8 * n + lc;
                const int tg = 16 * h + tl;
                const float2 hv = unsplit(Ah[tg], Al[tg]);
                const float af = p2 ? a1 : a0;
                #pragma unroll
                for (int c = 0; c < 2; c++) {
                    const int j = j0 + c;
                    const float gr = aR[2 * tl + c] + sPar[384 + j];
                    const float gz = aZ[2 * tl + c] + sPar[512 + j];
                    const float gn = aN[2 * tl + c] + sPar[640 + j];
                    const float rr = sigm(af * sVwih[e * 384 + j] + sPar[j] + gr);
                    const float zz = sigm(af * sVwih[e * 384 + 128 + j] + sPar[128 + j] + gz);
                    const float nn = tanha(af * sVwih[e * 384 + 256 + j] + sPar[256 + j] + rr * gn);
                    const float hh = c ? hv.y : hv.x;
                    const float nv = (1.f - zz) * nn + zz * hh;
                    if (h == 0) nv0[2 * tl + c] = nv;
                    else        sl[32 + 2 * tl + c] = nv;
                }
            }
        }
        #pragma unroll
        for (int t = 0; t < 32; t++) sl[t] = nv0[t];

        #pragma unroll
        for (int p2 = 0; p2 < 2; p2++) {
            float s = 0.f, q = 0.f;
            #pragma unroll
            for (int i2 = 0; i2 < 16; i2++) {
                const float v0 = sl[i2 * 4 + p2 * 2], v1 = sl[i2 * 4 + p2 * 2 + 1];
                s += v0 + v1;  q += v0 * v0 + v1 * v1;
            }
            s += __shfl_xor_sync(0xffffffffu, s, 1);
            s += __shfl_xor_sync(0xffffffffu, s, 2);
            q += __shfl_xor_sync(0xffffffffu, q, 1);
            q += __shfl_xor_sync(0xffffffffu, q, 2);
            mu_[p2] = s * (1.f / 128.f);
            rs_[p2] = rsqrtf(q * (1.f / 128.f) - mu_[p2] * mu_[p2] + 1e-5f);
        }
        #pragma unroll
        for (int t = 0; t < 32; t++) {
            const int i2 = t >> 1, p2 = t & 1;
            const int j0 = 8 * i2 + lc;
            const float v0 = (sl[2 * t] - mu_[p2]) * rs_[p2] * sPar[1280 + j0] + sPar[1408 + j0];
            const float v1 = (sl[2 * t + 1] - mu_[p2]) * rs_[p2] * sPar[1280 + j0 + 1] + sPar[1408 + j0 + 1];
            Ah[t] = split_pair(v0, v1, Al[t]);
        }

        float accM[64];
        #pragma unroll
        for (int i = 0; i < 64; i++) accM[i] = 0.f;
        PHASE(Ah, Al, accM);
        PHASE(Ah, Al, accM + 32);

        #pragma unroll
        for (int t = 0; t < 32; t++) {
            const int i2 = t >> 1;
            const int j0 = 8 * i2 + lc;
            const float v0 = fmaxf(accM[2 * t] + sPar[768 + j0], 0.f);
            const float v1 = fmaxf(accM[2 * t + 1] + sPar[768 + j0 + 1], 0.f);
            Ah[t] = split_pair(v0, v1, Al[t]);
        }

        #pragma unroll
        for (int i = 0; i < 64; i++) accM[i] = 0.f;
        PHASE(Ah, Al, accM);
        PHASE(Ah, Al, accM + 32);

        #pragma unroll
        for (int t = 0; t < 32; t++) {
            const int i2 = t >> 1;
            const int j0 = 8 * i2 + lc;
            sl[2 * t]     += accM[2 * t] + sPar[896 + j0];
            sl[2 * t + 1] += accM[2 * t + 1] + sPar[896 + j0 + 1];
        }
    }

    #pragma unroll
    for (int p2 = 0; p2 < 2; p2++) {
        float q = 0.f;
        #pragma unroll
        for (int i2 = 0; i2 < 16; i2++) {
            const float v0 = sl[i2 * 4 + p2 * 2], v1 = sl[i2 * 4 + p2 * 2 + 1];
            q += v0 * v0 + v1 * v1;
        }
        q += __shfl_xor_sync(0xffffffffu, q, 1);
        q += __shfl_xor_sync(0xffffffffu, q, 2);
        const float inv = 1.f / fmaxf(sqrtf(q), 1e-8f);
        float* dst = out + (blk * 8 + e) * (NS * DD) + (lq + 8 * p2) * DD;
        #pragma unroll
        for (int i2 = 0; i2 < 16; i2++) {
            float2 v;
            v.x = sl[i2 * 4 + p2 * 2] * inv;
            v.y = sl[i2 * 4 + p2 * 2 + 1] * inv;
            *(float2*)(dst + 8 * i2 + lc) = v;
        }
    }
#undef PHASE
}

// ---------------------------------------------------------------------------
// Kernel 3: temporal blend via mma.sync (proven R14/R15, unchanged)
// ---------------------------------------------------------------------------
#define TSMEM 73728

__global__ __launch_bounds__(256) void temporal_mma(float* __restrict__ out)
{
    extern __shared__ __align__(16) char tdyn[];
    const int tid = threadIdx.x, lane = tid & 31, warp = tid >> 5;
    const long b = (long)blockIdx.x * 8 + warp;
    const int lq = lane >> 2, lc = (lane & 3) * 2;

    for (int i = tid; i < 4608; i += 256)
        ((uint4*)tdyn)[i] = ((const uint4*)gWtB)[i];
    __syncthreads();
    const u32 base = smem_u32(tdyn);
    const u32 bLane = (u32)((lane & 15) * 144 + ((lane >> 4) & 1) * 16);

    float* b0 = out + b * 64 * (NS * DD);

    float sl[64];
    #pragma unroll
    for (int i2 = 0; i2 < 16; i2++)
        #pragma unroll
        for (int p2 = 0; p2 < 2; p2++) {
            const float2 v = *(const float2*)(b0 + (lq + 8 * p2) * DD + 8 * i2 + lc);
            sl[i2 * 4 + p2 * 2 + 0] = v.x;
            sl[i2 * 4 + p2 * 2 + 1] = v.y;
        }

    u32 Ah[32], Al[32];
    for (int t = 1; t < 64; t++) {
        #pragma unroll
        for (int q = 0; q < 32; q++)
            Ah[q] = split_pair(sl[2 * q], sl[2 * q + 1], Al[q]);

        float acc[64];
        #pragma unroll
        for (int i = 0; i < 64; i++) acc[i] = 0.f;
        gemm_blk2<true >(Ah, Al, base + 0u * 18432u + bLane, acc);
        gemm_blk2<false>(Ah, Al, base + 1u * 18432u + bLane, acc);
        gemm_blk2<true >(Ah, Al, base + 2u * 18432u + bLane, acc + 32);
        gemm_blk2<false>(Ah, Al, base + 3u * 18432u + bLane, acc + 32);

        float* cur = b0 + t * (NS * DD);
        #pragma unroll
        for (int q = 0; q < 32; q++) {
            const int i2 = q >> 1, p2 = q & 1;
            float* p = cur + (lq + 8 * p2) * DD + 8 * i2 + lc;
            const float2 c = *(const float2*)p;
            float2 v;
            v.x = 0.7f * c.x + 0.3f * tanha(acc[2 * q]);
            v.y = 0.7f * c.y + 0.3f * tanha(acc[2 * q + 1]);
            *(float2*)p = v;
            sl[2 * q] = v.x;
            sl[2 * q + 1] = v.y;
        }
    }
}

// ---------------------------------------------------------------------------
extern "C" void kernel_launch(void* const* d_in, const int* in_sizes, int n_in,
                              void* d_out, int out_size)
{
    const float* obs   = (const float*)d_in[0];
    const float* eW1   = (const float*)d_in[1];
    const float* eb1   = (const float*)d_in[2];
    const float* eW2   = (const float*)d_in[3];
    const float* eb2   = (const float*)d_in[4];
    const float* skipW = (const float*)d_in[5];
    const float* smu   = (const float*)d_in[6];
    const float* Wk    = (const float*)d_in[7];
    const float* Wv    = (const float*)d_in[8];
    const float* Wq    = (const float*)d_in[9];
    const float* gWih  = (const float*)d_in[10];
    const float* gWhh  = (const float*)d_in[11];
    const float* gbih  = (const float*)d_in[12];
    const float* gbhh  = (const float*)d_in[13];
    const float* mW1   = (const float*)d_in[14];
    const float* mb1   = (const float*)d_in[15];
    const float* mW2   = (const float*)d_in[16];
    const float* mb2   = (const float*)d_in[17];
    const float* lin_g = (const float*)d_in[18];
    const float* lin_b = (const float*)d_in[19];
    const float* lsl_g = (const float*)d_in[20];
    const float* lsl_b = (const float*)d_in[21];
    const float* lml_g = (const float*)d_in[22];
    const float* lml_b = (const float*)d_in[23];
    const float* Wt    = (const float*)d_in[24];
    float* out = (float*)d_out;

    static int init_done = 0;
    if (!init_done) {
        cudaFuncSetAttribute(slot_mma, cudaFuncAttributeMaxDynamicSharedMemorySize, SMEM_DYN);
        cudaFuncSetAttribute(temporal_mma, cudaFuncAttributeMaxDynamicSharedMemorySize, TSMEM);
        cudaFuncSetAttribute(encpro_mma, cudaFuncAttributeMaxDynamicSharedMemorySize, ESMEM);
        init_done = 1;
    }

    pack_all<<<(958464 + 255) / 256, 256>>>(eW1, eW2, skipW, Wk, Wv, Wq,
                                            gWih, gWhh, mW1, mW2, Wt);
    encpro_mma<<<BT / 128, 256, ESMEM>>>(obs, eb1, eb2, lin_g, lin_b);
    slot_mma<<<BT / 8, 256, SMEM_DYN>>>(smu, gbih, gbhh, mb1, mb2,
                                        lsl_g, lsl_b, lml_g, lml_b, out);
    temporal_mma<<<32, 256, TSMEM>>>(out);
}

// round 17
// speedup vs baseline: 6.5143x; 1.0877x over previous
#include <cuda_runtime.h>
#include <cuda_bf16.h>
#include <stdint.h>
#include <math.h>

#define BT 16384
#define DOBS 512
#define DD 128
#define NS 16

typedef unsigned long long u64;
typedef unsigned int u32;
typedef unsigned short u16;

__device__ __forceinline__ float tanha(float x) {
    float y;
    asm("tanh.approx.f32 %0, %1;" : "=f"(y) : "f"(x));
    return y;
}
__device__ __forceinline__ float sigm(float x) { return 0.5f * tanha(0.5f * x) + 0.5f; }

// fast split: hi = truncated top-16 bits (PRMT pack), lo = exact residual (RN bf16x2)
__device__ __forceinline__ u32 split_pair(float v0, float v1, u32& lo_out) {
    const u32 b0 = __float_as_uint(v0), b1 = __float_as_uint(v1);
    u32 hi;
    asm("prmt.b32 %0, %1, %2, 0x7632;" : "=r"(hi) : "r"(b0), "r"(b1));
    const float l0 = v0 - __uint_as_float(b0 & 0xffff0000u);
    const float l1 = v1 - __uint_as_float(b1 & 0xffff0000u);
    asm("cvt.rn.bf16x2.f32 %0, %1, %2;" : "=r"(lo_out) : "f"(l1), "f"(l0));
    return hi;
}
__device__ __forceinline__ float2 unsplit(u32 hi, u32 lo) {
    float2 r;
    r.x = __bfloat162float(__ushort_as_bfloat16((u16)(hi & 0xffff)))
        + __bfloat162float(__ushort_as_bfloat16((u16)(lo & 0xffff)));
    r.y = __bfloat162float(__ushort_as_bfloat16((u16)(hi >> 16)))
        + __bfloat162float(__ushort_as_bfloat16((u16)(lo >> 16)));
    return r;
}

__device__ __forceinline__ u32 smem_u32(const void* p) {
    u32 a;
    asm("{ .reg .u64 t; cvta.to.shared.u64 t, %1; cvt.u32.u64 %0, t; }" : "=r"(a) : "l"(p));
    return a;
}
__device__ __forceinline__ void mma_bf16(float* d, u32 a0, u32 a1, u32 a2, u32 a3,
                                         u32 b0, u32 b1) {
    asm volatile(
        "mma.sync.aligned.m16n8k16.row.col.f32.bf16.bf16.f32 "
        "{%0,%1,%2,%3}, {%4,%5,%6,%7}, {%8,%9}, {%0,%1,%2,%3};"
        : "+f"(d[0]), "+f"(d[1]), "+f"(d[2]), "+f"(d[3])
        : "r"(a0), "r"(a1), "r"(a2), "r"(a3), "r"(b0), "r"(b1));
}
__device__ __forceinline__ void cp16(u32 saddr, const void* g) {
    asm volatile("cp.async.cg.shared.global [%0], [%1], 16;" :: "r"(saddr), "l"(g));
}
#define CP_COMMIT() asm volatile("cp.async.commit_group;" ::: "memory")
#define CP_WAIT1()  asm volatile("cp.async.wait_group 1;" ::: "memory")

// One B block (k=128, n=64, row stride 144B). A fragments from registers.
template<bool DUAL>
__device__ __forceinline__ void gemm_blk2(const u32* Ah, const u32* Al, u32 bAd, float* acc) {
    #pragma unroll
    for (int k = 0; k < 8; k++) {
        #pragma unroll
        for (int q = 0; q < 4; q++) {
            u32 b0, b1, b2, b3;
            asm volatile("ldmatrix.sync.aligned.m8n8.x4.trans.shared.b16 {%0,%1,%2,%3}, [%4];"
                : "=r"(b0), "=r"(b1), "=r"(b2), "=r"(b3) : "r"(bAd + (u32)(k * 2304 + q * 32)));
            mma_bf16(acc + (q * 2) * 4,     Ah[k * 4], Ah[k * 4 + 1], Ah[k * 4 + 2], Ah[k * 4 + 3], b0, b1);
            mma_bf16(acc + (q * 2 + 1) * 4, Ah[k * 4], Ah[k * 4 + 1], Ah[k * 4 + 2], Ah[k * 4 + 3], b2, b3);
            if (DUAL) {
                mma_bf16(acc + (q * 2) * 4,     Al[k * 4], Al[k * 4 + 1], Al[k * 4 + 2], Al[k * 4 + 3], b0, b1);
                mma_bf16(acc + (q * 2 + 1) * 4, Al[k * 4], Al[k * 4 + 1], Al[k * 4 + 2], Al[k * 4 + 3], b2, b3);
            }
        }
    }
}

// Half-width variant: 2 n-tiles (32 cols), acc[16].
template<bool DUAL>
__device__ __forceinline__ void gemm_half2(const u32* Ah, const u32* Al, u32 bAd, float* acc) {
    #pragma unroll
    for (int k = 0; k < 8; k++) {
        #pragma unroll
        for (int q = 0; q < 2; q++) {
            u32 b0, b1, b2, b3;
            asm volatile("ldmatrix.sync.aligned.m8n8.x4.trans.shared.b16 {%0,%1,%2,%3}, [%4];"
                : "=r"(b0), "=r"(b1), "=r"(b2), "=r"(b3) : "r"(bAd + (u32)(k * 2304 + q * 32)));
            mma_bf16(acc + (q * 2) * 4,     Ah[k * 4], Ah[k * 4 + 1], Ah[k * 4 + 2], Ah[k * 4 + 3], b0, b1);
            mma_bf16(acc + (q * 2 + 1) * 4, Ah[k * 4], Ah[k * 4 + 1], Ah[k * 4 + 2], Ah[k * 4 + 3], b2, b3);
            if (DUAL) {
                mma_bf16(acc + (q * 2) * 4,     Al[k * 4], Al[k * 4 + 1], Al[k * 4 + 2], Al[k * 4 + 3], b0, b1);
                mma_bf16(acc + (q * 2 + 1) * 4, Al[k * 4], Al[k * 4 + 1], Al[k * 4 + 2], Al[k * 4 + 3], b2, b3);
            }
        }
    }
}

// ---------------- device scratch ----------------
__device__ float g_wqk[BT * DD];
__device__ float g_vwih[BT * 384];

__device__ u16 gBall[20 * 9216];
__device__ u16 gWtB[4 * 9216];
__device__ u16 gBenc[40 * 18432];

__device__ __forceinline__ u16 bf_hi(float w) {
    return (u16)(__float_as_uint(w) >> 16);
}
__device__ __forceinline__ u16 bf_lo(float w) {
    float hf = __uint_as_float(__float_as_uint(w) & 0xffff0000u);
    return __bfloat16_as_ushort(__float2bfloat16(w - hf));
}

__global__ __launch_bounds__(256) void pack_all(
    const float* __restrict__ eW1, const float* __restrict__ eW2, const float* __restrict__ skipW,
    const float* __restrict__ Wk, const float* __restrict__ Wv, const float* __restrict__ Wq,
    const float* __restrict__ gWih, const float* __restrict__ gWhh,
    const float* __restrict__ mW1, const float* __restrict__ mW2, const float* __restrict__ Wt)
{
    int idx = blockIdx.x * 256 + threadIdx.x;
    if (idx < 184320) {
        const int b = idx / 9216, r = idx % 9216;
        const int k = r / 72, n = r % 72;
        float w = 0.f;
        int s;
        if (b < 12) {
            const int half = b / 6, rem = b % 6, g = rem >> 1;
            s = rem & 1;
            if (n < 64) w = gWhh[k * 384 + g * 128 + half * 64 + n];
        } else {
            const int bb = b - 12, m = bb >> 2, half = (bb >> 1) & 1;
            s = bb & 1;
            if (n < 64) w = (m ? mW2 : mW1)[k * 128 + half * 64 + n];
        }
        gBall[idx] = s ? bf_lo(w) : bf_hi(w);
        return;
    }
    idx -= 184320;
    if (idx < 36864) {
        const int b = idx / 9216, r = idx % 9216;
        const int half = b >> 1, s = b & 1;
        const int k = r / 72, n = r % 72;
        float w = (n < 64) ? Wt[k * 128 + half * 64 + n] : 0.f;
        gWtB[idx] = s ? bf_lo(w) : bf_hi(w);
        return;
    }
    idx -= 36864;
    if (idx < 737280) {
        const int p = idx / 18432, r2 = idx % 18432;
        const int s = r2 / 9216, r = r2 % 9216;
        const int k = r / 72, n = r % 72;
        float w = 0.f;
        if (n < 64) {
            if (p < 16) {
                const int grp = p >> 3, pp = p & 7, kc = pp >> 1, nh = pp & 1;
                w = eW1[(kc * 128 + k) * 256 + grp * 128 + nh * 64 + n];
            } else if (p < 20) {
                const int q = p - 16, kc = q & 1, nh = q >> 1;
                w = eW2[(kc * 128 + k) * 128 + nh * 64 + n];
            } else if (p < 28) {
                const int q = p - 20, kc = q >> 1, nh = q & 1;
                w = skipW[(kc * 128 + k) * 128 + nh * 64 + n];
            } else if (p < 30) {
                w = Wk[k * 128 + (p - 28) * 64 + n];
            } else if (p < 32) {
                w = Wv[k * 128 + (p - 30) * 64 + n];
            } else if (p < 34) {
                w = Wq[((p - 32) * 64 + n) * 128 + k];
            } else {
                w = gWih[k * 384 + (p - 34) * 64 + n];
            }
        }
        gBenc[idx] = s ? bf_lo(w) : bf_hi(w);
    }
}

__device__ __forceinline__ void build_obs(const float* __restrict__ orow0, int kc,
                                          int lq, int lc, u32* Oh, u32* Ol)
{
    #pragma unroll
    for (int kt = 0; kt < 8; kt++) {
        const int kb = kc * 128 + kt * 16;
        const float2 a = *(const float2*)(orow0 + lq * DOBS + kb + lc);
        const float2 b = *(const float2*)(orow0 + (lq + 8) * DOBS + kb + lc);
        const float2 c = *(const float2*)(orow0 + lq * DOBS + kb + 8 + lc);
        const float2 d = *(const float2*)(orow0 + (lq + 8) * DOBS + kb + 8 + lc);
        Oh[kt * 4 + 0] = split_pair(a.x, a.y, Ol[kt * 4 + 0]);
        Oh[kt * 4 + 1] = split_pair(b.x, b.y, Ol[kt * 4 + 1]);
        Oh[kt * 4 + 2] = split_pair(c.x, c.y, Ol[kt * 4 + 2]);
        Oh[kt * 4 + 3] = split_pair(d.x, d.y, Ol[kt * 4 + 3]);
    }
}

// ---------------------------------------------------------------------------
// Kernel 1: fused encoder + prologue (proven R16, unchanged)
// ---------------------------------------------------------------------------
#define ESMEM 113664

__global__ __launch_bounds__(256) void encpro_mma(
    const float* __restrict__ obs,
    const float* __restrict__ eb1, const float* __restrict__ eb2,
    const float* __restrict__ lin_g, const float* __restrict__ lin_b)
{
    extern __shared__ __align__(16) char edyn[];
    float* sPar = (float*)(edyn + 110592);

    const int tid = threadIdx.x, lane = tid & 31, warp = tid >> 5;
    const int lq = lane >> 2, lc = (lane & 3) * 2;
    const long ent0 = (long)blockIdx.x * 128 + warp * 16;
    const u32 ring = smem_u32(edyn);

    {
        const char* s0 = (const char*)gBenc;
        for (int i = tid; i < 2304; i += 256) cp16(ring + (u32)i * 16, s0 + i * 16);
        CP_COMMIT();
        const char* s1 = (const char*)gBenc + 36864;
        for (int i = tid; i < 2304; i += 256) cp16(ring + 36864u + (u32)i * 16, s1 + i * 16);
        CP_COMMIT();
    }
    if (tid < 256) sPar[tid] = eb1[tid];
    if (tid < 128) {
        sPar[256 + tid] = eb2[tid];
        sPar[384 + tid] = lin_g[tid];
        sPar[512 + tid] = lin_b[tid];
    }
    __syncthreads();

    const u32 bLane = (u32)((lane & 15) * 144 + ((lane >> 4) & 1) * 16);
    int fb = 2, fs = 2, cs = 0;

#define EPHASE(AHP, ALP, ACC) do { \
    CP_WAIT1(); \
    __syncthreads(); \
    { const char* _s = (const char*)gBenc + fb * 36864; \
      u32 _d = ring + (u32)fs * 36864u; \
      for (int _i = tid; _i < 2304; _i += 256) cp16(_d + (u32)_i * 16, _s + _i * 16); \
      CP_COMMIT(); \
      fb++; if (fb == 40) fb = 0; \
      fs++; if (fs == 3) fs = 0; } \
    { const u32 _b = ring + (u32)cs * 36864u + bLane; \
      gemm_blk2<true>(AHP, ALP, _b, ACC); \
      gemm_blk2<false>(AHP, ALP, _b + 18432u, ACC); } \
    cs++; if (cs == 3) cs = 0; \
} while (0)

    const float* orow0 = obs + ent0 * DOBS;
    u32 Oh[32], Ol[32], A1h[32], A1l[32], A2h[32], A2l[32];
    float acc[64];

    #pragma unroll
    for (int i = 0; i < 64; i++) acc[i] = 0.f;
    for (int kc = 0; kc < 4; kc++) {
        build_obs(orow0, kc, lq, lc, Oh, Ol);
        EPHASE(Oh, Ol, acc);
        EPHASE(Oh, Ol, acc + 32);
    }
    #pragma unroll
    for (int t = 0; t < 32; t++) {
        const int j0 = 8 * (t >> 1) + lc;
        float v0 = acc[2 * t] + sPar[j0];
        float v1 = acc[2 * t + 1] + sPar[j0 + 1];
        v0 = 0.5f * v0 * (1.f + erff(v0 * 0.70710678118654752f));
        v1 = 0.5f * v1 * (1.f + erff(v1 * 0.70710678118654752f));
        A1h[t] = split_pair(v0, v1, A1l[t]);
    }
    #pragma unroll
    for (int i = 0; i < 64; i++) acc[i] = 0.f;
    for (int kc = 0; kc < 4; kc++) {
        build_obs(orow0, kc, lq, lc, Oh, Ol);
        EPHASE(Oh, Ol, acc);
        EPHASE(Oh, Ol, acc + 32);
    }
    #pragma unroll
    for (int t = 0; t < 32; t++) {
        const int j0 = 8 * (t >> 1) + lc;
        float v0 = acc[2 * t] + sPar[128 + j0];
        float v1 = acc[2 * t + 1] + sPar[128 + j0 + 1];
        v0 = 0.5f * v0 * (1.f + erff(v0 * 0.70710678118654752f));
        v1 = 0.5f * v1 * (1.f + erff(v1 * 0.70710678118654752f));
        A2h[t] = split_pair(v0, v1, A2l[t]);
    }
    #pragma unroll
    for (int i = 0; i < 64; i++) acc[i] = 0.f;
    EPHASE(A1h, A1l, acc);       EPHASE(A2h, A2l, acc);
    EPHASE(A1h, A1l, acc + 32);  EPHASE(A2h, A2l, acc + 32);
    for (int kc = 0; kc < 4; kc++) {
        build_obs(orow0, kc, lq, lc, Oh, Ol);
        EPHASE(Oh, Ol, acc);
        EPHASE(Oh, Ol, acc + 32);
    }
    float z[64];
    #pragma unroll
    for (int t = 0; t < 32; t++) {
        const int j0 = 8 * (t >> 1) + lc;
        z[2 * t]     = tanha(acc[2 * t] + sPar[256 + j0]);
        z[2 * t + 1] = tanha(acc[2 * t + 1] + sPar[256 + j0 + 1]);
    }
    float mu_[2], rs_[2];
    #pragma unroll
    for (int p2 = 0; p2 < 2; p2++) {
        float s = 0.f, q = 0.f;
        #pragma unroll
        for (int i2 = 0; i2 < 16; i2++) {
            const float v0 = z[i2 * 4 + p2 * 2], v1 = z[i2 * 4 + p2 * 2 + 1];
            s += v0 + v1;  q += v0 * v0 + v1 * v1;
        }
        s += __shfl_xor_sync(0xffffffffu, s, 1);
        s += __shfl_xor_sync(0xffffffffu, s, 2);
        q += __shfl_xor_sync(0xffffffffu, q, 1);
        q += __shfl_xor_sync(0xffffffffu, q, 2);
        mu_[p2] = s * (1.f / 128.f);
        rs_[p2] = rsqrtf(q * (1.f / 128.f) - mu_[p2] * mu_[p2] + 1e-5f);
    }
    #pragma unroll
    for (int t = 0; t < 32; t++) {
        const int p2 = t & 1;
        const int j0 = 8 * (t >> 1) + lc;
        const float v0 = (z[2 * t] - mu_[p2]) * rs_[p2] * sPar[384 + j0] + sPar[512 + j0];
        const float v1 = (z[2 * t + 1] - mu_[p2]) * rs_[p2] * sPar[384 + j0 + 1] + sPar[512 + j0 + 1];
        A1h[t] = split_pair(v0, v1, A1l[t]);
    }
    #pragma unroll
    for (int i = 0; i < 64; i++) acc[i] = 0.f;
    EPHASE(A1h, A1l, acc);  EPHASE(A1h, A1l, acc + 32);
    #pragma unroll
    for (int t = 0; t < 32; t++)
        A2h[t] = split_pair(acc[2 * t], acc[2 * t + 1], A2l[t]);
    #pragma unroll
    for (int i = 0; i < 64; i++) acc[i] = 0.f;
    EPHASE(A1h, A1l, acc);  EPHASE(A1h, A1l, acc + 32);
    #pragma unroll
    for (int t = 0; t < 32; t++)
        Oh[t] = split_pair(acc[2 * t], acc[2 * t + 1], Ol[t]);
    #pragma unroll
    for (int i = 0; i < 64; i++) acc[i] = 0.f;
    EPHASE(A2h, A2l, acc);  EPHASE(A2h, A2l, acc + 32);
    #pragma unroll
    for (int t = 0; t < 32; t++) {
        const int row = lq + 8 * (t & 1);
        const int j0 = 8 * (t >> 1) + lc;
        float2 v;  v.x = acc[2 * t];  v.y = acc[2 * t + 1];
        *(float2*)(g_wqk + (ent0 + row) * 128 + j0) = v;
    }
    for (int h6 = 0; h6 < 6; h6++) {
        #pragma unroll
        for (int i = 0; i < 32; i++) acc[i] = 0.f;
        EPHASE(Oh, Ol, acc);
        #pragma unroll
        for (int t = 0; t < 16; t++) {
            const int row = lq + 8 * (t & 1);
            const int col = 8 * (t >> 1) + lc;
            float2 v;  v.x = acc[2 * t];  v.y = acc[2 * t + 1];
            *(float2*)(g_vwih + (ent0 + row) * 384 + h6 * 64 + col) = v;
        }
    }
#undef EPHASE
}

// ---------------------------------------------------------------------------
// Kernel 2: register-resident mma.sync slot attention (proven R15, unchanged)
// ---------------------------------------------------------------------------
#define SMEM_DYN 133120

__global__ __launch_bounds__(256) void slot_mma(
    const float* __restrict__ slot_mu,
    const float* __restrict__ bih, const float* __restrict__ bhh,
    const float* __restrict__ mb1, const float* __restrict__ mb2,
    const float* __restrict__ lsl_g, const float* __restrict__ lsl_b,
    const float* __restrict__ lml_g, const float* __restrict__ lml_b,
    float* __restrict__ out)
{
    extern __shared__ __align__(16) char dyn[];
    float* sWqk  = (float*)(dyn + 110592);
    float* sVwih = (float*)(dyn + 114688);
    float* sPar  = (float*)(dyn + 126976);

    const int tid = threadIdx.x, lane = tid & 31, warp = tid >> 5;
    const int e = warp;
    const int lq = lane >> 2, lc = (lane & 3) * 2;
    const long blk = blockIdx.x;
    const float invscale = 0.088388347648318447f;
    const u32 ring = smem_u32(dyn);

    {
        const char* s0 = (const char*)gBall;
        for (int i = tid; i < 2304; i += 256) cp16(ring + (u32)i * 16, s0 + i * 16);
        CP_COMMIT();
        const char* s1 = (const char*)gBall + 36864;
        for (int i = tid; i < 2304; i += 256) cp16(ring + 36864u + (u32)i * 16, s1 + i * 16);
        CP_COMMIT();
    }

    for (int i = tid; i < 384; i += 256) { sPar[i] = bih[i]; sPar[384 + i] = bhh[i]; }
    if (tid < 128) {
        sPar[768 + tid] = mb1[tid];  sPar[896 + tid] = mb2[tid];
        sPar[1024 + tid] = lsl_g[tid]; sPar[1152 + tid] = lsl_b[tid];
        sPar[1280 + tid] = lml_g[tid]; sPar[1408 + tid] = lml_b[tid];
    }
    for (int i = tid; i < 8 * 384; i += 256) sVwih[i] = g_vwih[blk * (8 * 384) + i];
    for (int i = tid; i < 8 * 128; i += 256) sWqk[i] = g_wqk[blk * (8 * 128) + i];

    float sl[64];
    #pragma unroll
    for (int i2 = 0; i2 < 16; i2++)
        #pragma unroll
        for (int p2 = 0; p2 < 2; p2++) {
            const float* src = slot_mu + (lq + 8 * p2) * DD + 8 * i2 + lc;
            sl[i2 * 4 + p2 * 2 + 0] = src[0];
            sl[i2 * 4 + p2 * 2 + 1] = src[1];
        }

    __syncthreads();

    const u32 bLane = (u32)((lane & 15) * 144 + ((lane >> 4) & 1) * 16);
    int fb = 2, fs = 2, cs = 0;

#define PHASE(AHP, ALP, ACC) do { \
    CP_WAIT1(); \
    __syncthreads(); \
    { const char* _s = (const char*)gBall + fb * 36864; \
      u32 _d = ring + (u32)fs * 36864u; \
      for (int _i = tid; _i < 2304; _i += 256) cp16(_d + (u32)_i * 16, _s + _i * 16); \
      CP_COMMIT(); \
      fb++; if (fb == 10) fb = 0; \
      fs++; if (fs == 3) fs = 0; } \
    { const u32 _b = ring + (u32)cs * 36864u + bLane; \
      gemm_blk2<true>(AHP, ALP, _b, ACC); \
      gemm_blk2<false>(AHP, ALP, _b + 18432u, ACC); } \
    cs++; if (cs == 3) cs = 0; \
} while (0)

    u32 Ah[32], Al[32];

    for (int it = 0; it < 3; it++) {
        float mu_[2], rs_[2];
        #pragma unroll
        for (int p2 = 0; p2 < 2; p2++) {
            float s = 0.f, q = 0.f;
            #pragma unroll
            for (int i2 = 0; i2 < 16; i2++) {
                const float v0 = sl[i2 * 4 + p2 * 2], v1 = sl[i2 * 4 + p2 * 2 + 1];
                s += v0 + v1;  q += v0 * v0 + v1 * v1;
            }
            s += __shfl_xor_sync(0xffffffffu, s, 1);
            s += __shfl_xor_sync(0xffffffffu, s, 2);
            q += __shfl_xor_sync(0xffffffffu, q, 1);
            q += __shfl_xor_sync(0xffffffffu, q, 2);
            mu_[p2] = s * (1.f / 128.f);
            rs_[p2] = rsqrtf(q * (1.f / 128.f) - mu_[p2] * mu_[p2] + 1e-5f);
        }
        float pd0 = 0.f, pd1 = 0.f;
        #pragma unroll
        for (int i2 = 0; i2 < 16; i2++) {
            const int j0 = 8 * i2 + lc;
            const float g0 = sPar[1024 + j0], g1 = sPar[1024 + j0 + 1];
            const float bb0 = sPar[1152 + j0], bb1 = sPar[1152 + j0 + 1];
            const float w0 = sWqk[e * 128 + j0], w1 = sWqk[e * 128 + j0 + 1];
            pd0 += ((sl[i2 * 4 + 0] - mu_[0]) * rs_[0] * g0 + bb0) * w0
                 + ((sl[i2 * 4 + 1] - mu_[0]) * rs_[0] * g1 + bb1) * w1;
            pd1 += ((sl[i2 * 4 + 2] - mu_[1]) * rs_[1] * g0 + bb0) * w0
                 + ((sl[i2 * 4 + 3] - mu_[1]) * rs_[1] * g1 + bb1) * w1;
        }
        pd0 += __shfl_xor_sync(0xffffffffu, pd0, 1);
        pd0 += __shfl_xor_sync(0xffffffffu, pd0, 2);
        pd1 += __shfl_xor_sync(0xffffffffu, pd1, 1);
        pd1 += __shfl_xor_sync(0xffffffffu, pd1, 2);
        const float l0 = pd0 * invscale, l1 = pd1 * invscale;
        float m = fmaxf(l0, l1);
        m = fmaxf(m, __shfl_xor_sync(0xffffffffu, m, 4));
        m = fmaxf(m, __shfl_xor_sync(0xffffffffu, m, 8));
        m = fmaxf(m, __shfl_xor_sync(0xffffffffu, m, 16));
        const float ex0 = __expf(l0 - m), ex1 = __expf(l1 - m);
        float ssum = ex0 + ex1;
        ssum += __shfl_xor_sync(0xffffffffu, ssum, 4);
        ssum += __shfl_xor_sync(0xffffffffu, ssum, 8);
        ssum += __shfl_xor_sync(0xffffffffu, ssum, 16);
        const float a0 = ex0 / ssum, a1 = ex1 / ssum;

        #pragma unroll
        for (int t = 0; t < 32; t++)
            Ah[t] = split_pair(sl[2 * t], sl[2 * t + 1], Al[t]);

        float nv0[32];
        #pragma unroll
        for (int h = 0; h < 2; h++) {
            float aR[32], aZ[32], aN[32];
            #pragma unroll
            for (int i = 0; i < 32; i++) { aR[i] = 0.f; aZ[i] = 0.f; aN[i] = 0.f; }
            PHASE(Ah, Al, aR);
            PHASE(Ah, Al, aZ);
            PHASE(Ah, Al, aN);

            const int cb = 64 * h;
            #pragma unroll
            for (int tl = 0; tl < 16; tl++) {
                const int n = tl >> 1, p2 = tl & 1;
                const int j0 = cb + 8 * n + lc;
                const int tg = 16 * h + tl;
                const float2 hv = unsplit(Ah[tg], Al[tg]);
                const float af = p2 ? a1 : a0;
                #pragma unroll
                for (int c = 0; c < 2; c++) {
                    const int j = j0 + c;
                    const float gr = aR[2 * tl + c] + sPar[384 + j];
                    const float gz = aZ[2 * tl + c] + sPar[512 + j];
                    const float gn = aN[2 * tl + c] + sPar[640 + j];
                    const float rr = sigm(af * sVwih[e * 384 + j] + sPar[j] + gr);
                    const float zz = sigm(af * sVwih[e * 384 + 128 + j] + sPar[128 + j] + gz);
                    const float nn = tanha(af * sVwih[e * 384 + 256 + j] + sPar[256 + j] + rr * gn);
                    const float hh = c ? hv.y : hv.x;
                    const float nv = (1.f - zz) * nn + zz * hh;
                    if (h == 0) nv0[2 * tl + c] = nv;
                    else        sl[32 + 2 * tl + c] = nv;
                }
            }
        }
        #pragma unroll
        for (int t = 0; t < 32; t++) sl[t] = nv0[t];

        #pragma unroll
        for (int p2 = 0; p2 < 2; p2++) {
            float s = 0.f, q = 0.f;
            #pragma unroll
            for (int i2 = 0; i2 < 16; i2++) {
                const float v0 = sl[i2 * 4 + p2 * 2], v1 = sl[i2 * 4 + p2 * 2 + 1];
                s += v0 + v1;  q += v0 * v0 + v1 * v1;
            }
            s += __shfl_xor_sync(0xffffffffu, s, 1);
            s += __shfl_xor_sync(0xffffffffu, s, 2);
            q += __shfl_xor_sync(0xffffffffu, q, 1);
            q += __shfl_xor_sync(0xffffffffu, q, 2);
            mu_[p2] = s * (1.f / 128.f);
            rs_[p2] = rsqrtf(q * (1.f / 128.f) - mu_[p2] * mu_[p2] + 1e-5f);
        }
        #pragma unroll
        for (int t = 0; t < 32; t++) {
            const int i2 = t >> 1, p2 = t & 1;
            const int j0 = 8 * i2 + lc;
            const float v0 = (sl[2 * t] - mu_[p2]) * rs_[p2] * sPar[1280 + j0] + sPar[1408 + j0];
            const float v1 = (sl[2 * t + 1] - mu_[p2]) * rs_[p2] * sPar[1280 + j0 + 1] + sPar[1408 + j0 + 1];
            Ah[t] = split_pair(v0, v1, Al[t]);
        }

        float accM[64];
        #pragma unroll
        for (int i = 0; i < 64; i++) accM[i] = 0.f;
        PHASE(Ah, Al, accM);
        PHASE(Ah, Al, accM + 32);

        #pragma unroll
        for (int t = 0; t < 32; t++) {
            const int i2 = t >> 1;
            const int j0 = 8 * i2 + lc;
            const float v0 = fmaxf(accM[2 * t] + sPar[768 + j0], 0.f);
            const float v1 = fmaxf(accM[2 * t + 1] + sPar[768 + j0 + 1], 0.f);
            Ah[t] = split_pair(v0, v1, Al[t]);
        }

        #pragma unroll
        for (int i = 0; i < 64; i++) accM[i] = 0.f;
        PHASE(Ah, Al, accM);
        PHASE(Ah, Al, accM + 32);

        #pragma unroll
        for (int t = 0; t < 32; t++) {
            const int i2 = t >> 1;
            const int j0 = 8 * i2 + lc;
            sl[2 * t]     += accM[2 * t] + sPar[896 + j0];
            sl[2 * t + 1] += accM[2 * t + 1] + sPar[896 + j0 + 1];
        }
    }

    #pragma unroll
    for (int p2 = 0; p2 < 2; p2++) {
        float q = 0.f;
        #pragma unroll
        for (int i2 = 0; i2 < 16; i2++) {
            const float v0 = sl[i2 * 4 + p2 * 2], v1 = sl[i2 * 4 + p2 * 2 + 1];
            q += v0 * v0 + v1 * v1;
        }
        q += __shfl_xor_sync(0xffffffffu, q, 1);
        q += __shfl_xor_sync(0xffffffffu, q, 2);
        const float inv = 1.f / fmaxf(sqrtf(q), 1e-8f);
        float* dst = out + (blk * 8 + e) * (NS * DD) + (lq + 8 * p2) * DD;
        #pragma unroll
        for (int i2 = 0; i2 < 16; i2++) {
            float2 v;
            v.x = sl[i2 * 4 + p2 * 2] * inv;
            v.y = sl[i2 * 4 + p2 * 2 + 1] * inv;
            *(float2*)(dst + 8 * i2 + lc) = v;
        }
    }
#undef PHASE
}

// ---------------------------------------------------------------------------
// Kernel 3: temporal blend — 4-way n-split. 128 CTAs x 8 warps; CTA owns 2
// batches; warp (bl = warp>>2, q4 = warp&3) computes 32 cols of batch bl.
// State in ping-pong smem buffers; one barrier per step.
// ---------------------------------------------------------------------------
#define TSMEM 106496

__global__ __launch_bounds__(256) void temporal_mma(float* __restrict__ out)
{
    extern __shared__ __align__(16) char tdyn[];
    float* sSl = (float*)(tdyn + 73728);   // [2 bufs][2 batches][2048]
    const int tid = threadIdx.x, lane = tid & 31, warp = tid >> 5;
    const int bl = warp >> 2, q4 = warp & 3;
    const int lq = lane >> 2, lc = (lane & 3) * 2;
    const long b = (long)blockIdx.x * 2 + bl;

    // load Wt B blocks
    for (int i = tid; i < 4608; i += 256)
        ((uint4*)tdyn)[i] = ((const uint4*)gWtB)[i];
    // init state buffer 0 (t=0 slots of both batches)
    for (int i = tid; i < 4096; i += 256) {
        const int batch_l = i >> 11, el = i & 2047;
        sSl[batch_l * 2048 + el] =
            out[((long)blockIdx.x * 2 + batch_l) * 64 * (NS * DD) + el];
    }
    __syncthreads();

    const u32 base = smem_u32(tdyn);
    const u32 bLane = (u32)((lane & 15) * 144 + ((lane >> 4) & 1) * 16 + (q4 & 1) * 64);
    const u32 hiB = base + (u32)(q4 >> 1) * 2u * 18432u + bLane;
    const u32 loB = hiB + 18432u;

    float* b0 = out + b * 64 * (NS * DD);
    u32 Ah[32], Al[32];

    for (int t = 1; t < 64; t++) {
        const float* src = sSl + ((t - 1) & 1) * 4096 + bl * 2048;
        // build A fragments from full-K state
        #pragma unroll
        for (int k = 0; k < 8; k++) {
            const float2 a = *(const float2*)(src + lq * 128 + k * 16 + lc);
            const float2 bb = *(const float2*)(src + (lq + 8) * 128 + k * 16 + lc);
            const float2 c = *(const float2*)(src + lq * 128 + k * 16 + 8 + lc);
            const float2 d = *(const float2*)(src + (lq + 8) * 128 + k * 16 + 8 + lc);
            Ah[k * 4 + 0] = split_pair(a.x, a.y, Al[k * 4 + 0]);
            Ah[k * 4 + 1] = split_pair(bb.x, bb.y, Al[k * 4 + 1]);
            Ah[k * 4 + 2] = split_pair(c.x, c.y, Al[k * 4 + 2]);
            Ah[k * 4 + 3] = split_pair(d.x, d.y, Al[k * 4 + 3]);
        }
        float acc[16];
        #pragma unroll
        for (int i = 0; i < 16; i++) acc[i] = 0.f;
        gemm_half2<true >(Ah, Al, hiB, acc);
        gemm_half2<false>(Ah, Al, loB, acc);

        float* cur = b0 + t * (NS * DD);
        float* dstS = sSl + (t & 1) * 4096 + bl * 2048;
        #pragma unroll
        for (int g8 = 0; g8 < 4; g8++) {
            const int nb = q4 * 32 + (g8 >> 1) * 16 + (g8 & 1) * 8;
            #pragma unroll
            for (int rh = 0; rh < 2; rh++) {
                const int off = (lq + 8 * rh) * 128 + nb + lc;
                const float2 c = *(const float2*)(cur + off);
                float2 v;
                v.x = 0.7f * c.x + 0.3f * tanha(acc[g8 * 4 + rh * 2]);
                v.y = 0.7f * c.y + 0.3f * tanha(acc[g8 * 4 + rh * 2 + 1]);
                *(float2*)(cur + off) = v;
                *(float2*)(dstS + off) = v;
            }
        }
        __syncthreads();
    }
}

// ---------------------------------------------------------------------------
extern "C" void kernel_launch(void* const* d_in, const int* in_sizes, int n_in,
                              void* d_out, int out_size)
{
    const float* obs   = (const float*)d_in[0];
    const float* eW1   = (const float*)d_in[1];
    const float* eb1   = (const float*)d_in[2];
    const float* eW2   = (const float*)d_in[3];
    const float* eb2   = (const float*)d_in[4];
    const float* skipW = (const float*)d_in[5];
    const float* smu   = (const float*)d_in[6];
    const float* Wk    = (const float*)d_in[7];
    const float* Wv    = (const float*)d_in[8];
    const float* Wq    = (const float*)d_in[9];
    const float* gWih  = (const float*)d_in[10];
    const float* gWhh  = (const float*)d_in[11];
    const float* gbih  = (const float*)d_in[12];
    const float* gbhh  = (const float*)d_in[13];
    const float* mW1   = (const float*)d_in[14];
    const float* mb1   = (const float*)d_in[15];
    const float* mW2   = (const float*)d_in[16];
    const float* mb2   = (const float*)d_in[17];
    const float* lin_g = (const float*)d_in[18];
    const float* lin_b = (const float*)d_in[19];
    const float* lsl_g = (const float*)d_in[20];
    const float* lsl_b = (const float*)d_in[21];
    const float* lml_g = (const float*)d_in[22];
    const float* lml_b = (const float*)d_in[23];
    const float* Wt    = (const float*)d_in[24];
    float* out = (float*)d_out;

    static int init_done = 0;
    if (!init_done) {
        cudaFuncSetAttribute(slot_mma, cudaFuncAttributeMaxDynamicSharedMemorySize, SMEM_DYN);
        cudaFuncSetAttribute(temporal_mma, cudaFuncAttributeMaxDynamicSharedMemorySize, TSMEM);
        cudaFuncSetAttribute(encpro_mma, cudaFuncAttributeMaxDynamicSharedMemorySize, ESMEM);
        init_done = 1;
    }

    pack_all<<<(958464 + 255) / 256, 256>>>(eW1, eW2, skipW, Wk, Wv, Wq,
                                            gWih, gWhh, mW1, mW2, Wt);
    encpro_mma<<<BT / 128, 256, ESMEM>>>(obs, eb1, eb2, lin_g, lin_b);
    slot_mma<<<BT / 8, 256, SMEM_DYN>>>(smu, gbih, gbhh, mb1, mb2,
                                        lsl_g, lsl_b, lml_g, lml_b, out);
    temporal_mma<<<128, 256, TSMEM>>>(out);
}